// round 2
// baseline (speedup 1.0000x reference)
#include <cuda_runtime.h>

#define N_NODES  100000
#define N_EDGES  1600000
#define N_GRAPHS 64
#define IN_DIM   128
#define HID_DIM  256
#define OUT_DIM  256
#define D        256   // feature dim of hidden/out layers

// Scratch (no allocations allowed in kernel_launch)
__device__ float g_deg [N_NODES];
__device__ float g_dinv[N_NODES];
__device__ float g_hs [(size_t)N_NODES * D];   // dinv-scaled features (gather source)
__device__ float g_agg[(size_t)N_NODES * D];   // scatter accumulator
__device__ float g_h  [(size_t)N_NODES * D];   // layer output (relu'd)

// ---------------------------------------------------------------------------
// Degree / normalization
// ---------------------------------------------------------------------------
__global__ void deg_init_kernel(float* deg) {
    int i = blockIdx.x * blockDim.x + threadIdx.x;
    if (i < N_NODES) deg[i] = 1.0f;   // self loop
}

__global__ void deg_count_kernel(const int* __restrict__ cols, float* deg) {
    int e = blockIdx.x * blockDim.x + threadIdx.x;
    if (e < N_EDGES) atomicAdd(&deg[cols[e]], 1.0f);
}

__global__ void dinv_kernel(const float* __restrict__ deg, float* __restrict__ dinv) {
    int i = blockIdx.x * blockDim.x + threadIdx.x;
    if (i < N_NODES) dinv[i] = rsqrtf(fmaxf(deg[i], 1.0f));
}

// ---------------------------------------------------------------------------
// GEMM: hs = (A @ W) * dinv[row];  agg = hs  (self-loop init)
// A: [N_NODES, K] row-major, W: [K, 256] row-major.
// BM=128, BN=64, BK=8, 256 threads, 8x4 per thread.
// ---------------------------------------------------------------------------
template <int K>
__global__ __launch_bounds__(256)
void gemm_scale_kernel(const float* __restrict__ A, const float* __restrict__ W,
                       const float* __restrict__ dinv,
                       float* __restrict__ hs, float* __restrict__ agg)
{
    constexpr int BM = 128, BN = 64, BK = 8;
    __shared__ float As[BK][BM];
    __shared__ float Bs[BK][BN];

    const int tid = threadIdx.x;
    const int m0  = blockIdx.x * BM;
    const int n0  = blockIdx.y * BN;
    const int tx  = tid & 15;   // 0..15 -> 4 cols each
    const int ty  = tid >> 4;   // 0..15 -> 8 rows each

    const int a_row = tid >> 1;           // 0..127
    const int a_k4  = (tid & 1) * 4;      // 0 or 4
    const int b_k   = tid >> 4;           // 0..7 (tid < 128)
    const int b_n   = (tid & 15) * 4;

    float acc[8][4];
    #pragma unroll
    for (int i = 0; i < 8; i++)
        #pragma unroll
        for (int j = 0; j < 4; j++) acc[i][j] = 0.0f;

    for (int k0 = 0; k0 < K; k0 += BK) {
        // load A tile (transposed into As[k][m])
        float4 av = make_float4(0.f, 0.f, 0.f, 0.f);
        int gm = m0 + a_row;
        if (gm < N_NODES)
            av = *(const float4*)(A + (size_t)gm * K + k0 + a_k4);
        As[a_k4 + 0][a_row] = av.x;
        As[a_k4 + 1][a_row] = av.y;
        As[a_k4 + 2][a_row] = av.z;
        As[a_k4 + 3][a_row] = av.w;
        // load B tile
        if (tid < 128) {
            float4 bv = *(const float4*)(W + (size_t)(k0 + b_k) * D + n0 + b_n);
            *(float4*)&Bs[b_k][b_n] = bv;
        }
        __syncthreads();

        #pragma unroll
        for (int kk = 0; kk < BK; kk++) {
            float rm[8], rn[4];
            #pragma unroll
            for (int i = 0; i < 8; i++) rm[i] = As[kk][ty * 8 + i];
            #pragma unroll
            for (int j = 0; j < 4; j++) rn[j] = Bs[kk][tx * 4 + j];
            #pragma unroll
            for (int i = 0; i < 8; i++)
                #pragma unroll
                for (int j = 0; j < 4; j++)
                    acc[i][j] = fmaf(rm[i], rn[j], acc[i][j]);
        }
        __syncthreads();
    }

    #pragma unroll
    for (int i = 0; i < 8; i++) {
        int m = m0 + ty * 8 + i;
        if (m >= N_NODES) continue;
        float dv = dinv[m];
        float4 v;
        v.x = acc[i][0] * dv;
        v.y = acc[i][1] * dv;
        v.z = acc[i][2] * dv;
        v.w = acc[i][3] * dv;
        size_t off = (size_t)m * D + n0 + tx * 4;
        *(float4*)(hs  + off) = v;
        *(float4*)(agg + off) = v;   // self-loop contribution
    }
}

// ---------------------------------------------------------------------------
// Scatter: one warp per edge; agg[col] += hs[row]  (256 floats = 64 red.v4)
// ---------------------------------------------------------------------------
__global__ __launch_bounds__(256)
void scatter_kernel(const int* __restrict__ rows, const int* __restrict__ cols,
                    const float* __restrict__ hs, float* __restrict__ agg)
{
    int warp = (blockIdx.x * blockDim.x + threadIdx.x) >> 5;
    int lane = threadIdx.x & 31;
    if (warp >= N_EDGES) return;
    int r = __ldg(&rows[warp]);
    int c = __ldg(&cols[warp]);
    const float4* src = (const float4*)(hs  + (size_t)r * D);
    float4*       dst = (float4*)      (agg + (size_t)c * D);
    #pragma unroll
    for (int i = 0; i < 2; i++) {
        float4 v = __ldg(&src[lane + 32 * i]);
        asm volatile("red.global.add.v4.f32 [%0], {%1,%2,%3,%4};"
                     :: "l"(dst + lane + 32 * i),
                        "f"(v.x), "f"(v.y), "f"(v.z), "f"(v.w)
                     : "memory");
    }
}

// ---------------------------------------------------------------------------
// Epilogue: out = relu(agg * dinv[node] + bias)
// ---------------------------------------------------------------------------
__global__ __launch_bounds__(256)
void epilogue_kernel(const float* __restrict__ agg, const float* __restrict__ dinv,
                     const float* __restrict__ bias, float* __restrict__ out)
{
    int idx = blockIdx.x * blockDim.x + threadIdx.x;     // float4 index
    if (idx >= N_NODES * (D / 4)) return;
    int node = idx >> 6;          // 64 float4 per row
    int c4   = idx & 63;
    float dv = dinv[node];
    float4 a = ((const float4*)agg)[idx];
    float4 b = ((const float4*)bias)[c4];
    float4 r;
    r.x = fmaxf(fmaf(a.x, dv, b.x), 0.f);
    r.y = fmaxf(fmaf(a.y, dv, b.y), 0.f);
    r.z = fmaxf(fmaf(a.z, dv, b.z), 0.f);
    r.w = fmaxf(fmaf(a.w, dv, b.w), 0.f);
    ((float4*)out)[idx] = r;
}

// ---------------------------------------------------------------------------
// Global mean pool: batch is sorted -> binary search range per graph.
// 64 blocks x 256 threads (one thread per feature dim). No atomics.
// ---------------------------------------------------------------------------
__device__ __forceinline__ int lower_bound_i(const int* a, int n, int v) {
    int lo = 0, hi = n;
    while (lo < hi) {
        int mid = (lo + hi) >> 1;
        if (a[mid] < v) lo = mid + 1; else hi = mid;
    }
    return lo;
}

__global__ __launch_bounds__(256)
void pool_kernel(const float* __restrict__ h, const int* __restrict__ batch,
                 float* __restrict__ out)
{
    int g = blockIdx.x;
    int t = threadIdx.x;
    __shared__ int slo, shi;
    if (t == 0) slo = lower_bound_i(batch, N_NODES, g);
    if (t == 1) shi = lower_bound_i(batch, N_NODES, g + 1);
    __syncthreads();
    int lo = slo, hi = shi;
    float s = 0.f;
    for (int n = lo; n < hi; n++)
        s += h[(size_t)n * D + t];
    int cnt = hi - lo;
    out[g * D + t] = s / (float)max(cnt, 1);
}

// ---------------------------------------------------------------------------
extern "C" void kernel_launch(void* const* d_in, const int* in_sizes, int n_in,
                              void* d_out, int out_size)
{
    const float* x     = (const float*)d_in[0];
    const int*   eidx  = (const int*)  d_in[1];   // [2, E]
    const int*   batch = (const int*)  d_in[2];
    const float* W1    = (const float*)d_in[3];
    const float* b1    = (const float*)d_in[4];
    const float* W2    = (const float*)d_in[5];
    const float* b2    = (const float*)d_in[6];
    float* out = (float*)d_out;

    const int* erow = eidx;            // sources
    const int* ecol = eidx + N_EDGES;  // targets

    float *deg, *dinv, *hs, *agg, *h;
    cudaGetSymbolAddress((void**)&deg,  g_deg);
    cudaGetSymbolAddress((void**)&dinv, g_dinv);
    cudaGetSymbolAddress((void**)&hs,   g_hs);
    cudaGetSymbolAddress((void**)&agg,  g_agg);
    cudaGetSymbolAddress((void**)&h,    g_h);

    // normalization
    deg_init_kernel <<<(N_NODES + 255) / 256, 256>>>(deg);
    deg_count_kernel<<<(N_EDGES + 255) / 256, 256>>>(ecol, deg);
    dinv_kernel     <<<(N_NODES + 255) / 256, 256>>>(deg, dinv);

    dim3 ggrid((N_NODES + 127) / 128, D / 64);
    int  sgrid = N_EDGES / 8;                       // 8 warps/block, 1 edge/warp
    int  egrid = (N_NODES * (D / 4) + 255) / 256;

    // layer 1
    gemm_scale_kernel<IN_DIM><<<ggrid, 256>>>(x, W1, dinv, hs, agg);
    scatter_kernel   <<<sgrid, 256>>>(erow, ecol, hs, agg);
    epilogue_kernel  <<<egrid, 256>>>(agg, dinv, b1, h);

    // layer 2
    gemm_scale_kernel<HID_DIM><<<ggrid, 256>>>(h, W2, dinv, hs, agg);
    scatter_kernel   <<<sgrid, 256>>>(erow, ecol, hs, agg);
    epilogue_kernel  <<<egrid, 256>>>(agg, dinv, b2, h);

    // global mean pool
    pool_kernel<<<N_GRAPHS, 256>>>(h, batch, out);
}

// round 3
// speedup vs baseline: 1.5843x; 1.5843x over previous
#include <cuda_runtime.h>

#define N_NODES  100000
#define N_EDGES  1600000
#define N_GRAPHS 64
#define IN_DIM   128
#define HID_DIM  256
#define OUT_DIM  256
#define D        256

// ---------------- scratch (no allocs allowed) ----------------
__device__ int   g_cnt   [N_NODES];
__device__ float g_dinv  [N_NODES];
__device__ int   g_start [N_NODES + 1];
__device__ int   g_cursor[N_NODES];
__device__ int   g_srow  [N_EDGES];
__device__ float g_agg128[(size_t)N_NODES * IN_DIM];
__device__ float g_h     [(size_t)N_NODES * D];
__device__ float g_hs    [(size_t)N_NODES * D];
__device__ float g_h2    [(size_t)N_NODES * D];

// ---------------- degree / CSR build ----------------
__global__ void zero_cnt_kernel(int* cnt) {
    int i = blockIdx.x * blockDim.x + threadIdx.x;
    if (i < N_NODES) cnt[i] = 0;
}

__global__ void hist_kernel(const int* __restrict__ cols, int* cnt) {
    int e = blockIdx.x * blockDim.x + threadIdx.x;
    if (e < N_EDGES) atomicAdd(&cnt[cols[e]], 1);
}

__global__ void dinv_kernel(const int* __restrict__ cnt, float* __restrict__ dinv) {
    int i = blockIdx.x * blockDim.x + threadIdx.x;
    if (i < N_NODES) dinv[i] = rsqrtf((float)(cnt[i] + 1));   // +1 self loop
}

// single-block exclusive scan of cnt -> start (and cursor copy)
__global__ __launch_bounds__(1024)
void scan_kernel(const int* __restrict__ cnt, int* __restrict__ start,
                 int* __restrict__ cursor)
{
    constexpr int CH = (N_NODES + 1023) / 1024;   // 98
    __shared__ int sums[1024];
    int t  = threadIdx.x;
    int lo = t * CH;
    int hi = min(lo + CH, N_NODES);
    int s = 0;
    for (int i = lo; i < hi; i++) s += cnt[i];
    sums[t] = s;
    __syncthreads();
    #pragma unroll
    for (int off = 1; off < 1024; off <<= 1) {
        int v = (t >= off) ? sums[t - off] : 0;
        __syncthreads();
        sums[t] += v;
        __syncthreads();
    }
    int pre = (t == 0) ? 0 : sums[t - 1];
    for (int i = lo; i < hi; i++) {
        start[i]  = pre;
        cursor[i] = pre;
        pre += cnt[i];
    }
    if (t == 0) start[N_NODES] = N_EDGES;
}

__global__ void place_kernel(const int* __restrict__ rows, const int* __restrict__ cols,
                             int* cursor, int* __restrict__ srow)
{
    int e = blockIdx.x * blockDim.x + threadIdx.x;
    if (e >= N_EDGES) return;
    int c = cols[e];
    int p = atomicAdd(&cursor[c], 1);
    srow[p] = rows[e];
}

// ---------------- layer-1 aggregation in 128 dims ----------------
// out[c] = dinv[c] * ( dinv[c]*x[c] + sum_{r in N(c)} dinv[r]*x[r] )
__global__ __launch_bounds__(256)
void agg1_kernel(const float* __restrict__ x, const int* __restrict__ srow,
                 const int* __restrict__ start, const float* __restrict__ dinv,
                 float* __restrict__ out)
{
    int warp = (blockIdx.x * blockDim.x + threadIdx.x) >> 5;
    int lane = threadIdx.x & 31;
    if (warp >= N_NODES) return;
    int node = warp;
    int s = start[node], e = start[node + 1];
    float dc = dinv[node];
    float4 acc = ((const float4*)(x + (size_t)node * IN_DIM))[lane];
    acc.x *= dc; acc.y *= dc; acc.z *= dc; acc.w *= dc;
    int i = s;
    for (; i + 2 <= e; i += 2) {
        int r0 = srow[i], r1 = srow[i + 1];
        float d0 = dinv[r0], d1 = dinv[r1];
        float4 v0 = ((const float4*)(x + (size_t)r0 * IN_DIM))[lane];
        float4 v1 = ((const float4*)(x + (size_t)r1 * IN_DIM))[lane];
        acc.x += v0.x * d0 + v1.x * d1;
        acc.y += v0.y * d0 + v1.y * d1;
        acc.z += v0.z * d0 + v1.z * d1;
        acc.w += v0.w * d0 + v1.w * d1;
    }
    if (i < e) {
        int r = srow[i];
        float d = dinv[r];
        float4 v = ((const float4*)(x + (size_t)r * IN_DIM))[lane];
        acc.x += v.x * d; acc.y += v.y * d; acc.z += v.z * d; acc.w += v.w * d;
    }
    acc.x *= dc; acc.y *= dc; acc.z *= dc; acc.w *= dc;
    ((float4*)(out + (size_t)node * IN_DIM))[lane] = acc;
}

// ---------------- layer-2 aggregation in 256 dims + bias + relu ----------------
// out[c] = relu( dinv[c] * ( hs[c] + sum hs[r] ) + bias )   (hs already dinv-scaled)
__global__ __launch_bounds__(256)
void agg2_kernel(const float* __restrict__ hs, const int* __restrict__ srow,
                 const int* __restrict__ start, const float* __restrict__ dinv,
                 const float* __restrict__ bias, float* __restrict__ out)
{
    int warp = (blockIdx.x * blockDim.x + threadIdx.x) >> 5;
    int lane = threadIdx.x & 31;
    if (warp >= N_NODES) return;
    int node = warp;
    int s = start[node], e = start[node + 1];
    const float4* self = (const float4*)(hs + (size_t)node * D);
    float4 a0 = self[lane];
    float4 a1 = self[lane + 32];
    int i = s;
    for (; i + 2 <= e; i += 2) {
        int r0 = srow[i], r1 = srow[i + 1];
        const float4* p0 = (const float4*)(hs + (size_t)r0 * D);
        const float4* p1 = (const float4*)(hs + (size_t)r1 * D);
        float4 u0 = p0[lane],      w0 = p1[lane];
        float4 u1 = p0[lane + 32], w1 = p1[lane + 32];
        a0.x += u0.x + w0.x; a0.y += u0.y + w0.y; a0.z += u0.z + w0.z; a0.w += u0.w + w0.w;
        a1.x += u1.x + w1.x; a1.y += u1.y + w1.y; a1.z += u1.z + w1.z; a1.w += u1.w + w1.w;
    }
    if (i < e) {
        int r = srow[i];
        const float4* p = (const float4*)(hs + (size_t)r * D);
        float4 u0 = p[lane], u1 = p[lane + 32];
        a0.x += u0.x; a0.y += u0.y; a0.z += u0.z; a0.w += u0.w;
        a1.x += u1.x; a1.y += u1.y; a1.z += u1.z; a1.w += u1.w;
    }
    float dc = dinv[node];
    float4 b0 = ((const float4*)bias)[lane];
    float4 b1 = ((const float4*)bias)[lane + 32];
    float4 r0, r1;
    r0.x = fmaxf(fmaf(a0.x, dc, b0.x), 0.f);
    r0.y = fmaxf(fmaf(a0.y, dc, b0.y), 0.f);
    r0.z = fmaxf(fmaf(a0.z, dc, b0.z), 0.f);
    r0.w = fmaxf(fmaf(a0.w, dc, b0.w), 0.f);
    r1.x = fmaxf(fmaf(a1.x, dc, b1.x), 0.f);
    r1.y = fmaxf(fmaf(a1.y, dc, b1.y), 0.f);
    r1.z = fmaxf(fmaf(a1.z, dc, b1.z), 0.f);
    r1.w = fmaxf(fmaf(a1.w, dc, b1.w), 0.f);
    float4* o = (float4*)(out + (size_t)node * D);
    o[lane] = r0;
    o[lane + 32] = r1;
}

// ---------------- GEMM 128x128 tile, 8x8 per thread ----------------
// out = A[N x K] @ W[K x 256], optional +bias+relu (gemm1) or *dinv[row] (gemm2)
template <int K, bool RELU, bool SCALE>
__global__ __launch_bounds__(256)
void gemm_kernel(const float* __restrict__ A, const float* __restrict__ W,
                 const float* __restrict__ bias, const float* __restrict__ dinv,
                 float* __restrict__ out)
{
    constexpr int BM = 128, BN = 128, BK = 8;
    __shared__ float As[BK][BM];
    __shared__ float Bs[BK][BN];

    const int tid = threadIdx.x;
    const int m0  = blockIdx.x * BM;
    const int n0  = blockIdx.y * BN;
    const int tx  = tid & 15;    // 16 col groups
    const int ty  = tid >> 4;    // 16 row groups

    const int a_row = tid >> 1;
    const int a_k4  = (tid & 1) * 4;
    const int b_k   = tid >> 5;         // 0..7
    const int b_n   = (tid & 31) * 4;   // 0..124

    float acc[2][2][4][4];
    #pragma unroll
    for (int a = 0; a < 2; a++)
        #pragma unroll
        for (int b = 0; b < 2; b++)
            #pragma unroll
            for (int i = 0; i < 4; i++)
                #pragma unroll
                for (int j = 0; j < 4; j++) acc[a][b][i][j] = 0.f;

    for (int k0 = 0; k0 < K; k0 += BK) {
        float4 av = make_float4(0.f, 0.f, 0.f, 0.f);
        int gm = m0 + a_row;
        if (gm < N_NODES)
            av = *(const float4*)(A + (size_t)gm * K + k0 + a_k4);
        As[a_k4 + 0][a_row] = av.x;
        As[a_k4 + 1][a_row] = av.y;
        As[a_k4 + 2][a_row] = av.z;
        As[a_k4 + 3][a_row] = av.w;
        float4 bv = *(const float4*)(W + (size_t)(k0 + b_k) * D + n0 + b_n);
        *(float4*)&Bs[b_k][b_n] = bv;
        __syncthreads();

        #pragma unroll
        for (int kk = 0; kk < BK; kk++) {
            float rm[2][4], rn[2][4];
            *(float4*)rm[0] = *(const float4*)&As[kk][ty * 4];
            *(float4*)rm[1] = *(const float4*)&As[kk][64 + ty * 4];
            *(float4*)rn[0] = *(const float4*)&Bs[kk][tx * 4];
            *(float4*)rn[1] = *(const float4*)&Bs[kk][64 + tx * 4];
            #pragma unroll
            for (int a = 0; a < 2; a++)
                #pragma unroll
                for (int i = 0; i < 4; i++)
                    #pragma unroll
                    for (int b = 0; b < 2; b++)
                        #pragma unroll
                        for (int j = 0; j < 4; j++)
                            acc[a][b][i][j] = fmaf(rm[a][i], rn[b][j], acc[a][b][i][j]);
        }
        __syncthreads();
    }

    #pragma unroll
    for (int a = 0; a < 2; a++) {
        #pragma unroll
        for (int i = 0; i < 4; i++) {
            int m = m0 + a * 64 + ty * 4 + i;
            if (m >= N_NODES) continue;
            float sc = SCALE ? dinv[m] : 1.f;
            #pragma unroll
            for (int b = 0; b < 2; b++) {
                int col = n0 + b * 64 + tx * 4;
                float4 v;
                v.x = acc[a][b][i][0] * sc;
                v.y = acc[a][b][i][1] * sc;
                v.z = acc[a][b][i][2] * sc;
                v.w = acc[a][b][i][3] * sc;
                if (RELU) {
                    float4 bb = *(const float4*)(bias + col);
                    v.x = fmaxf(v.x + bb.x, 0.f);
                    v.y = fmaxf(v.y + bb.y, 0.f);
                    v.z = fmaxf(v.z + bb.z, 0.f);
                    v.w = fmaxf(v.w + bb.w, 0.f);
                }
                *(float4*)(out + (size_t)m * D + col) = v;
            }
        }
    }
}

// ---------------- global mean pool ----------------
__device__ __forceinline__ int lower_bound_i(const int* a, int n, int v) {
    int lo = 0, hi = n;
    while (lo < hi) {
        int mid = (lo + hi) >> 1;
        if (a[mid] < v) lo = mid + 1; else hi = mid;
    }
    return lo;
}

__global__ __launch_bounds__(128)
void pool_kernel(const float* __restrict__ h, const int* __restrict__ batch,
                 float* __restrict__ out)
{
    int g = blockIdx.x;
    int t = blockIdx.y * 128 + threadIdx.x;   // feature dim
    __shared__ int slo, shi;
    if (threadIdx.x == 0) slo = lower_bound_i(batch, N_NODES, g);
    if (threadIdx.x == 1) shi = lower_bound_i(batch, N_NODES, g + 1);
    __syncthreads();
    int lo = slo, hi = shi;
    float s = 0.f;
    for (int n = lo; n < hi; n++)
        s += h[(size_t)n * D + t];
    int cnt = hi - lo;
    out[g * D + t] = s / (float)max(cnt, 1);
}

// ---------------------------------------------------------------------------
extern "C" void kernel_launch(void* const* d_in, const int* in_sizes, int n_in,
                              void* d_out, int out_size)
{
    const float* x     = (const float*)d_in[0];
    const int*   eidx  = (const int*)  d_in[1];
    const int*   batch = (const int*)  d_in[2];
    const float* W1    = (const float*)d_in[3];
    const float* b1    = (const float*)d_in[4];
    const float* W2    = (const float*)d_in[5];
    const float* b2    = (const float*)d_in[6];
    float* out = (float*)d_out;

    const int* erow = eidx;
    const int* ecol = eidx + N_EDGES;

    int *cnt, *startp, *cursor, *srow;
    float *dinv, *agg128, *h, *hs, *h2;
    cudaGetSymbolAddress((void**)&cnt,    g_cnt);
    cudaGetSymbolAddress((void**)&dinv,   g_dinv);
    cudaGetSymbolAddress((void**)&startp, g_start);
    cudaGetSymbolAddress((void**)&cursor, g_cursor);
    cudaGetSymbolAddress((void**)&srow,   g_srow);
    cudaGetSymbolAddress((void**)&agg128, g_agg128);
    cudaGetSymbolAddress((void**)&h,      g_h);
    cudaGetSymbolAddress((void**)&hs,     g_hs);
    cudaGetSymbolAddress((void**)&h2,     g_h2);

    // CSR build
    zero_cnt_kernel<<<(N_NODES + 255) / 256, 256>>>(cnt);
    hist_kernel    <<<(N_EDGES + 255) / 256, 256>>>(ecol, cnt);
    dinv_kernel    <<<(N_NODES + 255) / 256, 256>>>(cnt, dinv);
    scan_kernel    <<<1, 1024>>>(cnt, startp, cursor);
    place_kernel   <<<(N_EDGES + 255) / 256, 256>>>(erow, ecol, cursor, srow);

    dim3 ggrid((N_NODES + 127) / 128, 2);
    int  agrid = (N_NODES * 32 + 255) / 256;   // one warp per node

    // layer 1: aggregate(128) -> gemm+bias+relu
    agg1_kernel<<<agrid, 256>>>(x, srow, startp, dinv, agg128);
    gemm_kernel<IN_DIM, true, false><<<ggrid, 256>>>(agg128, W1, b1, dinv, h);

    // layer 2: gemm*dinv -> aggregate(256)+bias+relu
    gemm_kernel<HID_DIM, false, true><<<ggrid, 256>>>(h, W2, b2, dinv, hs);
    agg2_kernel<<<agrid, 256>>>(hs, srow, startp, dinv, b2, h2);

    // pool
    pool_kernel<<<dim3(N_GRAPHS, 2), 128>>>(h2, batch, out);
}

// round 4
// speedup vs baseline: 1.9730x; 1.2453x over previous
#include <cuda_runtime.h>
#include <cuda_bf16.h>

#define N_NODES  100000
#define N_EDGES  1600000
#define N_GRAPHS 64
#define IN_DIM   128
#define HID_DIM  256
#define OUT_DIM  256
#define D        256
#define SCAN_NB  98          // ceil(N_NODES / 1024)

// ---------------- scratch (no allocs allowed) ----------------
__device__ int   g_cnt   [N_NODES];
__device__ float g_dinv  [N_NODES];
__device__ int   g_start [N_NODES + 1];
__device__ int   g_cursor[N_NODES];
__device__ int   g_srow  [N_EDGES];
__device__ int   g_bsum  [SCAN_NB];
__device__ int   g_boff  [SCAN_NB];
__device__ float g_agg128[(size_t)N_NODES * IN_DIM];
__device__ float g_h     [(size_t)N_NODES * D];
__device__ __nv_bfloat16 g_hs[(size_t)N_NODES * D];
__device__ float g_h2    [(size_t)N_NODES * D];

// ---------------- degree / CSR build ----------------
__global__ void zero_cnt_kernel(int* cnt) {
    int i = blockIdx.x * blockDim.x + threadIdx.x;
    if (i < N_NODES) cnt[i] = 0;
}

__global__ void hist_kernel(const int* __restrict__ cols, int* cnt) {
    int e = blockIdx.x * blockDim.x + threadIdx.x;
    if (e < N_EDGES) atomicAdd(&cnt[cols[e]], 1);
}

__global__ void dinv_kernel(const int* __restrict__ cnt, float* __restrict__ dinv) {
    int i = blockIdx.x * blockDim.x + threadIdx.x;
    if (i < N_NODES) dinv[i] = rsqrtf((float)(cnt[i] + 1));   // +1 self loop
}

// ---- 3-phase exclusive scan of cnt -> start/cursor ----
__global__ __launch_bounds__(256)
void partial_sum_kernel(const int* __restrict__ cnt, int* __restrict__ bsum) {
    __shared__ int sh[256];
    int b = blockIdx.x, t = threadIdx.x;
    int base = b * 1024;
    int s = 0;
    #pragma unroll
    for (int j = 0; j < 4; j++) {
        int i = base + t + j * 256;
        if (i < N_NODES) s += cnt[i];
    }
    sh[t] = s;
    __syncthreads();
    for (int off = 128; off > 0; off >>= 1) {
        if (t < off) sh[t] += sh[t + off];
        __syncthreads();
    }
    if (t == 0) bsum[b] = sh[0];
}

__global__ __launch_bounds__(128)
void scan_bsum_kernel(const int* __restrict__ bsum, int* __restrict__ boff) {
    __shared__ int sh[128];
    int t = threadIdx.x;
    sh[t] = (t < SCAN_NB) ? bsum[t] : 0;
    __syncthreads();
    for (int off = 1; off < 128; off <<= 1) {
        int v = (t >= off) ? sh[t - off] : 0;
        __syncthreads();
        sh[t] += v;
        __syncthreads();
    }
    if (t < SCAN_NB) boff[t] = (t == 0) ? 0 : sh[t - 1];
}

__global__ __launch_bounds__(256)
void scan_final_kernel(const int* __restrict__ cnt, const int* __restrict__ boff,
                       int* __restrict__ start, int* __restrict__ cursor) {
    __shared__ int sh[256];
    int b = blockIdx.x, t = threadIdx.x;
    int base = b * 1024 + t * 4;
    int c[4];
    int s = 0;
    #pragma unroll
    for (int j = 0; j < 4; j++) {
        int i = base + j;
        c[j] = (i < N_NODES) ? cnt[i] : 0;
        s += c[j];
    }
    sh[t] = s;
    __syncthreads();
    for (int off = 1; off < 256; off <<= 1) {
        int v = (t >= off) ? sh[t - off] : 0;
        __syncthreads();
        sh[t] += v;
        __syncthreads();
    }
    int pre = boff[b] + ((t == 0) ? 0 : sh[t - 1]);
    #pragma unroll
    for (int j = 0; j < 4; j++) {
        int i = base + j;
        if (i < N_NODES) { start[i] = pre; cursor[i] = pre; }
        pre += c[j];
    }
    if (b == 0 && t == 0) start[N_NODES] = N_EDGES;
}

__global__ void place_kernel(const int* __restrict__ rows, const int* __restrict__ cols,
                             int* cursor, int* __restrict__ srow)
{
    int e = blockIdx.x * blockDim.x + threadIdx.x;
    if (e >= N_EDGES) return;
    int c = cols[e];
    int p = atomicAdd(&cursor[c], 1);
    srow[p] = rows[e];
}

// ---------------- layer-1 aggregation in 128 dims (fp32) ----------------
// out[c] = dinv[c] * ( dinv[c]*x[c] + sum_{r in N(c)} dinv[r]*x[r] )
__global__ __launch_bounds__(256)
void agg1_kernel(const float* __restrict__ x, const int* __restrict__ srow,
                 const int* __restrict__ start, const float* __restrict__ dinv,
                 float* __restrict__ out)
{
    int warp = (blockIdx.x * blockDim.x + threadIdx.x) >> 5;
    int lane = threadIdx.x & 31;
    if (warp >= N_NODES) return;
    int node = warp;
    int s = start[node], e = start[node + 1];
    float dc = dinv[node];
    float4 acc = ((const float4*)(x + (size_t)node * IN_DIM))[lane];
    acc.x *= dc; acc.y *= dc; acc.z *= dc; acc.w *= dc;
    int i = s;
    for (; i + 4 <= e; i += 4) {
        int r0 = srow[i], r1 = srow[i + 1], r2 = srow[i + 2], r3 = srow[i + 3];
        float d0 = dinv[r0], d1 = dinv[r1], d2 = dinv[r2], d3 = dinv[r3];
        float4 v0 = ((const float4*)(x + (size_t)r0 * IN_DIM))[lane];
        float4 v1 = ((const float4*)(x + (size_t)r1 * IN_DIM))[lane];
        float4 v2 = ((const float4*)(x + (size_t)r2 * IN_DIM))[lane];
        float4 v3 = ((const float4*)(x + (size_t)r3 * IN_DIM))[lane];
        acc.x += v0.x * d0 + v1.x * d1 + v2.x * d2 + v3.x * d3;
        acc.y += v0.y * d0 + v1.y * d1 + v2.y * d2 + v3.y * d3;
        acc.z += v0.z * d0 + v1.z * d1 + v2.z * d2 + v3.z * d3;
        acc.w += v0.w * d0 + v1.w * d1 + v2.w * d2 + v3.w * d3;
    }
    for (; i < e; i++) {
        int r = srow[i];
        float d = dinv[r];
        float4 v = ((const float4*)(x + (size_t)r * IN_DIM))[lane];
        acc.x += v.x * d; acc.y += v.y * d; acc.z += v.z * d; acc.w += v.w * d;
    }
    acc.x *= dc; acc.y *= dc; acc.z *= dc; acc.w *= dc;
    ((float4*)(out + (size_t)node * IN_DIM))[lane] = acc;
}

// ---------------- layer-2 aggregation (bf16 gather, fp32 accumulate) ----------------
__device__ __forceinline__ void bf16x8_add(uint4 v, float* a) {
    float2 f0 = __bfloat1622float2(*(__nv_bfloat162*)&v.x);
    float2 f1 = __bfloat1622float2(*(__nv_bfloat162*)&v.y);
    float2 f2 = __bfloat1622float2(*(__nv_bfloat162*)&v.z);
    float2 f3 = __bfloat1622float2(*(__nv_bfloat162*)&v.w);
    a[0] += f0.x; a[1] += f0.y; a[2] += f1.x; a[3] += f1.y;
    a[4] += f2.x; a[5] += f2.y; a[6] += f3.x; a[7] += f3.y;
}

__global__ __launch_bounds__(256)
void agg2_kernel(const __nv_bfloat16* __restrict__ hs, const int* __restrict__ srow,
                 const int* __restrict__ start, const float* __restrict__ dinv,
                 const float* __restrict__ bias, float* __restrict__ out)
{
    int warp = (blockIdx.x * blockDim.x + threadIdx.x) >> 5;
    int lane = threadIdx.x & 31;
    if (warp >= N_NODES) return;
    int node = warp;
    int s = start[node], e = start[node + 1];

    float acc[8] = {0, 0, 0, 0, 0, 0, 0, 0};
    uint4 sv = ((const uint4*)(hs + (size_t)node * D))[lane];
    bf16x8_add(sv, acc);

    int i = s;
    for (; i + 4 <= e; i += 4) {
        int r0 = srow[i], r1 = srow[i + 1], r2 = srow[i + 2], r3 = srow[i + 3];
        uint4 v0 = ((const uint4*)(hs + (size_t)r0 * D))[lane];
        uint4 v1 = ((const uint4*)(hs + (size_t)r1 * D))[lane];
        uint4 v2 = ((const uint4*)(hs + (size_t)r2 * D))[lane];
        uint4 v3 = ((const uint4*)(hs + (size_t)r3 * D))[lane];
        bf16x8_add(v0, acc); bf16x8_add(v1, acc);
        bf16x8_add(v2, acc); bf16x8_add(v3, acc);
    }
    for (; i < e; i++) {
        int r = srow[i];
        uint4 v = ((const uint4*)(hs + (size_t)r * D))[lane];
        bf16x8_add(v, acc);
    }

    float dc = dinv[node];
    float4 b_lo = ((const float4*)bias)[lane * 2];
    float4 b_hi = ((const float4*)bias)[lane * 2 + 1];
    float4 r0, r1;
    r0.x = fmaxf(fmaf(acc[0], dc, b_lo.x), 0.f);
    r0.y = fmaxf(fmaf(acc[1], dc, b_lo.y), 0.f);
    r0.z = fmaxf(fmaf(acc[2], dc, b_lo.z), 0.f);
    r0.w = fmaxf(fmaf(acc[3], dc, b_lo.w), 0.f);
    r1.x = fmaxf(fmaf(acc[4], dc, b_hi.x), 0.f);
    r1.y = fmaxf(fmaf(acc[5], dc, b_hi.y), 0.f);
    r1.z = fmaxf(fmaf(acc[6], dc, b_hi.z), 0.f);
    r1.w = fmaxf(fmaf(acc[7], dc, b_hi.w), 0.f);
    float4* o = (float4*)(out + (size_t)node * D);
    o[lane * 2]     = r0;
    o[lane * 2 + 1] = r1;
}

// ---------------- GEMM 128x128 tile, 8x8 per thread ----------------
template <int K, bool RELU, bool SCALE, typename OutT>
__global__ __launch_bounds__(256)
void gemm_kernel(const float* __restrict__ A, const float* __restrict__ W,
                 const float* __restrict__ bias, const float* __restrict__ dinv,
                 OutT* __restrict__ out)
{
    constexpr int BM = 128, BN = 128, BK = 8;
    __shared__ float As[BK][BM];
    __shared__ float Bs[BK][BN];

    const int tid = threadIdx.x;
    const int m0  = blockIdx.x * BM;
    const int n0  = blockIdx.y * BN;
    const int tx  = tid & 15;
    const int ty  = tid >> 4;

    const int a_row = tid >> 1;
    const int a_k4  = (tid & 1) * 4;
    const int b_k   = tid >> 5;
    const int b_n   = (tid & 31) * 4;

    float acc[2][2][4][4];
    #pragma unroll
    for (int a = 0; a < 2; a++)
        #pragma unroll
        for (int b = 0; b < 2; b++)
            #pragma unroll
            for (int i = 0; i < 4; i++)
                #pragma unroll
                for (int j = 0; j < 4; j++) acc[a][b][i][j] = 0.f;

    for (int k0 = 0; k0 < K; k0 += BK) {
        float4 av = make_float4(0.f, 0.f, 0.f, 0.f);
        int gm = m0 + a_row;
        if (gm < N_NODES)
            av = *(const float4*)(A + (size_t)gm * K + k0 + a_k4);
        As[a_k4 + 0][a_row] = av.x;
        As[a_k4 + 1][a_row] = av.y;
        As[a_k4 + 2][a_row] = av.z;
        As[a_k4 + 3][a_row] = av.w;
        float4 bv = *(const float4*)(W + (size_t)(k0 + b_k) * D + n0 + b_n);
        *(float4*)&Bs[b_k][b_n] = bv;
        __syncthreads();

        #pragma unroll
        for (int kk = 0; kk < BK; kk++) {
            float rm[2][4], rn[2][4];
            *(float4*)rm[0] = *(const float4*)&As[kk][ty * 4];
            *(float4*)rm[1] = *(const float4*)&As[kk][64 + ty * 4];
            *(float4*)rn[0] = *(const float4*)&Bs[kk][tx * 4];
            *(float4*)rn[1] = *(const float4*)&Bs[kk][64 + tx * 4];
            #pragma unroll
            for (int a = 0; a < 2; a++)
                #pragma unroll
                for (int i = 0; i < 4; i++)
                    #pragma unroll
                    for (int b = 0; b < 2; b++)
                        #pragma unroll
                        for (int j = 0; j < 4; j++)
                            acc[a][b][i][j] = fmaf(rm[a][i], rn[b][j], acc[a][b][i][j]);
        }
        __syncthreads();
    }

    #pragma unroll
    for (int a = 0; a < 2; a++) {
        #pragma unroll
        for (int i = 0; i < 4; i++) {
            int m = m0 + a * 64 + ty * 4 + i;
            if (m >= N_NODES) continue;
            float sc = SCALE ? dinv[m] : 1.f;
            #pragma unroll
            for (int b = 0; b < 2; b++) {
                int col = n0 + b * 64 + tx * 4;
                float4 v;
                v.x = acc[a][b][i][0] * sc;
                v.y = acc[a][b][i][1] * sc;
                v.z = acc[a][b][i][2] * sc;
                v.w = acc[a][b][i][3] * sc;
                if (RELU) {
                    float4 bb = *(const float4*)(bias + col);
                    v.x = fmaxf(v.x + bb.x, 0.f);
                    v.y = fmaxf(v.y + bb.y, 0.f);
                    v.z = fmaxf(v.z + bb.z, 0.f);
                    v.w = fmaxf(v.w + bb.w, 0.f);
                }
                if constexpr (sizeof(OutT) == 4) {
                    *(float4*)((float*)out + (size_t)m * D + col) = v;
                } else {
                    __nv_bfloat162 p0 = __floats2bfloat162_rn(v.x, v.y);
                    __nv_bfloat162 p1 = __floats2bfloat162_rn(v.z, v.w);
                    uint2 u;
                    u.x = *(unsigned*)&p0;
                    u.y = *(unsigned*)&p1;
                    *(uint2*)((__nv_bfloat16*)out + (size_t)m * D + col) = u;
                }
            }
        }
    }
}

// ---------------- global mean pool ----------------
__device__ __forceinline__ int lower_bound_i(const int* a, int n, int v) {
    int lo = 0, hi = n;
    while (lo < hi) {
        int mid = (lo + hi) >> 1;
        if (a[mid] < v) lo = mid + 1; else hi = mid;
    }
    return lo;
}

__global__ __launch_bounds__(128)
void pool_kernel(const float* __restrict__ h, const int* __restrict__ batch,
                 float* __restrict__ out)
{
    int g = blockIdx.x;
    int t = blockIdx.y * 128 + threadIdx.x;
    __shared__ int slo, shi;
    if (threadIdx.x == 0) slo = lower_bound_i(batch, N_NODES, g);
    if (threadIdx.x == 1) shi = lower_bound_i(batch, N_NODES, g + 1);
    __syncthreads();
    int lo = slo, hi = shi;
    float s = 0.f;
    for (int n = lo; n < hi; n++)
        s += h[(size_t)n * D + t];
    int cnt = hi - lo;
    out[g * D + t] = s / (float)max(cnt, 1);
}

// ---------------------------------------------------------------------------
extern "C" void kernel_launch(void* const* d_in, const int* in_sizes, int n_in,
                              void* d_out, int out_size)
{
    const float* x     = (const float*)d_in[0];
    const int*   eidx  = (const int*)  d_in[1];
    const int*   batch = (const int*)  d_in[2];
    const float* W1    = (const float*)d_in[3];
    const float* b1    = (const float*)d_in[4];
    const float* W2    = (const float*)d_in[5];
    const float* b2    = (const float*)d_in[6];
    float* out = (float*)d_out;

    const int* erow = eidx;
    const int* ecol = eidx + N_EDGES;

    int *cnt, *startp, *cursor, *srow, *bsum, *boff;
    float *dinv, *agg128, *h, *h2;
    __nv_bfloat16* hs;
    cudaGetSymbolAddress((void**)&cnt,    g_cnt);
    cudaGetSymbolAddress((void**)&dinv,   g_dinv);
    cudaGetSymbolAddress((void**)&startp, g_start);
    cudaGetSymbolAddress((void**)&cursor, g_cursor);
    cudaGetSymbolAddress((void**)&srow,   g_srow);
    cudaGetSymbolAddress((void**)&bsum,   g_bsum);
    cudaGetSymbolAddress((void**)&boff,   g_boff);
    cudaGetSymbolAddress((void**)&agg128, g_agg128);
    cudaGetSymbolAddress((void**)&h,      g_h);
    cudaGetSymbolAddress((void**)&hs,     g_hs);
    cudaGetSymbolAddress((void**)&h2,     g_h2);

    // CSR build
    zero_cnt_kernel   <<<(N_NODES + 255) / 256, 256>>>(cnt);
    hist_kernel       <<<(N_EDGES + 255) / 256, 256>>>(ecol, cnt);
    dinv_kernel       <<<(N_NODES + 255) / 256, 256>>>(cnt, dinv);
    partial_sum_kernel<<<SCAN_NB, 256>>>(cnt, bsum);
    scan_bsum_kernel  <<<1, 128>>>(bsum, boff);
    scan_final_kernel <<<SCAN_NB, 256>>>(cnt, boff, startp, cursor);
    place_kernel      <<<(N_EDGES + 255) / 256, 256>>>(erow, ecol, cursor, srow);

    dim3 ggrid((N_NODES + 127) / 128, 2);
    int  agrid = (N_NODES * 32 + 255) / 256;

    // layer 1: aggregate(128) -> gemm+bias+relu
    agg1_kernel<<<agrid, 256>>>(x, srow, startp, dinv, agg128);
    gemm_kernel<IN_DIM, true, false, float><<<ggrid, 256>>>(agg128, W1, b1, dinv, h);

    // layer 2: gemm*dinv (bf16 out) -> aggregate+bias+relu
    gemm_kernel<HID_DIM, false, true, __nv_bfloat16><<<ggrid, 256>>>(h, W2, b2, dinv, hs);
    agg2_kernel<<<agrid, 256>>>(hs, srow, startp, dinv, b2, h2);

    // pool
    pool_kernel<<<dim3(N_GRAPHS, 2), 128>>>(h2, batch, out);
}

// round 6
// speedup vs baseline: 3.1277x; 1.5853x over previous
#include <cuda_runtime.h>
#include <cuda_bf16.h>
#include <cstdint>

#define N_NODES  100000
#define N_EDGES  1600000
#define N_GRAPHS 64
#define IN_DIM   128
#define HID_DIM  256
#define OUT_DIM  256
#define D        256
#define SCAN_NB  98          // ceil(N_NODES / 1024)

// ---------------- scratch (no allocs allowed) ----------------
__device__ int   g_cnt   [N_NODES];
__device__ float g_dinv  [N_NODES];
__device__ int   g_start [N_NODES + 1];
__device__ int   g_cursor[N_NODES];
__device__ int   g_srow  [N_EDGES];
__device__ int   g_bsum  [SCAN_NB];
__device__ int   g_boff  [SCAN_NB];
__device__ float g_agg128[(size_t)N_NODES * IN_DIM];
__device__ float g_h     [(size_t)N_NODES * D];
__device__ __nv_bfloat16 g_hs[(size_t)N_NODES * D];
__device__ float g_h2    [(size_t)N_NODES * D];

// ---------------- degree / CSR build ----------------
__global__ void zero_cnt_kernel(int* cnt) {
    int i = blockIdx.x * blockDim.x + threadIdx.x;
    if (i < N_NODES) cnt[i] = 0;
}

__global__ void hist_kernel(const int* __restrict__ cols, int* cnt) {
    int e = blockIdx.x * blockDim.x + threadIdx.x;
    if (e < N_EDGES) atomicAdd(&cnt[cols[e]], 1);
}

__global__ void dinv_kernel(const int* __restrict__ cnt, float* __restrict__ dinv) {
    int i = blockIdx.x * blockDim.x + threadIdx.x;
    if (i < N_NODES) dinv[i] = rsqrtf((float)(cnt[i] + 1));   // +1 self loop
}

// ---- 3-phase exclusive scan of cnt -> start/cursor ----
__global__ __launch_bounds__(256)
void partial_sum_kernel(const int* __restrict__ cnt, int* __restrict__ bsum) {
    __shared__ int sh[256];
    int b = blockIdx.x, t = threadIdx.x;
    int base = b * 1024;
    int s = 0;
    #pragma unroll
    for (int j = 0; j < 4; j++) {
        int i = base + t + j * 256;
        if (i < N_NODES) s += cnt[i];
    }
    sh[t] = s;
    __syncthreads();
    for (int off = 128; off > 0; off >>= 1) {
        if (t < off) sh[t] += sh[t + off];
        __syncthreads();
    }
    if (t == 0) bsum[b] = sh[0];
}

__global__ __launch_bounds__(128)
void scan_bsum_kernel(const int* __restrict__ bsum, int* __restrict__ boff) {
    __shared__ int sh[128];
    int t = threadIdx.x;
    sh[t] = (t < SCAN_NB) ? bsum[t] : 0;
    __syncthreads();
    for (int off = 1; off < 128; off <<= 1) {
        int v = (t >= off) ? sh[t - off] : 0;
        __syncthreads();
        sh[t] += v;
        __syncthreads();
    }
    if (t < SCAN_NB) boff[t] = (t == 0) ? 0 : sh[t - 1];
}

__global__ __launch_bounds__(256)
void scan_final_kernel(const int* __restrict__ cnt, const int* __restrict__ boff,
                       int* __restrict__ start, int* __restrict__ cursor) {
    __shared__ int sh[256];
    int b = blockIdx.x, t = threadIdx.x;
    int base = b * 1024 + t * 4;
    int c[4];
    int s = 0;
    #pragma unroll
    for (int j = 0; j < 4; j++) {
        int i = base + j;
        c[j] = (i < N_NODES) ? cnt[i] : 0;
        s += c[j];
    }
    sh[t] = s;
    __syncthreads();
    for (int off = 1; off < 256; off <<= 1) {
        int v = (t >= off) ? sh[t - off] : 0;
        __syncthreads();
        sh[t] += v;
        __syncthreads();
    }
    int pre = boff[b] + ((t == 0) ? 0 : sh[t - 1]);
    #pragma unroll
    for (int j = 0; j < 4; j++) {
        int i = base + j;
        if (i < N_NODES) { start[i] = pre; cursor[i] = pre; }
        pre += c[j];
    }
    if (b == 0 && t == 0) start[N_NODES] = N_EDGES;
}

__global__ void place_kernel(const int* __restrict__ rows, const int* __restrict__ cols,
                             int* cursor, int* __restrict__ srow)
{
    int e = blockIdx.x * blockDim.x + threadIdx.x;
    if (e >= N_EDGES) return;
    int c = cols[e];
    int p = atomicAdd(&cursor[c], 1);
    srow[p] = rows[e];
}

// ---------------- layer-1 aggregation in 128 dims (fp32) ----------------
__global__ __launch_bounds__(256)
void agg1_kernel(const float* __restrict__ x, const int* __restrict__ srow,
                 const int* __restrict__ start, const float* __restrict__ dinv,
                 float* __restrict__ out)
{
    int warp = (blockIdx.x * blockDim.x + threadIdx.x) >> 5;
    int lane = threadIdx.x & 31;
    if (warp >= N_NODES) return;
    int node = warp;
    int s = start[node], e = start[node + 1];
    float dc = dinv[node];
    float4 acc = ((const float4*)(x + (size_t)node * IN_DIM))[lane];
    acc.x *= dc; acc.y *= dc; acc.z *= dc; acc.w *= dc;
    int i = s;
    for (; i + 4 <= e; i += 4) {
        int r0 = srow[i], r1 = srow[i + 1], r2 = srow[i + 2], r3 = srow[i + 3];
        float d0 = dinv[r0], d1 = dinv[r1], d2 = dinv[r2], d3 = dinv[r3];
        float4 v0 = ((const float4*)(x + (size_t)r0 * IN_DIM))[lane];
        float4 v1 = ((const float4*)(x + (size_t)r1 * IN_DIM))[lane];
        float4 v2 = ((const float4*)(x + (size_t)r2 * IN_DIM))[lane];
        float4 v3 = ((const float4*)(x + (size_t)r3 * IN_DIM))[lane];
        acc.x += v0.x * d0 + v1.x * d1 + v2.x * d2 + v3.x * d3;
        acc.y += v0.y * d0 + v1.y * d1 + v2.y * d2 + v3.y * d3;
        acc.z += v0.z * d0 + v1.z * d1 + v2.z * d2 + v3.z * d3;
        acc.w += v0.w * d0 + v1.w * d1 + v2.w * d2 + v3.w * d3;
    }
    for (; i < e; i++) {
        int r = srow[i];
        float d = dinv[r];
        float4 v = ((const float4*)(x + (size_t)r * IN_DIM))[lane];
        acc.x += v.x * d; acc.y += v.y * d; acc.z += v.z * d; acc.w += v.w * d;
    }
    acc.x *= dc; acc.y *= dc; acc.z *= dc; acc.w *= dc;
    ((float4*)(out + (size_t)node * IN_DIM))[lane] = acc;
}

// ---------------- layer-2 aggregation (bf16 gather, fp32 accumulate) ----------------
__device__ __forceinline__ void bf16x8_add(uint4 v, float* a) {
    float2 f0 = __bfloat1622float2(*(__nv_bfloat162*)&v.x);
    float2 f1 = __bfloat1622float2(*(__nv_bfloat162*)&v.y);
    float2 f2 = __bfloat1622float2(*(__nv_bfloat162*)&v.z);
    float2 f3 = __bfloat1622float2(*(__nv_bfloat162*)&v.w);
    a[0] += f0.x; a[1] += f0.y; a[2] += f1.x; a[3] += f1.y;
    a[4] += f2.x; a[5] += f2.y; a[6] += f3.x; a[7] += f3.y;
}

__global__ __launch_bounds__(256)
void agg2_kernel(const __nv_bfloat16* __restrict__ hs, const int* __restrict__ srow,
                 const int* __restrict__ start, const float* __restrict__ dinv,
                 const float* __restrict__ bias, float* __restrict__ out)
{
    int warp = (blockIdx.x * blockDim.x + threadIdx.x) >> 5;
    int lane = threadIdx.x & 31;
    if (warp >= N_NODES) return;
    int node = warp;
    int s = start[node], e = start[node + 1];

    float acc[8] = {0, 0, 0, 0, 0, 0, 0, 0};
    uint4 sv = ((const uint4*)(hs + (size_t)node * D))[lane];
    bf16x8_add(sv, acc);

    int i = s;
    for (; i + 4 <= e; i += 4) {
        int r0 = srow[i], r1 = srow[i + 1], r2 = srow[i + 2], r3 = srow[i + 3];
        uint4 v0 = ((const uint4*)(hs + (size_t)r0 * D))[lane];
        uint4 v1 = ((const uint4*)(hs + (size_t)r1 * D))[lane];
        uint4 v2 = ((const uint4*)(hs + (size_t)r2 * D))[lane];
        uint4 v3 = ((const uint4*)(hs + (size_t)r3 * D))[lane];
        bf16x8_add(v0, acc); bf16x8_add(v1, acc);
        bf16x8_add(v2, acc); bf16x8_add(v3, acc);
    }
    for (; i < e; i++) {
        int r = srow[i];
        uint4 v = ((const uint4*)(hs + (size_t)r * D))[lane];
        bf16x8_add(v, acc);
    }

    float dc = dinv[node];
    float4 b_lo = ((const float4*)bias)[lane * 2];
    float4 b_hi = ((const float4*)bias)[lane * 2 + 1];
    float4 r0, r1;
    r0.x = fmaxf(fmaf(acc[0], dc, b_lo.x), 0.f);
    r0.y = fmaxf(fmaf(acc[1], dc, b_lo.y), 0.f);
    r0.z = fmaxf(fmaf(acc[2], dc, b_lo.z), 0.f);
    r0.w = fmaxf(fmaf(acc[3], dc, b_lo.w), 0.f);
    r1.x = fmaxf(fmaf(acc[4], dc, b_hi.x), 0.f);
    r1.y = fmaxf(fmaf(acc[5], dc, b_hi.y), 0.f);
    r1.z = fmaxf(fmaf(acc[6], dc, b_hi.z), 0.f);
    r1.w = fmaxf(fmaf(acc[7], dc, b_hi.w), 0.f);
    float4* o = (float4*)(out + (size_t)node * D);
    o[lane * 2]     = r0;
    o[lane * 2 + 1] = r1;
}

// ---------------- tf32 tensor-core GEMM ----------------
// out[N x 256] = A[N x K] @ W[K x 256]  (+bias+relu | *dinv[row], bf16 out)
// 128x128x32 tiles, 8 warps; warp computes 32(m) x 64(n) via m16n8k8 frags.
__device__ __forceinline__ unsigned f2tf32(float f) {
    unsigned r;
    asm("cvt.rna.tf32.f32 %0, %1;" : "=r"(r) : "f"(f));
    return r;
}

__device__ __forceinline__ void mma_tf32(float* c, const unsigned* a, const unsigned* b) {
    asm volatile(
        "mma.sync.aligned.m16n8k8.row.col.f32.tf32.tf32.f32 "
        "{%0,%1,%2,%3}, {%4,%5,%6,%7}, {%8,%9}, {%0,%1,%2,%3};"
        : "+f"(c[0]), "+f"(c[1]), "+f"(c[2]), "+f"(c[3])
        : "r"(a[0]), "r"(a[1]), "r"(a[2]), "r"(a[3]), "r"(b[0]), "r"(b[1]));
}

template <int K, bool RELU, bool SCALE, typename OutT>
__global__ __launch_bounds__(256)
void gemm_tc_kernel(const float* __restrict__ A, const float* __restrict__ W,
                    const float* __restrict__ bias, const float* __restrict__ dinv,
                    OutT* __restrict__ out)
{
    constexpr int BM = 128, BN = 128, BK = 32;
    constexpr int APAD = 36, BPAD = 132;
    __shared__ unsigned As[BM][APAD];
    __shared__ unsigned Bs[BK][BPAD];

    const int tid  = threadIdx.x;
    const int wid  = tid >> 5;
    const int lane = tid & 31;
    const int gid  = lane >> 2;     // groupID 0..7
    const int tig  = lane & 3;      // thread-in-group 0..3
    const int wm   = (wid & 3) * 32;
    const int wn   = (wid >> 2) * 64;

    const int m0 = blockIdx.x * BM;
    const int n0 = blockIdx.y * BN;

    float c[2][8][4];
    #pragma unroll
    for (int mt = 0; mt < 2; mt++)
        #pragma unroll
        for (int nt = 0; nt < 8; nt++)
            #pragma unroll
            for (int r = 0; r < 4; r++) c[mt][nt][r] = 0.f;

    for (int k0 = 0; k0 < K; k0 += BK) {
        // A tile: 128 rows x 32 cols
        #pragma unroll
        for (int it = 0; it < 4; it++) {
            int r  = it * 32 + (tid >> 3);
            int c4 = (tid & 7) * 4;
            float4 v = make_float4(0.f, 0.f, 0.f, 0.f);
            if (m0 + r < N_NODES)
                v = *(const float4*)(A + (size_t)(m0 + r) * K + k0 + c4);
            uint4 u;
            u.x = f2tf32(v.x); u.y = f2tf32(v.y);
            u.z = f2tf32(v.z); u.w = f2tf32(v.w);
            *(uint4*)&As[r][c4] = u;
        }
        // B tile: 32 k-rows x 128 n-cols
        #pragma unroll
        for (int it = 0; it < 4; it++) {
            int kr = it * 8 + (tid >> 5);
            int c4 = (tid & 31) * 4;
            float4 v = *(const float4*)(W + (size_t)(k0 + kr) * D + n0 + c4);
            uint4 u;
            u.x = f2tf32(v.x); u.y = f2tf32(v.y);
            u.z = f2tf32(v.z); u.w = f2tf32(v.w);
            *(uint4*)&Bs[kr][c4] = u;
        }
        __syncthreads();

        #pragma unroll
        for (int ks = 0; ks < 4; ks++) {
            int kb = ks * 8;
            unsigned a[2][4];
            #pragma unroll
            for (int mt = 0; mt < 2; mt++) {
                int row = wm + mt * 16;
                a[mt][0] = As[row + gid    ][kb + tig];
                a[mt][1] = As[row + gid + 8][kb + tig];
                a[mt][2] = As[row + gid    ][kb + tig + 4];
                a[mt][3] = As[row + gid + 8][kb + tig + 4];
            }
            unsigned b[8][2];
            #pragma unroll
            for (int nt = 0; nt < 8; nt++) {
                int col = wn + nt * 8 + gid;
                b[nt][0] = Bs[kb + tig    ][col];
                b[nt][1] = Bs[kb + tig + 4][col];
            }
            #pragma unroll
            for (int mt = 0; mt < 2; mt++)
                #pragma unroll
                for (int nt = 0; nt < 8; nt++)
                    mma_tf32(c[mt][nt], a[mt], b[nt]);
        }
        __syncthreads();
    }

    // epilogue
    #pragma unroll
    for (int mt = 0; mt < 2; mt++) {
        #pragma unroll
        for (int rh = 0; rh < 2; rh++) {
            int row = m0 + wm + mt * 16 + gid + rh * 8;
            if (row >= N_NODES) continue;
            float sc = SCALE ? dinv[row] : 1.f;
            #pragma unroll
            for (int nt = 0; nt < 8; nt++) {
                int col = n0 + wn + nt * 8 + 2 * tig;
                float v0 = c[mt][nt][rh * 2 + 0] * sc;
                float v1 = c[mt][nt][rh * 2 + 1] * sc;
                if (RELU) {
                    v0 = fmaxf(v0 + bias[col],     0.f);
                    v1 = fmaxf(v1 + bias[col + 1], 0.f);
                }
                if constexpr (sizeof(OutT) == 4) {
                    float2 v; v.x = v0; v.y = v1;
                    *(float2*)((float*)out + (size_t)row * D + col) = v;
                } else {
                    __nv_bfloat162 p = __floats2bfloat162_rn(v0, v1);
                    *(unsigned*)((__nv_bfloat16*)out + (size_t)row * D + col) =
                        *(unsigned*)&p;
                }
            }
        }
    }
}

// ---------------- global mean pool ----------------
__device__ __forceinline__ int lower_bound_i(const int* a, int n, int v) {
    int lo = 0, hi = n;
    while (lo < hi) {
        int mid = (lo + hi) >> 1;
        if (a[mid] < v) lo = mid + 1; else hi = mid;
    }
    return lo;
}

__global__ __launch_bounds__(128)
void pool_kernel(const float* __restrict__ h, const int* __restrict__ batch,
                 float* __restrict__ out)
{
    int g = blockIdx.x;
    int t = blockIdx.y * 128 + threadIdx.x;
    __shared__ int slo, shi;
    if (threadIdx.x == 0) slo = lower_bound_i(batch, N_NODES, g);
    if (threadIdx.x == 1) shi = lower_bound_i(batch, N_NODES, g + 1);
    __syncthreads();
    int lo = slo, hi = shi;
    float s = 0.f;
    for (int n = lo; n < hi; n++)
        s += h[(size_t)n * D + t];
    int cnt = hi - lo;
    out[g * D + t] = s / (float)max(cnt, 1);
}

// ---------------------------------------------------------------------------
extern "C" void kernel_launch(void* const* d_in, const int* in_sizes, int n_in,
                              void* d_out, int out_size)
{
    const float* x     = (const float*)d_in[0];
    const int*   eidx  = (const int*)  d_in[1];
    const int*   batch = (const int*)  d_in[2];
    const float* W1    = (const float*)d_in[3];
    const float* b1    = (const float*)d_in[4];
    const float* W2    = (const float*)d_in[5];
    const float* b2    = (const float*)d_in[6];
    float* out = (float*)d_out;

    const int* erow = eidx;
    const int* ecol = eidx + N_EDGES;

    int *cnt, *startp, *cursor, *srow, *bsum, *boff;
    float *dinv, *agg128, *h, *h2;
    __nv_bfloat16* hs;
    cudaGetSymbolAddress((void**)&cnt,    g_cnt);
    cudaGetSymbolAddress((void**)&dinv,   g_dinv);
    cudaGetSymbolAddress((void**)&startp, g_start);
    cudaGetSymbolAddress((void**)&cursor, g_cursor);
    cudaGetSymbolAddress((void**)&srow,   g_srow);
    cudaGetSymbolAddress((void**)&bsum,   g_bsum);
    cudaGetSymbolAddress((void**)&boff,   g_boff);
    cudaGetSymbolAddress((void**)&agg128, g_agg128);
    cudaGetSymbolAddress((void**)&h,      g_h);
    cudaGetSymbolAddress((void**)&hs,     g_hs);
    cudaGetSymbolAddress((void**)&h2,     g_h2);

    // CSR build
    zero_cnt_kernel   <<<(N_NODES + 255) / 256, 256>>>(cnt);
    hist_kernel       <<<(N_EDGES + 255) / 256, 256>>>(ecol, cnt);
    dinv_kernel       <<<(N_NODES + 255) / 256, 256>>>(cnt, dinv);
    partial_sum_kernel<<<SCAN_NB, 256>>>(cnt, bsum);
    scan_bsum_kernel  <<<1, 128>>>(bsum, boff);
    scan_final_kernel <<<SCAN_NB, 256>>>(cnt, boff, startp, cursor);
    place_kernel      <<<(N_EDGES + 255) / 256, 256>>>(erow, ecol, cursor, srow);

    dim3 ggrid((N_NODES + 127) / 128, 2);
    int  agrid = (N_NODES * 32 + 255) / 256;

    // layer 1: aggregate(128) -> tf32 gemm + bias + relu
    agg1_kernel<<<agrid, 256>>>(x, srow, startp, dinv, agg128);
    gemm_tc_kernel<IN_DIM, true, false, float><<<ggrid, 256>>>(agg128, W1, b1, dinv, h);

    // layer 2: tf32 gemm * dinv (bf16 out) -> aggregate + bias + relu
    gemm_tc_kernel<HID_DIM, false, true, __nv_bfloat16><<<ggrid, 256>>>(h, W2, b2, dinv, hs);
    agg2_kernel<<<agrid, 256>>>(hs, srow, startp, dinv, b2, h2);

    // pool
    pool_kernel<<<dim3(N_GRAPHS, 2), 128>>>(h2, batch, out);
}

// round 8
// speedup vs baseline: 3.7510x; 1.1993x over previous
#include <cuda_runtime.h>
#include <cuda_bf16.h>
#include <cstdint>

#define N_NODES  100000
#define N_EDGES  1600000
#define N_GRAPHS 64
#define IN_DIM   128
#define HID_DIM  256
#define OUT_DIM  256
#define D        256
#define SCAN_NB  98          // ceil(N_NODES / 1024)

// ---------------- scratch (no allocs allowed) ----------------
__device__ int   g_cnt   [N_NODES];
__device__ float g_dinv  [N_NODES];
__device__ int   g_start [N_NODES + 1];
__device__ int   g_cursor[N_NODES];
__device__ int   g_srow  [N_EDGES];
__device__ int   g_bsum  [SCAN_NB];
__device__ int   g_boff  [SCAN_NB];
__device__ __nv_bfloat16 g_xs[(size_t)N_NODES * IN_DIM];   // bf16(x * dinv)
__device__ float g_agg128[(size_t)N_NODES * IN_DIM];
__device__ float g_h     [(size_t)N_NODES * D];
__device__ __nv_bfloat16 g_hs[(size_t)N_NODES * D];
__device__ float g_h2    [(size_t)N_NODES * D];

// ---------------- degree / CSR build ----------------
__global__ void zero_cnt_kernel(int* cnt) {
    int i = blockIdx.x * blockDim.x + threadIdx.x;
    if (i < N_NODES) cnt[i] = 0;
}

__global__ void hist_kernel(const int* __restrict__ cols, int* cnt) {
    int e = blockIdx.x * blockDim.x + threadIdx.x;
    if (e < N_EDGES) atomicAdd(&cnt[cols[e]], 1);
}

__global__ void dinv_kernel(const int* __restrict__ cnt, float* __restrict__ dinv) {
    int i = blockIdx.x * blockDim.x + threadIdx.x;
    if (i < N_NODES) dinv[i] = rsqrtf((float)(cnt[i] + 1));   // +1 self loop
}

// ---- 3-phase exclusive scan of cnt -> start/cursor ----
__global__ __launch_bounds__(256)
void partial_sum_kernel(const int* __restrict__ cnt, int* __restrict__ bsum) {
    __shared__ int sh[256];
    int b = blockIdx.x, t = threadIdx.x;
    int base = b * 1024;
    int s = 0;
    #pragma unroll
    for (int j = 0; j < 4; j++) {
        int i = base + t + j * 256;
        if (i < N_NODES) s += cnt[i];
    }
    sh[t] = s;
    __syncthreads();
    for (int off = 128; off > 0; off >>= 1) {
        if (t < off) sh[t] += sh[t + off];
        __syncthreads();
    }
    if (t == 0) bsum[b] = sh[0];
}

__global__ __launch_bounds__(128)
void scan_bsum_kernel(const int* __restrict__ bsum, int* __restrict__ boff) {
    __shared__ int sh[128];
    int t = threadIdx.x;
    sh[t] = (t < SCAN_NB) ? bsum[t] : 0;
    __syncthreads();
    for (int off = 1; off < 128; off <<= 1) {
        int v = (t >= off) ? sh[t - off] : 0;
        __syncthreads();
        sh[t] += v;
        __syncthreads();
    }
    if (t < SCAN_NB) boff[t] = (t == 0) ? 0 : sh[t - 1];
}

__global__ __launch_bounds__(256)
void scan_final_kernel(const int* __restrict__ cnt, const int* __restrict__ boff,
                       int* __restrict__ start, int* __restrict__ cursor) {
    __shared__ int sh[256];
    int b = blockIdx.x, t = threadIdx.x;
    int base = b * 1024 + t * 4;
    int c[4];
    int s = 0;
    #pragma unroll
    for (int j = 0; j < 4; j++) {
        int i = base + j;
        c[j] = (i < N_NODES) ? cnt[i] : 0;
        s += c[j];
    }
    sh[t] = s;
    __syncthreads();
    for (int off = 1; off < 256; off <<= 1) {
        int v = (t >= off) ? sh[t - off] : 0;
        __syncthreads();
        sh[t] += v;
        __syncthreads();
    }
    int pre = boff[b] + ((t == 0) ? 0 : sh[t - 1]);
    #pragma unroll
    for (int j = 0; j < 4; j++) {
        int i = base + j;
        if (i < N_NODES) { start[i] = pre; cursor[i] = pre; }
        pre += c[j];
    }
    if (b == 0 && t == 0) start[N_NODES] = N_EDGES;
}

__global__ void place_kernel(const int* __restrict__ rows, const int* __restrict__ cols,
                             int* cursor, int* __restrict__ srow)
{
    int e = blockIdx.x * blockDim.x + threadIdx.x;
    if (e >= N_EDGES) return;
    int c = cols[e];
    int p = atomicAdd(&cursor[c], 1);
    srow[p] = rows[e];
}

// ---------------- xs = bf16(x * dinv[node]) ----------------
__global__ __launch_bounds__(256)
void scale_x_kernel(const float* __restrict__ x, const float* __restrict__ dinv,
                    __nv_bfloat16* __restrict__ xs)
{
    int idx = blockIdx.x * blockDim.x + threadIdx.x;   // bf16x2 index
    if (idx >= N_NODES * (IN_DIM / 2)) return;
    int node = idx >> 6;                // 64 pairs per row
    float dc = dinv[node];
    float2 v = ((const float2*)x)[idx];
    __nv_bfloat162 p = __floats2bfloat162_rn(v.x * dc, v.y * dc);
    ((__nv_bfloat162*)xs)[idx] = p;
}

// ---------------- layer-1 aggregation (bf16 gather, fp32 accumulate) ----------------
// out[c] = dinv[c] * ( xs[c] + sum_{r in N(c)} xs[r] ),  xs = bf16(dinv*x)
__device__ __forceinline__ void bf16x4_add(uint2 v, float* a) {
    float2 f0 = __bfloat1622float2(*(__nv_bfloat162*)&v.x);
    float2 f1 = __bfloat1622float2(*(__nv_bfloat162*)&v.y);
    a[0] += f0.x; a[1] += f0.y; a[2] += f1.x; a[3] += f1.y;
}

__global__ __launch_bounds__(256)
void agg1_kernel(const __nv_bfloat16* __restrict__ xs, const int* __restrict__ srow,
                 const int* __restrict__ start, const float* __restrict__ dinv,
                 float* __restrict__ out)
{
    int warp = (blockIdx.x * blockDim.x + threadIdx.x) >> 5;
    int lane = threadIdx.x & 31;
    if (warp >= N_NODES) return;
    int node = warp;
    int s = start[node], e = start[node + 1];

    float acc[4] = {0, 0, 0, 0};
    uint2 sv = ((const uint2*)(xs + (size_t)node * IN_DIM))[lane];
    bf16x4_add(sv, acc);

    int i = s;
    for (; i + 4 <= e; i += 4) {
        int r0 = srow[i], r1 = srow[i + 1], r2 = srow[i + 2], r3 = srow[i + 3];
        uint2 v0 = ((const uint2*)(xs + (size_t)r0 * IN_DIM))[lane];
        uint2 v1 = ((const uint2*)(xs + (size_t)r1 * IN_DIM))[lane];
        uint2 v2 = ((const uint2*)(xs + (size_t)r2 * IN_DIM))[lane];
        uint2 v3 = ((const uint2*)(xs + (size_t)r3 * IN_DIM))[lane];
        bf16x4_add(v0, acc); bf16x4_add(v1, acc);
        bf16x4_add(v2, acc); bf16x4_add(v3, acc);
    }
    for (; i < e; i++) {
        int r = srow[i];
        uint2 v = ((const uint2*)(xs + (size_t)r * IN_DIM))[lane];
        bf16x4_add(v, acc);
    }

    float dc = dinv[node];
    float4 o;
    o.x = acc[0] * dc; o.y = acc[1] * dc; o.z = acc[2] * dc; o.w = acc[3] * dc;
    ((float4*)(out + (size_t)node * IN_DIM))[lane] = o;
}

// ---------------- layer-2 aggregation (bf16 gather, fp32 accumulate) ----------------
__device__ __forceinline__ void bf16x8_add(uint4 v, float* a) {
    float2 f0 = __bfloat1622float2(*(__nv_bfloat162*)&v.x);
    float2 f1 = __bfloat1622float2(*(__nv_bfloat162*)&v.y);
    float2 f2 = __bfloat1622float2(*(__nv_bfloat162*)&v.z);
    float2 f3 = __bfloat1622float2(*(__nv_bfloat162*)&v.w);
    a[0] += f0.x; a[1] += f0.y; a[2] += f1.x; a[3] += f1.y;
    a[4] += f2.x; a[5] += f2.y; a[6] += f3.x; a[7] += f3.y;
}

__global__ __launch_bounds__(256)
void agg2_kernel(const __nv_bfloat16* __restrict__ hs, const int* __restrict__ srow,
                 const int* __restrict__ start, const float* __restrict__ dinv,
                 const float* __restrict__ bias, float* __restrict__ out)
{
    int warp = (blockIdx.x * blockDim.x + threadIdx.x) >> 5;
    int lane = threadIdx.x & 31;
    if (warp >= N_NODES) return;
    int node = warp;
    int s = start[node], e = start[node + 1];

    float acc[8] = {0, 0, 0, 0, 0, 0, 0, 0};
    uint4 sv = ((const uint4*)(hs + (size_t)node * D))[lane];
    bf16x8_add(sv, acc);

    int i = s;
    for (; i + 4 <= e; i += 4) {
        int r0 = srow[i], r1 = srow[i + 1], r2 = srow[i + 2], r3 = srow[i + 3];
        uint4 v0 = ((const uint4*)(hs + (size_t)r0 * D))[lane];
        uint4 v1 = ((const uint4*)(hs + (size_t)r1 * D))[lane];
        uint4 v2 = ((const uint4*)(hs + (size_t)r2 * D))[lane];
        uint4 v3 = ((const uint4*)(hs + (size_t)r3 * D))[lane];
        bf16x8_add(v0, acc); bf16x8_add(v1, acc);
        bf16x8_add(v2, acc); bf16x8_add(v3, acc);
    }
    for (; i < e; i++) {
        int r = srow[i];
        uint4 v = ((const uint4*)(hs + (size_t)r * D))[lane];
        bf16x8_add(v, acc);
    }

    float dc = dinv[node];
    float4 b_lo = ((const float4*)bias)[lane * 2];
    float4 b_hi = ((const float4*)bias)[lane * 2 + 1];
    float4 r0, r1;
    r0.x = fmaxf(fmaf(acc[0], dc, b_lo.x), 0.f);
    r0.y = fmaxf(fmaf(acc[1], dc, b_lo.y), 0.f);
    r0.z = fmaxf(fmaf(acc[2], dc, b_lo.z), 0.f);
    r0.w = fmaxf(fmaf(acc[3], dc, b_lo.w), 0.f);
    r1.x = fmaxf(fmaf(acc[4], dc, b_hi.x), 0.f);
    r1.y = fmaxf(fmaf(acc[5], dc, b_hi.y), 0.f);
    r1.z = fmaxf(fmaf(acc[6], dc, b_hi.z), 0.f);
    r1.w = fmaxf(fmaf(acc[7], dc, b_hi.w), 0.f);
    float4* o = (float4*)(out + (size_t)node * D);
    o[lane * 2]     = r0;
    o[lane * 2 + 1] = r1;
}

// ---------------- tf32 tensor-core GEMM ----------------
__device__ __forceinline__ unsigned f2tf32(float f) {
    unsigned r;
    asm("cvt.rna.tf32.f32 %0, %1;" : "=r"(r) : "f"(f));
    return r;
}

__device__ __forceinline__ void mma_tf32(float* c, const unsigned* a, const unsigned* b) {
    asm volatile(
        "mma.sync.aligned.m16n8k8.row.col.f32.tf32.tf32.f32 "
        "{%0,%1,%2,%3}, {%4,%5,%6,%7}, {%8,%9}, {%0,%1,%2,%3};"
        : "+f"(c[0]), "+f"(c[1]), "+f"(c[2]), "+f"(c[3])
        : "r"(a[0]), "r"(a[1]), "r"(a[2]), "r"(a[3]), "r"(b[0]), "r"(b[1]));
}

template <int K, bool RELU, bool SCALE, typename OutT>
__global__ __launch_bounds__(256)
void gemm_tc_kernel(const float* __restrict__ A, const float* __restrict__ W,
                    const float* __restrict__ bias, const float* __restrict__ dinv,
                    OutT* __restrict__ out)
{
    constexpr int BM = 128, BN = 128, BK = 32;
    constexpr int APAD = 36, BPAD = 132;
    __shared__ unsigned As[BM][APAD];
    __shared__ unsigned Bs[BK][BPAD];

    const int tid  = threadIdx.x;
    const int wid  = tid >> 5;
    const int lane = tid & 31;
    const int gid  = lane >> 2;
    const int tig  = lane & 3;
    const int wm   = (wid & 3) * 32;
    const int wn   = (wid >> 2) * 64;

    const int m0 = blockIdx.x * BM;
    const int n0 = blockIdx.y * BN;

    float c[2][8][4];
    #pragma unroll
    for (int mt = 0; mt < 2; mt++)
        #pragma unroll
        for (int nt = 0; nt < 8; nt++)
            #pragma unroll
            for (int r = 0; r < 4; r++) c[mt][nt][r] = 0.f;

    for (int k0 = 0; k0 < K; k0 += BK) {
        #pragma unroll
        for (int it = 0; it < 4; it++) {
            int r  = it * 32 + (tid >> 3);
            int c4 = (tid & 7) * 4;
            float4 v = make_float4(0.f, 0.f, 0.f, 0.f);
            if (m0 + r < N_NODES)
                v = *(const float4*)(A + (size_t)(m0 + r) * K + k0 + c4);
            uint4 u;
            u.x = f2tf32(v.x); u.y = f2tf32(v.y);
            u.z = f2tf32(v.z); u.w = f2tf32(v.w);
            *(uint4*)&As[r][c4] = u;
        }
        #pragma unroll
        for (int it = 0; it < 4; it++) {
            int kr = it * 8 + (tid >> 5);
            int c4 = (tid & 31) * 4;
            float4 v = *(const float4*)(W + (size_t)(k0 + kr) * D + n0 + c4);
            uint4 u;
            u.x = f2tf32(v.x); u.y = f2tf32(v.y);
            u.z = f2tf32(v.z); u.w = f2tf32(v.w);
            *(uint4*)&Bs[kr][c4] = u;
        }
        __syncthreads();

        #pragma unroll
        for (int ks = 0; ks < 4; ks++) {
            int kb = ks * 8;
            unsigned a[2][4];
            #pragma unroll
            for (int mt = 0; mt < 2; mt++) {
                int row = wm + mt * 16;
                a[mt][0] = As[row + gid    ][kb + tig];
                a[mt][1] = As[row + gid + 8][kb + tig];
                a[mt][2] = As[row + gid    ][kb + tig + 4];
                a[mt][3] = As[row + gid + 8][kb + tig + 4];
            }
            unsigned b[8][2];
            #pragma unroll
            for (int nt = 0; nt < 8; nt++) {
                int col = wn + nt * 8 + gid;
                b[nt][0] = Bs[kb + tig    ][col];
                b[nt][1] = Bs[kb + tig + 4][col];
            }
            #pragma unroll
            for (int mt = 0; mt < 2; mt++)
                #pragma unroll
                for (int nt = 0; nt < 8; nt++)
                    mma_tf32(c[mt][nt], a[mt], b[nt]);
        }
        __syncthreads();
    }

    #pragma unroll
    for (int mt = 0; mt < 2; mt++) {
        #pragma unroll
        for (int rh = 0; rh < 2; rh++) {
            int row = m0 + wm + mt * 16 + gid + rh * 8;
            if (row >= N_NODES) continue;
            float sc = SCALE ? dinv[row] : 1.f;
            #pragma unroll
            for (int nt = 0; nt < 8; nt++) {
                int col = n0 + wn + nt * 8 + 2 * tig;
                float v0 = c[mt][nt][rh * 2 + 0] * sc;
                float v1 = c[mt][nt][rh * 2 + 1] * sc;
                if (RELU) {
                    v0 = fmaxf(v0 + bias[col],     0.f);
                    v1 = fmaxf(v1 + bias[col + 1], 0.f);
                }
                if constexpr (sizeof(OutT) == 4) {
                    float2 v; v.x = v0; v.y = v1;
                    *(float2*)((float*)out + (size_t)row * D + col) = v;
                } else {
                    __nv_bfloat162 p = __floats2bfloat162_rn(v0, v1);
                    *(unsigned*)((__nv_bfloat16*)out + (size_t)row * D + col) =
                        *(unsigned*)&p;
                }
            }
        }
    }
}

// ---------------- global mean pool (parallel, atomic partials) ----------------
#define POOL_CH 4

__global__ void zero_out_kernel(float* out) {
    int i = blockIdx.x * blockDim.x + threadIdx.x;
    if (i < N_GRAPHS * D) out[i] = 0.f;
}

__device__ __forceinline__ int lower_bound_i(const int* a, int n, int v) {
    int lo = 0, hi = n;
    while (lo < hi) {
        int mid = (lo + hi) >> 1;
        if (a[mid] < v) lo = mid + 1; else hi = mid;
    }
    return lo;
}

__global__ __launch_bounds__(128)
void pool_kernel(const float* __restrict__ h, const int* __restrict__ batch,
                 float* __restrict__ out)
{
    int g  = blockIdx.x;
    int t  = blockIdx.y * 128 + threadIdx.x;
    int ch = blockIdx.z;
    __shared__ int slo, shi;
    if (threadIdx.x == 0) slo = lower_bound_i(batch, N_NODES, g);
    if (threadIdx.x == 1) shi = lower_bound_i(batch, N_NODES, g + 1);
    __syncthreads();
    int lo = slo, hi = shi;
    int cnt = hi - lo;
    int len = (cnt + POOL_CH - 1) / POOL_CH;
    int a = lo + ch * len;
    int b = min(a + len, hi);
    if (a >= b) return;
    float s = 0.f;
    for (int n = a; n < b; n++)
        s += h[(size_t)n * D + t];
    atomicAdd(&out[g * D + t], s / (float)max(cnt, 1));
}

// ---------------------------------------------------------------------------
extern "C" void kernel_launch(void* const* d_in, const int* in_sizes, int n_in,
                              void* d_out, int out_size)
{
    const float* x     = (const float*)d_in[0];
    const int*   eidx  = (const int*)  d_in[1];
    const int*   batch = (const int*)  d_in[2];
    const float* W1    = (const float*)d_in[3];
    const float* b1    = (const float*)d_in[4];
    const float* W2    = (const float*)d_in[5];
    const float* b2    = (const float*)d_in[6];
    float* out = (float*)d_out;

    const int* erow = eidx;
    const int* ecol = eidx + N_EDGES;

    int *cnt, *startp, *cursor, *srow, *bsum, *boff;
    float *dinv, *agg128, *h, *h2;
    __nv_bfloat16 *hs, *xs;
    cudaGetSymbolAddress((void**)&cnt,    g_cnt);
    cudaGetSymbolAddress((void**)&dinv,   g_dinv);
    cudaGetSymbolAddress((void**)&startp, g_start);
    cudaGetSymbolAddress((void**)&cursor, g_cursor);
    cudaGetSymbolAddress((void**)&srow,   g_srow);
    cudaGetSymbolAddress((void**)&bsum,   g_bsum);
    cudaGetSymbolAddress((void**)&boff,   g_boff);
    cudaGetSymbolAddress((void**)&xs,     g_xs);
    cudaGetSymbolAddress((void**)&agg128, g_agg128);
    cudaGetSymbolAddress((void**)&h,      g_h);
    cudaGetSymbolAddress((void**)&hs,     g_hs);
    cudaGetSymbolAddress((void**)&h2,     g_h2);

    // CSR build
    zero_cnt_kernel   <<<(N_NODES + 255) / 256, 256>>>(cnt);
    hist_kernel       <<<(N_EDGES + 255) / 256, 256>>>(ecol, cnt);
    dinv_kernel       <<<(N_NODES + 255) / 256, 256>>>(cnt, dinv);
    partial_sum_kernel<<<SCAN_NB, 256>>>(cnt, bsum);
    scan_bsum_kernel  <<<1, 128>>>(bsum, boff);
    scan_final_kernel <<<SCAN_NB, 256>>>(cnt, boff, startp, cursor);
    place_kernel      <<<(N_EDGES + 255) / 256, 256>>>(erow, ecol, cursor, srow);

    dim3 ggrid((N_NODES + 127) / 128, 2);
    int  agrid = (N_NODES * 32 + 255) / 256;

    // layer 1: xs=bf16(x*dinv) -> aggregate(128, bf16) -> tf32 gemm + bias + relu
    scale_x_kernel<<<(N_NODES * (IN_DIM / 2) + 255) / 256, 256>>>(x, dinv, xs);
    agg1_kernel<<<agrid, 256>>>(xs, srow, startp, dinv, agg128);
    gemm_tc_kernel<IN_DIM, true, false, float><<<ggrid, 256>>>(agg128, W1, b1, dinv, h);

    // layer 2: tf32 gemm * dinv (bf16 out) -> aggregate + bias + relu
    gemm_tc_kernel<HID_DIM, false, true, __nv_bfloat16><<<ggrid, 256>>>(h, W2, b2, dinv, hs);
    agg2_kernel<<<agrid, 256>>>(hs, srow, startp, dinv, b2, h2);

    // pool (zero-init + parallel partials)
    zero_out_kernel<<<(N_GRAPHS * D + 255) / 256, 256>>>(out);
    pool_kernel<<<dim3(N_GRAPHS, 2, POOL_CH), 128>>>(h2, batch, out);
}

// round 9
// speedup vs baseline: 3.8314x; 1.0214x over previous
#include <cuda_runtime.h>
#include <cuda_bf16.h>
#include <cstdint>

#define N_NODES  100000
#define N_EDGES  1600000
#define N_GRAPHS 64
#define IN_DIM   128
#define HID_DIM  256
#define OUT_DIM  256
#define D        256
#define SCAN_NB  98          // ceil(N_NODES / 1024)
#define POOL_CH  24          // chunks per graph in fused agg2+pool

// ---------------- scratch (no allocs allowed) ----------------
__device__ int   g_cnt   [N_NODES];
__device__ float g_dinv  [N_NODES];
__device__ int   g_start [N_NODES + 1];
__device__ int   g_cursor[N_NODES];
__device__ int   g_srow  [N_EDGES];
__device__ int   g_bsum  [SCAN_NB];
__device__ int   g_boff  [SCAN_NB];
__device__ __nv_bfloat16 g_xs[(size_t)N_NODES * IN_DIM];   // bf16(x * dinv)
__device__ float g_agg128[(size_t)N_NODES * IN_DIM];
__device__ float g_h     [(size_t)N_NODES * D];
__device__ __nv_bfloat16 g_hs[(size_t)N_NODES * D];

// ---------------- degree / CSR build ----------------
__global__ void zero_cnt_kernel(int* cnt) {
    int i = blockIdx.x * blockDim.x + threadIdx.x;
    if (i < N_NODES) cnt[i] = 0;
}

__global__ void hist_kernel(const int* __restrict__ cols, int* cnt) {
    int e = blockIdx.x * blockDim.x + threadIdx.x;
    if (e < N_EDGES) atomicAdd(&cnt[cols[e]], 1);
}

__global__ void dinv_kernel(const int* __restrict__ cnt, float* __restrict__ dinv) {
    int i = blockIdx.x * blockDim.x + threadIdx.x;
    if (i < N_NODES) dinv[i] = rsqrtf((float)(cnt[i] + 1));   // +1 self loop
}

// ---- 3-phase exclusive scan of cnt -> start/cursor ----
__global__ __launch_bounds__(256)
void partial_sum_kernel(const int* __restrict__ cnt, int* __restrict__ bsum) {
    __shared__ int sh[256];
    int b = blockIdx.x, t = threadIdx.x;
    int base = b * 1024;
    int s = 0;
    #pragma unroll
    for (int j = 0; j < 4; j++) {
        int i = base + t + j * 256;
        if (i < N_NODES) s += cnt[i];
    }
    sh[t] = s;
    __syncthreads();
    for (int off = 128; off > 0; off >>= 1) {
        if (t < off) sh[t] += sh[t + off];
        __syncthreads();
    }
    if (t == 0) bsum[b] = sh[0];
}

__global__ __launch_bounds__(128)
void scan_bsum_kernel(const int* __restrict__ bsum, int* __restrict__ boff) {
    __shared__ int sh[128];
    int t = threadIdx.x;
    sh[t] = (t < SCAN_NB) ? bsum[t] : 0;
    __syncthreads();
    for (int off = 1; off < 128; off <<= 1) {
        int v = (t >= off) ? sh[t - off] : 0;
        __syncthreads();
        sh[t] += v;
        __syncthreads();
    }
    if (t < SCAN_NB) boff[t] = (t == 0) ? 0 : sh[t - 1];
}

__global__ __launch_bounds__(256)
void scan_final_kernel(const int* __restrict__ cnt, const int* __restrict__ boff,
                       int* __restrict__ start, int* __restrict__ cursor) {
    __shared__ int sh[256];
    int b = blockIdx.x, t = threadIdx.x;
    int base = b * 1024 + t * 4;
    int c[4];
    int s = 0;
    #pragma unroll
    for (int j = 0; j < 4; j++) {
        int i = base + j;
        c[j] = (i < N_NODES) ? cnt[i] : 0;
        s += c[j];
    }
    sh[t] = s;
    __syncthreads();
    for (int off = 1; off < 256; off <<= 1) {
        int v = (t >= off) ? sh[t - off] : 0;
        __syncthreads();
        sh[t] += v;
        __syncthreads();
    }
    int pre = boff[b] + ((t == 0) ? 0 : sh[t - 1]);
    #pragma unroll
    for (int j = 0; j < 4; j++) {
        int i = base + j;
        if (i < N_NODES) { start[i] = pre; cursor[i] = pre; }
        pre += c[j];
    }
    if (b == 0 && t == 0) start[N_NODES] = N_EDGES;
}

__global__ void place_kernel(const int* __restrict__ rows, const int* __restrict__ cols,
                             int* cursor, int* __restrict__ srow)
{
    int e = blockIdx.x * blockDim.x + threadIdx.x;
    if (e >= N_EDGES) return;
    int c = cols[e];
    int p = atomicAdd(&cursor[c], 1);
    srow[p] = rows[e];
}

// ---------------- xs = bf16(x * dinv[node]) ----------------
__global__ __launch_bounds__(256)
void scale_x_kernel(const float* __restrict__ x, const float* __restrict__ dinv,
                    __nv_bfloat16* __restrict__ xs)
{
    int idx = blockIdx.x * blockDim.x + threadIdx.x;   // bf16x2 index
    if (idx >= N_NODES * (IN_DIM / 2)) return;
    int node = idx >> 6;                // 64 pairs per row
    float dc = dinv[node];
    float2 v = ((const float2*)x)[idx];
    __nv_bfloat162 p = __floats2bfloat162_rn(v.x * dc, v.y * dc);
    ((__nv_bfloat162*)xs)[idx] = p;
}

// ---------------- layer-1 aggregation (bf16 gather, fp32 accumulate) ----------------
__device__ __forceinline__ void bf16x4_add(uint2 v, float* a) {
    float2 f0 = __bfloat1622float2(*(__nv_bfloat162*)&v.x);
    float2 f1 = __bfloat1622float2(*(__nv_bfloat162*)&v.y);
    a[0] += f0.x; a[1] += f0.y; a[2] += f1.x; a[3] += f1.y;
}

__global__ __launch_bounds__(256)
void agg1_kernel(const __nv_bfloat16* __restrict__ xs, const int* __restrict__ srow,
                 const int* __restrict__ start, const float* __restrict__ dinv,
                 float* __restrict__ out)
{
    int warp = (blockIdx.x * blockDim.x + threadIdx.x) >> 5;
    int lane = threadIdx.x & 31;
    if (warp >= N_NODES) return;
    int node = warp;
    int s = start[node], e = start[node + 1];

    float acc[4] = {0, 0, 0, 0};
    uint2 sv = ((const uint2*)(xs + (size_t)node * IN_DIM))[lane];
    bf16x4_add(sv, acc);

    int i = s;
    for (; i + 4 <= e; i += 4) {
        int r0 = srow[i], r1 = srow[i + 1], r2 = srow[i + 2], r3 = srow[i + 3];
        uint2 v0 = ((const uint2*)(xs + (size_t)r0 * IN_DIM))[lane];
        uint2 v1 = ((const uint2*)(xs + (size_t)r1 * IN_DIM))[lane];
        uint2 v2 = ((const uint2*)(xs + (size_t)r2 * IN_DIM))[lane];
        uint2 v3 = ((const uint2*)(xs + (size_t)r3 * IN_DIM))[lane];
        bf16x4_add(v0, acc); bf16x4_add(v1, acc);
        bf16x4_add(v2, acc); bf16x4_add(v3, acc);
    }
    for (; i < e; i++) {
        int r = srow[i];
        uint2 v = ((const uint2*)(xs + (size_t)r * IN_DIM))[lane];
        bf16x4_add(v, acc);
    }

    float dc = dinv[node];
    float4 o;
    o.x = acc[0] * dc; o.y = acc[1] * dc; o.z = acc[2] * dc; o.w = acc[3] * dc;
    ((float4*)(out + (size_t)node * IN_DIM))[lane] = o;
}

// ---------------- fused layer-2 aggregation + global mean pool ----------------
// For each node of graph g: v = relu(dinv*agg + bias); pool[g] += v / cnt(g).
// grid (N_GRAPHS, POOL_CH), 8 warps/block; warp processes whole nodes; block
// reduces pooled partials in smem; one atomicAdd per dim per block.
__device__ __forceinline__ void bf16x8_add(uint4 v, float* a) {
    float2 f0 = __bfloat1622float2(*(__nv_bfloat162*)&v.x);
    float2 f1 = __bfloat1622float2(*(__nv_bfloat162*)&v.y);
    float2 f2 = __bfloat1622float2(*(__nv_bfloat162*)&v.z);
    float2 f3 = __bfloat1622float2(*(__nv_bfloat162*)&v.w);
    a[0] += f0.x; a[1] += f0.y; a[2] += f1.x; a[3] += f1.y;
    a[4] += f2.x; a[5] += f2.y; a[6] += f3.x; a[7] += f3.y;
}

__device__ __forceinline__ int lower_bound_i(const int* a, int n, int v) {
    int lo = 0, hi = n;
    while (lo < hi) {
        int mid = (lo + hi) >> 1;
        if (a[mid] < v) lo = mid + 1; else hi = mid;
    }
    return lo;
}

__global__ __launch_bounds__(256)
void aggpool2_kernel(const __nv_bfloat16* __restrict__ hs, const int* __restrict__ srow,
                     const int* __restrict__ start, const float* __restrict__ dinv,
                     const float* __restrict__ bias, const int* __restrict__ batch,
                     float* __restrict__ out)
{
    int g  = blockIdx.x;
    int ch = blockIdx.y;
    int w    = threadIdx.x >> 5;
    int lane = threadIdx.x & 31;

    __shared__ int slo, shi;
    __shared__ float red[8 * 256];
    if (threadIdx.x == 0) slo = lower_bound_i(batch, N_NODES, g);
    if (threadIdx.x == 1) shi = lower_bound_i(batch, N_NODES, g + 1);
    __syncthreads();
    int lo = slo, hi = shi;
    int cnt = hi - lo;

    float pool[8] = {0, 0, 0, 0, 0, 0, 0, 0};
    if (cnt > 0) {
        float4 b_lo = ((const float4*)bias)[lane * 2];
        float4 b_hi = ((const float4*)bias)[lane * 2 + 1];
        for (int node = lo + ch * 8 + w; node < hi; node += POOL_CH * 8) {
            int s = start[node], e = start[node + 1];
            float acc[8] = {0, 0, 0, 0, 0, 0, 0, 0};
            uint4 sv = ((const uint4*)(hs + (size_t)node * D))[lane];
            bf16x8_add(sv, acc);
            int i = s;
            for (; i + 4 <= e; i += 4) {
                int r0 = srow[i], r1 = srow[i + 1], r2 = srow[i + 2], r3 = srow[i + 3];
                uint4 v0 = ((const uint4*)(hs + (size_t)r0 * D))[lane];
                uint4 v1 = ((const uint4*)(hs + (size_t)r1 * D))[lane];
                uint4 v2 = ((const uint4*)(hs + (size_t)r2 * D))[lane];
                uint4 v3 = ((const uint4*)(hs + (size_t)r3 * D))[lane];
                bf16x8_add(v0, acc); bf16x8_add(v1, acc);
                bf16x8_add(v2, acc); bf16x8_add(v3, acc);
            }
            for (; i < e; i++) {
                int r = srow[i];
                uint4 v = ((const uint4*)(hs + (size_t)r * D))[lane];
                bf16x8_add(v, acc);
            }
            float dc = dinv[node];
            pool[0] += fmaxf(fmaf(acc[0], dc, b_lo.x), 0.f);
            pool[1] += fmaxf(fmaf(acc[1], dc, b_lo.y), 0.f);
            pool[2] += fmaxf(fmaf(acc[2], dc, b_lo.z), 0.f);
            pool[3] += fmaxf(fmaf(acc[3], dc, b_lo.w), 0.f);
            pool[4] += fmaxf(fmaf(acc[4], dc, b_hi.x), 0.f);
            pool[5] += fmaxf(fmaf(acc[5], dc, b_hi.y), 0.f);
            pool[6] += fmaxf(fmaf(acc[6], dc, b_hi.z), 0.f);
            pool[7] += fmaxf(fmaf(acc[7], dc, b_hi.w), 0.f);
        }
        float inv = 1.f / (float)cnt;
        #pragma unroll
        for (int j = 0; j < 8; j++) pool[j] *= inv;
    }

    #pragma unroll
    for (int j = 0; j < 8; j++) red[w * 256 + lane * 8 + j] = pool[j];
    __syncthreads();
    int t = threadIdx.x;
    float s = 0.f;
    #pragma unroll
    for (int wj = 0; wj < 8; wj++) s += red[wj * 256 + t];
    atomicAdd(&out[g * D + t], s);
}

// ---------------- tf32 tensor-core GEMM (register-staged double buffer) ----------------
__device__ __forceinline__ unsigned f2tf32(float f) {
    unsigned r;
    asm("cvt.rna.tf32.f32 %0, %1;" : "=r"(r) : "f"(f));
    return r;
}

__device__ __forceinline__ void mma_tf32(float* c, const unsigned* a, const unsigned* b) {
    asm volatile(
        "mma.sync.aligned.m16n8k8.row.col.f32.tf32.tf32.f32 "
        "{%0,%1,%2,%3}, {%4,%5,%6,%7}, {%8,%9}, {%0,%1,%2,%3};"
        : "+f"(c[0]), "+f"(c[1]), "+f"(c[2]), "+f"(c[3])
        : "r"(a[0]), "r"(a[1]), "r"(a[2]), "r"(a[3]), "r"(b[0]), "r"(b[1]));
}

template <int K, bool RELU, bool SCALE, typename OutT>
__global__ __launch_bounds__(256)
void gemm_tc_kernel(const float* __restrict__ A, const float* __restrict__ W,
                    const float* __restrict__ bias, const float* __restrict__ dinv,
                    OutT* __restrict__ out)
{
    constexpr int BM = 128, BN = 128, BK = 32;
    constexpr int APAD = 36, BPAD = 132;
    __shared__ unsigned As[BM][APAD];
    __shared__ unsigned Bs[BK][BPAD];

    const int tid  = threadIdx.x;
    const int wid  = tid >> 5;
    const int lane = tid & 31;
    const int gid  = lane >> 2;
    const int tig  = lane & 3;
    const int wm   = (wid & 3) * 32;
    const int wn   = (wid >> 2) * 64;

    const int m0 = blockIdx.x * BM;
    const int n0 = blockIdx.y * BN;

    const int a_r  = tid >> 3;          // 0..31 (per-it base row)
    const int a_c4 = (tid & 7) * 4;
    const int b_kr = tid >> 5;          // 0..7 (per-it base k-row)
    const int b_c4 = (tid & 31) * 4;

    float c[2][8][4];
    #pragma unroll
    for (int mt = 0; mt < 2; mt++)
        #pragma unroll
        for (int nt = 0; nt < 8; nt++)
            #pragma unroll
            for (int r = 0; r < 4; r++) c[mt][nt][r] = 0.f;

    float4 ra[4], rb[4];

    // prologue: load tile k0 = 0 into registers
    #pragma unroll
    for (int it = 0; it < 4; it++) {
        int r = it * 32 + a_r;
        ra[it] = make_float4(0.f, 0.f, 0.f, 0.f);
        if (m0 + r < N_NODES)
            ra[it] = *(const float4*)(A + (size_t)(m0 + r) * K + a_c4);
        rb[it] = *(const float4*)(W + (size_t)(it * 8 + b_kr) * D + n0 + b_c4);
    }

    for (int k0 = 0; k0 < K; k0 += BK) {
        // store current tile (cvt to tf32)
        #pragma unroll
        for (int it = 0; it < 4; it++) {
            int r = it * 32 + a_r;
            uint4 u;
            u.x = f2tf32(ra[it].x); u.y = f2tf32(ra[it].y);
            u.z = f2tf32(ra[it].z); u.w = f2tf32(ra[it].w);
            *(uint4*)&As[r][a_c4] = u;
            uint4 v;
            v.x = f2tf32(rb[it].x); v.y = f2tf32(rb[it].y);
            v.z = f2tf32(rb[it].z); v.w = f2tf32(rb[it].w);
            *(uint4*)&Bs[it * 8 + b_kr][b_c4] = v;
        }
        __syncthreads();

        // issue next-tile loads early (latency hidden behind mma)
        const bool more = (k0 + BK < K);
        if (more) {
            int kn = k0 + BK;
            #pragma unroll
            for (int it = 0; it < 4; it++) {
                int r = it * 32 + a_r;
                float4 av = make_float4(0.f, 0.f, 0.f, 0.f);
                if (m0 + r < N_NODES)
                    av = *(const float4*)(A + (size_t)(m0 + r) * K + kn + a_c4);
                ra[it] = av;
                rb[it] = *(const float4*)(W + (size_t)(kn + it * 8 + b_kr) * D + n0 + b_c4);
            }
        }

        // compute on the staged tile
        #pragma unroll
        for (int ks = 0; ks < 4; ks++) {
            int kb = ks * 8;
            unsigned a[2][4];
            #pragma unroll
            for (int mt = 0; mt < 2; mt++) {
                int row = wm + mt * 16;
                a[mt][0] = As[row + gid    ][kb + tig];
                a[mt][1] = As[row + gid + 8][kb + tig];
                a[mt][2] = As[row + gid    ][kb + tig + 4];
                a[mt][3] = As[row + gid + 8][kb + tig + 4];
            }
            unsigned b[8][2];
            #pragma unroll
            for (int nt = 0; nt < 8; nt++) {
                int col = wn + nt * 8 + gid;
                b[nt][0] = Bs[kb + tig    ][col];
                b[nt][1] = Bs[kb + tig + 4][col];
            }
            #pragma unroll
            for (int mt = 0; mt < 2; mt++)
                #pragma unroll
                for (int nt = 0; nt < 8; nt++)
                    mma_tf32(c[mt][nt], a[mt], b[nt]);
        }
        __syncthreads();
    }

    // epilogue
    #pragma unroll
    for (int mt = 0; mt < 2; mt++) {
        #pragma unroll
        for (int rh = 0; rh < 2; rh++) {
            int row = m0 + wm + mt * 16 + gid + rh * 8;
            if (row >= N_NODES) continue;
            float sc = SCALE ? dinv[row] : 1.f;
            #pragma unroll
            for (int nt = 0; nt < 8; nt++) {
                int col = n0 + wn + nt * 8 + 2 * tig;
                float v0 = c[mt][nt][rh * 2 + 0] * sc;
                float v1 = c[mt][nt][rh * 2 + 1] * sc;
                if (RELU) {
                    v0 = fmaxf(v0 + bias[col],     0.f);
                    v1 = fmaxf(v1 + bias[col + 1], 0.f);
                }
                if constexpr (sizeof(OutT) == 4) {
                    float2 v; v.x = v0; v.y = v1;
                    *(float2*)((float*)out + (size_t)row * D + col) = v;
                } else {
                    __nv_bfloat162 p = __floats2bfloat162_rn(v0, v1);
                    *(unsigned*)((__nv_bfloat16*)out + (size_t)row * D + col) =
                        *(unsigned*)&p;
                }
            }
        }
    }
}

// ---------------- out zero-init (d_out is poisoned) ----------------
__global__ void zero_out_kernel(float* out) {
    int i = blockIdx.x * blockDim.x + threadIdx.x;
    if (i < N_GRAPHS * D) out[i] = 0.f;
}

// ---------------------------------------------------------------------------
extern "C" void kernel_launch(void* const* d_in, const int* in_sizes, int n_in,
                              void* d_out, int out_size)
{
    const float* x     = (const float*)d_in[0];
    const int*   eidx  = (const int*)  d_in[1];
    const int*   batch = (const int*)  d_in[2];
    const float* W1    = (const float*)d_in[3];
    const float* b1    = (const float*)d_in[4];
    const float* W2    = (const float*)d_in[5];
    const float* b2    = (const float*)d_in[6];
    float* out = (float*)d_out;

    const int* erow = eidx;
    const int* ecol = eidx + N_EDGES;

    int *cnt, *startp, *cursor, *srow, *bsum, *boff;
    float *dinv, *agg128, *h;
    __nv_bfloat16 *hs, *xs;
    cudaGetSymbolAddress((void**)&cnt,    g_cnt);
    cudaGetSymbolAddress((void**)&dinv,   g_dinv);
    cudaGetSymbolAddress((void**)&startp, g_start);
    cudaGetSymbolAddress((void**)&cursor, g_cursor);
    cudaGetSymbolAddress((void**)&srow,   g_srow);
    cudaGetSymbolAddress((void**)&bsum,   g_bsum);
    cudaGetSymbolAddress((void**)&boff,   g_boff);
    cudaGetSymbolAddress((void**)&xs,     g_xs);
    cudaGetSymbolAddress((void**)&agg128, g_agg128);
    cudaGetSymbolAddress((void**)&h,      g_h);
    cudaGetSymbolAddress((void**)&hs,     g_hs);

    // CSR build
    zero_cnt_kernel   <<<(N_NODES + 255) / 256, 256>>>(cnt);
    hist_kernel       <<<(N_EDGES + 255) / 256, 256>>>(ecol, cnt);
    dinv_kernel       <<<(N_NODES + 255) / 256, 256>>>(cnt, dinv);
    partial_sum_kernel<<<SCAN_NB, 256>>>(cnt, bsum);
    scan_bsum_kernel  <<<1, 128>>>(bsum, boff);
    scan_final_kernel <<<SCAN_NB, 256>>>(cnt, boff, startp, cursor);
    place_kernel      <<<(N_EDGES + 255) / 256, 256>>>(erow, ecol, cursor, srow);

    dim3 ggrid((N_NODES + 127) / 128, 2);
    int  agrid = (N_NODES * 32 + 255) / 256;

    // layer 1: xs=bf16(x*dinv) -> aggregate(128, bf16) -> tf32 gemm + bias + relu
    scale_x_kernel<<<(N_NODES * (IN_DIM / 2) + 255) / 256, 256>>>(x, dinv, xs);
    agg1_kernel<<<agrid, 256>>>(xs, srow, startp, dinv, agg128);
    gemm_tc_kernel<IN_DIM, true, false, float><<<ggrid, 256>>>(agg128, W1, b1, dinv, h);

    // layer 2: tf32 gemm * dinv (bf16 out) -> fused aggregate + bias + relu + pool
    gemm_tc_kernel<HID_DIM, false, true, __nv_bfloat16><<<ggrid, 256>>>(h, W2, b2, dinv, hs);
    zero_out_kernel<<<(N_GRAPHS * D + 255) / 256, 256>>>(out);
    aggpool2_kernel<<<dim3(N_GRAPHS, POOL_CH), 256>>>(hs, srow, startp, dinv, b2, batch, out);
}

// round 10
// speedup vs baseline: 3.9016x; 1.0183x over previous
#include <cuda_runtime.h>
#include <cuda_bf16.h>
#include <cstdint>

#define N_NODES  100000
#define N_EDGES  1600000
#define N_GRAPHS 64
#define IN_DIM   128
#define HID_DIM  256
#define OUT_DIM  256
#define D        256
#define SCAN_NB  98          // ceil(N_NODES / 1024)
#define POOL_CH  24          // chunks per graph in fused agg2+pool

// ---------------- scratch (no allocs allowed) ----------------
__device__ int   g_cnt   [N_NODES];
__device__ float g_dinv  [N_NODES];
__device__ int   g_start [N_NODES + 1];
__device__ int   g_cursor[N_NODES];
__device__ int   g_srow  [N_EDGES];
__device__ int   g_bsum  [SCAN_NB];
__device__ int   g_boff  [SCAN_NB];
__device__ __nv_bfloat16 g_xs[(size_t)N_NODES * IN_DIM];   // bf16(x * dinv)
__device__ float g_agg128[(size_t)N_NODES * IN_DIM];       // tf32-rounded
__device__ float g_h     [(size_t)N_NODES * D];            // tf32-rounded
__device__ __nv_bfloat16 g_hs[(size_t)N_NODES * D];
__device__ float g_w1t   [IN_DIM * D];                     // tf32-rounded W1
__device__ float g_w2t   [HID_DIM * D];                    // tf32-rounded W2

__device__ __forceinline__ unsigned f2tf32(float f) {
    unsigned r;
    asm("cvt.rna.tf32.f32 %0, %1;" : "=r"(r) : "f"(f));
    return r;
}

// ---------------- degree / CSR build ----------------
__global__ void zero_cnt_kernel(int* cnt) {
    int i = blockIdx.x * blockDim.x + threadIdx.x;
    if (i < N_NODES) cnt[i] = 0;
}

__global__ void hist_kernel(const int* __restrict__ cols, int* cnt) {
    int e = blockIdx.x * blockDim.x + threadIdx.x;
    if (e < N_EDGES) atomicAdd(&cnt[cols[e]], 1);
}

__global__ void dinv_kernel(const int* __restrict__ cnt, float* __restrict__ dinv) {
    int i = blockIdx.x * blockDim.x + threadIdx.x;
    if (i < N_NODES) dinv[i] = rsqrtf((float)(cnt[i] + 1));   // +1 self loop
}

__global__ __launch_bounds__(256)
void partial_sum_kernel(const int* __restrict__ cnt, int* __restrict__ bsum) {
    __shared__ int sh[256];
    int b = blockIdx.x, t = threadIdx.x;
    int base = b * 1024;
    int s = 0;
    #pragma unroll
    for (int j = 0; j < 4; j++) {
        int i = base + t + j * 256;
        if (i < N_NODES) s += cnt[i];
    }
    sh[t] = s;
    __syncthreads();
    for (int off = 128; off > 0; off >>= 1) {
        if (t < off) sh[t] += sh[t + off];
        __syncthreads();
    }
    if (t == 0) bsum[b] = sh[0];
}

__global__ __launch_bounds__(128)
void scan_bsum_kernel(const int* __restrict__ bsum, int* __restrict__ boff) {
    __shared__ int sh[128];
    int t = threadIdx.x;
    sh[t] = (t < SCAN_NB) ? bsum[t] : 0;
    __syncthreads();
    for (int off = 1; off < 128; off <<= 1) {
        int v = (t >= off) ? sh[t - off] : 0;
        __syncthreads();
        sh[t] += v;
        __syncthreads();
    }
    if (t < SCAN_NB) boff[t] = (t == 0) ? 0 : sh[t - 1];
}

__global__ __launch_bounds__(256)
void scan_final_kernel(const int* __restrict__ cnt, const int* __restrict__ boff,
                       int* __restrict__ start, int* __restrict__ cursor) {
    __shared__ int sh[256];
    int b = blockIdx.x, t = threadIdx.x;
    int base = b * 1024 + t * 4;
    int c[4];
    int s = 0;
    #pragma unroll
    for (int j = 0; j < 4; j++) {
        int i = base + j;
        c[j] = (i < N_NODES) ? cnt[i] : 0;
        s += c[j];
    }
    sh[t] = s;
    __syncthreads();
    for (int off = 1; off < 256; off <<= 1) {
        int v = (t >= off) ? sh[t - off] : 0;
        __syncthreads();
        sh[t] += v;
        __syncthreads();
    }
    int pre = boff[b] + ((t == 0) ? 0 : sh[t - 1]);
    #pragma unroll
    for (int j = 0; j < 4; j++) {
        int i = base + j;
        if (i < N_NODES) { start[i] = pre; cursor[i] = pre; }
        pre += c[j];
    }
    if (b == 0 && t == 0) start[N_NODES] = N_EDGES;
}

__global__ void place_kernel(const int* __restrict__ rows, const int* __restrict__ cols,
                             int* cursor, int* __restrict__ srow)
{
    int e = blockIdx.x * blockDim.x + threadIdx.x;
    if (e >= N_EDGES) return;
    int c = cols[e];
    int p = atomicAdd(&cursor[c], 1);
    srow[p] = rows[e];
}

// ---------------- W pre-round to tf32 ----------------
__global__ void round_w_kernel(const float* __restrict__ W, float* __restrict__ Wt, int n) {
    int i = blockIdx.x * blockDim.x + threadIdx.x;
    if (i < n) Wt[i] = __uint_as_float(f2tf32(W[i]));
}

// ---------------- xs = bf16(x * dinv[node]) ----------------
__global__ __launch_bounds__(256)
void scale_x_kernel(const float* __restrict__ x, const float* __restrict__ dinv,
                    __nv_bfloat16* __restrict__ xs)
{
    int idx = blockIdx.x * blockDim.x + threadIdx.x;
    if (idx >= N_NODES * (IN_DIM / 2)) return;
    int node = idx >> 6;
    float dc = dinv[node];
    float2 v = ((const float2*)x)[idx];
    __nv_bfloat162 p = __floats2bfloat162_rn(v.x * dc, v.y * dc);
    ((__nv_bfloat162*)xs)[idx] = p;
}

// ---------------- layer-1 aggregation (bf16 gather, fp32 acc, tf32-rounded out) ----------------
__device__ __forceinline__ void bf16x4_add(uint2 v, float* a) {
    float2 f0 = __bfloat1622float2(*(__nv_bfloat162*)&v.x);
    float2 f1 = __bfloat1622float2(*(__nv_bfloat162*)&v.y);
    a[0] += f0.x; a[1] += f0.y; a[2] += f1.x; a[3] += f1.y;
}

__global__ __launch_bounds__(256)
void agg1_kernel(const __nv_bfloat16* __restrict__ xs, const int* __restrict__ srow,
                 const int* __restrict__ start, const float* __restrict__ dinv,
                 float* __restrict__ out)
{
    int warp = (blockIdx.x * blockDim.x + threadIdx.x) >> 5;
    int lane = threadIdx.x & 31;
    if (warp >= N_NODES) return;
    int node = warp;
    int s = start[node], e = start[node + 1];

    float acc[4] = {0, 0, 0, 0};
    uint2 sv = ((const uint2*)(xs + (size_t)node * IN_DIM))[lane];
    bf16x4_add(sv, acc);

    int i = s;
    for (; i + 4 <= e; i += 4) {
        int r0 = srow[i], r1 = srow[i + 1], r2 = srow[i + 2], r3 = srow[i + 3];
        uint2 v0 = ((const uint2*)(xs + (size_t)r0 * IN_DIM))[lane];
        uint2 v1 = ((const uint2*)(xs + (size_t)r1 * IN_DIM))[lane];
        uint2 v2 = ((const uint2*)(xs + (size_t)r2 * IN_DIM))[lane];
        uint2 v3 = ((const uint2*)(xs + (size_t)r3 * IN_DIM))[lane];
        bf16x4_add(v0, acc); bf16x4_add(v1, acc);
        bf16x4_add(v2, acc); bf16x4_add(v3, acc);
    }
    for (; i < e; i++) {
        int r = srow[i];
        uint2 v = ((const uint2*)(xs + (size_t)r * IN_DIM))[lane];
        bf16x4_add(v, acc);
    }

    float dc = dinv[node];
    float4 o;
    o.x = __uint_as_float(f2tf32(acc[0] * dc));
    o.y = __uint_as_float(f2tf32(acc[1] * dc));
    o.z = __uint_as_float(f2tf32(acc[2] * dc));
    o.w = __uint_as_float(f2tf32(acc[3] * dc));
    ((float4*)(out + (size_t)node * IN_DIM))[lane] = o;
}

// ---------------- fused layer-2 aggregation + global mean pool ----------------
__device__ __forceinline__ void bf16x8_add(uint4 v, float* a) {
    float2 f0 = __bfloat1622float2(*(__nv_bfloat162*)&v.x);
    float2 f1 = __bfloat1622float2(*(__nv_bfloat162*)&v.y);
    float2 f2 = __bfloat1622float2(*(__nv_bfloat162*)&v.z);
    float2 f3 = __bfloat1622float2(*(__nv_bfloat162*)&v.w);
    a[0] += f0.x; a[1] += f0.y; a[2] += f1.x; a[3] += f1.y;
    a[4] += f2.x; a[5] += f2.y; a[6] += f3.x; a[7] += f3.y;
}

__device__ __forceinline__ int lower_bound_i(const int* a, int n, int v) {
    int lo = 0, hi = n;
    while (lo < hi) {
        int mid = (lo + hi) >> 1;
        if (a[mid] < v) lo = mid + 1; else hi = mid;
    }
    return lo;
}

__global__ __launch_bounds__(256)
void aggpool2_kernel(const __nv_bfloat16* __restrict__ hs, const int* __restrict__ srow,
                     const int* __restrict__ start, const float* __restrict__ dinv,
                     const float* __restrict__ bias, const int* __restrict__ batch,
                     float* __restrict__ out)
{
    int g  = blockIdx.x;
    int ch = blockIdx.y;
    int w    = threadIdx.x >> 5;
    int lane = threadIdx.x & 31;

    __shared__ int slo, shi;
    __shared__ float red[8 * 256];
    if (threadIdx.x == 0) slo = lower_bound_i(batch, N_NODES, g);
    if (threadIdx.x == 1) shi = lower_bound_i(batch, N_NODES, g + 1);
    __syncthreads();
    int lo = slo, hi = shi;
    int cnt = hi - lo;

    float pool[8] = {0, 0, 0, 0, 0, 0, 0, 0};
    if (cnt > 0) {
        float4 b_lo = ((const float4*)bias)[lane * 2];
        float4 b_hi = ((const float4*)bias)[lane * 2 + 1];
        for (int node = lo + ch * 8 + w; node < hi; node += POOL_CH * 8) {
            int s = start[node], e = start[node + 1];
            float acc[8] = {0, 0, 0, 0, 0, 0, 0, 0};
            uint4 sv = ((const uint4*)(hs + (size_t)node * D))[lane];
            bf16x8_add(sv, acc);
            int i = s;
            for (; i + 4 <= e; i += 4) {
                int r0 = srow[i], r1 = srow[i + 1], r2 = srow[i + 2], r3 = srow[i + 3];
                uint4 v0 = ((const uint4*)(hs + (size_t)r0 * D))[lane];
                uint4 v1 = ((const uint4*)(hs + (size_t)r1 * D))[lane];
                uint4 v2 = ((const uint4*)(hs + (size_t)r2 * D))[lane];
                uint4 v3 = ((const uint4*)(hs + (size_t)r3 * D))[lane];
                bf16x8_add(v0, acc); bf16x8_add(v1, acc);
                bf16x8_add(v2, acc); bf16x8_add(v3, acc);
            }
            for (; i < e; i++) {
                int r = srow[i];
                uint4 v = ((const uint4*)(hs + (size_t)r * D))[lane];
                bf16x8_add(v, acc);
            }
            float dc = dinv[node];
            pool[0] += fmaxf(fmaf(acc[0], dc, b_lo.x), 0.f);
            pool[1] += fmaxf(fmaf(acc[1], dc, b_lo.y), 0.f);
            pool[2] += fmaxf(fmaf(acc[2], dc, b_lo.z), 0.f);
            pool[3] += fmaxf(fmaf(acc[3], dc, b_lo.w), 0.f);
            pool[4] += fmaxf(fmaf(acc[4], dc, b_hi.x), 0.f);
            pool[5] += fmaxf(fmaf(acc[5], dc, b_hi.y), 0.f);
            pool[6] += fmaxf(fmaf(acc[6], dc, b_hi.z), 0.f);
            pool[7] += fmaxf(fmaf(acc[7], dc, b_hi.w), 0.f);
        }
        float inv = 1.f / (float)cnt;
        #pragma unroll
        for (int j = 0; j < 8; j++) pool[j] *= inv;
    }

    #pragma unroll
    for (int j = 0; j < 8; j++) red[w * 256 + lane * 8 + j] = pool[j];
    __syncthreads();
    int t = threadIdx.x;
    float s = 0.f;
    #pragma unroll
    for (int wj = 0; wj < 8; wj++) s += red[wj * 256 + t];
    atomicAdd(&out[g * D + t], s);
}

// ---------------- tf32 GEMM, cp.async 2-stage pipeline ----------------
// Inputs A and W are ALREADY tf32-rounded floats -> tiles are raw byte copies.
__device__ __forceinline__ void mma_tf32(float* c, const unsigned* a, const unsigned* b) {
    asm volatile(
        "mma.sync.aligned.m16n8k8.row.col.f32.tf32.tf32.f32 "
        "{%0,%1,%2,%3}, {%4,%5,%6,%7}, {%8,%9}, {%0,%1,%2,%3};"
        : "+f"(c[0]), "+f"(c[1]), "+f"(c[2]), "+f"(c[3])
        : "r"(a[0]), "r"(a[1]), "r"(a[2]), "r"(a[3]), "r"(b[0]), "r"(b[1]));
}

__device__ __forceinline__ void cp16(unsigned smem_dst, const void* gsrc, bool valid) {
    int sz = valid ? 16 : 0;
    asm volatile("cp.async.ca.shared.global [%0], [%1], 16, %2;"
                 :: "r"(smem_dst), "l"(gsrc), "r"(sz));
}

#define GEMM_BM 128
#define GEMM_BN 128
#define GEMM_BK 32
#define GEMM_APAD 36
#define GEMM_BPAD 132
#define GEMM_A_WORDS (GEMM_BM * GEMM_APAD)       // 4608
#define GEMM_B_WORDS (GEMM_BK * GEMM_BPAD)       // 4224
#define GEMM_SMEM_BYTES ((2 * GEMM_A_WORDS + 2 * GEMM_B_WORDS) * 4)  // 70656

template <int K, bool RELU, bool SCALE, typename OutT>
__global__ __launch_bounds__(256)
void gemm_tc_kernel(const float* __restrict__ A, const float* __restrict__ W,
                    const float* __restrict__ bias, const float* __restrict__ dinv,
                    OutT* __restrict__ out)
{
    extern __shared__ unsigned smem[];
    unsigned* As = smem;                          // [2][BM][APAD]
    unsigned* Bs = smem + 2 * GEMM_A_WORDS;       // [2][BK][BPAD]

    const int tid  = threadIdx.x;
    const int wid  = tid >> 5;
    const int lane = tid & 31;
    const int gid  = lane >> 2;
    const int tig  = lane & 3;
    const int wm   = (wid & 3) * 32;
    const int wn   = (wid >> 2) * 64;

    const int m0 = blockIdx.x * GEMM_BM;
    const int n0 = blockIdx.y * GEMM_BN;

    const int a_r  = tid >> 3;          // 0..31 per-it row base
    const int a_c4 = (tid & 7) * 4;     // word offset in A row
    const int b_kr = tid >> 5;          // 0..7 per-it k-row base
    const int b_c4 = (tid & 31) * 4;

    unsigned sbase = (unsigned)__cvta_generic_to_shared(smem);
    unsigned aBase = sbase;
    unsigned bBase = sbase + 2 * GEMM_A_WORDS * 4;

    // stage loader: copies tile k0 into stage s
    auto load_stage = [&](int s, int k0) {
        #pragma unroll
        for (int it = 0; it < 4; it++) {
            int r = it * 32 + a_r;
            bool valid = (m0 + r < N_NODES);
            unsigned dst = aBase + (unsigned)((s * GEMM_A_WORDS + r * GEMM_APAD + a_c4) * 4);
            cp16(dst, A + (size_t)(m0 + r) * K + k0 + a_c4, valid);
            int kr = it * 8 + b_kr;
            unsigned dstB = bBase + (unsigned)((s * GEMM_B_WORDS + kr * GEMM_BPAD + b_c4) * 4);
            cp16(dstB, W + (size_t)(k0 + kr) * D + n0 + b_c4, true);
        }
        asm volatile("cp.async.commit_group;");
    };

    float c[2][8][4];
    #pragma unroll
    for (int mt = 0; mt < 2; mt++)
        #pragma unroll
        for (int nt = 0; nt < 8; nt++)
            #pragma unroll
            for (int r = 0; r < 4; r++) c[mt][nt][r] = 0.f;

    load_stage(0, 0);

    int cur = 0;
    for (int k0 = 0; k0 < K; k0 += GEMM_BK) {
        asm volatile("cp.async.wait_group 0;");
        __syncthreads();

        if (k0 + GEMM_BK < K)
            load_stage(cur ^ 1, k0 + GEMM_BK);

        const unsigned* Ac = As + cur * GEMM_A_WORDS;
        const unsigned* Bc = Bs + cur * GEMM_B_WORDS;

        #pragma unroll
        for (int ks = 0; ks < 4; ks++) {
            int kb = ks * 8;
            unsigned a[2][4];
            #pragma unroll
            for (int mt = 0; mt < 2; mt++) {
                int row = wm + mt * 16;
                a[mt][0] = Ac[(row + gid    ) * GEMM_APAD + kb + tig];
                a[mt][1] = Ac[(row + gid + 8) * GEMM_APAD + kb + tig];
                a[mt][2] = Ac[(row + gid    ) * GEMM_APAD + kb + tig + 4];
                a[mt][3] = Ac[(row + gid + 8) * GEMM_APAD + kb + tig + 4];
            }
            unsigned b[8][2];
            #pragma unroll
            for (int nt = 0; nt < 8; nt++) {
                int col = wn + nt * 8 + gid;
                b[nt][0] = Bc[(kb + tig    ) * GEMM_BPAD + col];
                b[nt][1] = Bc[(kb + tig + 4) * GEMM_BPAD + col];
            }
            #pragma unroll
            for (int mt = 0; mt < 2; mt++)
                #pragma unroll
                for (int nt = 0; nt < 8; nt++)
                    mma_tf32(c[mt][nt], a[mt], b[nt]);
        }
        __syncthreads();
        cur ^= 1;
    }

    // epilogue
    #pragma unroll
    for (int mt = 0; mt < 2; mt++) {
        #pragma unroll
        for (int rh = 0; rh < 2; rh++) {
            int row = m0 + wm + mt * 16 + gid + rh * 8;
            if (row >= N_NODES) continue;
            float sc = SCALE ? dinv[row] : 1.f;
            #pragma unroll
            for (int nt = 0; nt < 8; nt++) {
                int col = n0 + wn + nt * 8 + 2 * tig;
                float v0 = c[mt][nt][rh * 2 + 0] * sc;
                float v1 = c[mt][nt][rh * 2 + 1] * sc;
                if (RELU) {
                    v0 = fmaxf(v0 + bias[col],     0.f);
                    v1 = fmaxf(v1 + bias[col + 1], 0.f);
                }
                if constexpr (sizeof(OutT) == 4) {
                    // h feeds gemm2: round to tf32 now (idempotent with mma-load cvt)
                    float2 v;
                    v.x = __uint_as_float(f2tf32(v0));
                    v.y = __uint_as_float(f2tf32(v1));
                    *(float2*)((float*)out + (size_t)row * D + col) = v;
                } else {
                    __nv_bfloat162 p = __floats2bfloat162_rn(v0, v1);
                    *(unsigned*)((__nv_bfloat16*)out + (size_t)row * D + col) =
                        *(unsigned*)&p;
                }
            }
        }
    }
}

// ---------------- out zero-init (d_out is poisoned) ----------------
__global__ void zero_out_kernel(float* out) {
    int i = blockIdx.x * blockDim.x + threadIdx.x;
    if (i < N_GRAPHS * D) out[i] = 0.f;
}

// ---------------------------------------------------------------------------
extern "C" void kernel_launch(void* const* d_in, const int* in_sizes, int n_in,
                              void* d_out, int out_size)
{
    const float* x     = (const float*)d_in[0];
    const int*   eidx  = (const int*)  d_in[1];
    const int*   batch = (const int*)  d_in[2];
    const float* W1    = (const float*)d_in[3];
    const float* b1    = (const float*)d_in[4];
    const float* W2    = (const float*)d_in[5];
    const float* b2    = (const float*)d_in[6];
    float* out = (float*)d_out;

    const int* erow = eidx;
    const int* ecol = eidx + N_EDGES;

    int *cnt, *startp, *cursor, *srow, *bsum, *boff;
    float *dinv, *agg128, *h, *w1t, *w2t;
    __nv_bfloat16 *hs, *xs;
    cudaGetSymbolAddress((void**)&cnt,    g_cnt);
    cudaGetSymbolAddress((void**)&dinv,   g_dinv);
    cudaGetSymbolAddress((void**)&startp, g_start);
    cudaGetSymbolAddress((void**)&cursor, g_cursor);
    cudaGetSymbolAddress((void**)&srow,   g_srow);
    cudaGetSymbolAddress((void**)&bsum,   g_bsum);
    cudaGetSymbolAddress((void**)&boff,   g_boff);
    cudaGetSymbolAddress((void**)&xs,     g_xs);
    cudaGetSymbolAddress((void**)&agg128, g_agg128);
    cudaGetSymbolAddress((void**)&h,      g_h);
    cudaGetSymbolAddress((void**)&hs,     g_hs);
    cudaGetSymbolAddress((void**)&w1t,    g_w1t);
    cudaGetSymbolAddress((void**)&w2t,    g_w2t);

    static bool attr_done = false;
    if (!attr_done) {
        cudaFuncSetAttribute(gemm_tc_kernel<IN_DIM, true, false, float>,
                             cudaFuncAttributeMaxDynamicSharedMemorySize, GEMM_SMEM_BYTES);
        cudaFuncSetAttribute(gemm_tc_kernel<HID_DIM, false, true, __nv_bfloat16>,
                             cudaFuncAttributeMaxDynamicSharedMemorySize, GEMM_SMEM_BYTES);
        attr_done = true;
    }

    // CSR build
    zero_cnt_kernel   <<<(N_NODES + 255) / 256, 256>>>(cnt);
    hist_kernel       <<<(N_EDGES + 255) / 256, 256>>>(ecol, cnt);
    dinv_kernel       <<<(N_NODES + 255) / 256, 256>>>(cnt, dinv);
    partial_sum_kernel<<<SCAN_NB, 256>>>(cnt, bsum);
    scan_bsum_kernel  <<<1, 128>>>(bsum, boff);
    scan_final_kernel <<<SCAN_NB, 256>>>(cnt, boff, startp, cursor);
    place_kernel      <<<(N_EDGES + 255) / 256, 256>>>(erow, ecol, cursor, srow);

    // W pre-round (tiny)
    round_w_kernel<<<(IN_DIM * D + 255) / 256, 256>>>(W1, w1t, IN_DIM * D);
    round_w_kernel<<<(HID_DIM * D + 255) / 256, 256>>>(W2, w2t, HID_DIM * D);

    dim3 ggrid((N_NODES + 127) / 128, 2);
    int  agrid = (N_NODES * 32 + 255) / 256;

    // layer 1: xs=bf16(x*dinv) -> aggregate(128) -> tf32 gemm + bias + relu
    scale_x_kernel<<<(N_NODES * (IN_DIM / 2) + 255) / 256, 256>>>(x, dinv, xs);
    agg1_kernel<<<agrid, 256>>>(xs, srow, startp, dinv, agg128);
    gemm_tc_kernel<IN_DIM, true, false, float>
        <<<ggrid, 256, GEMM_SMEM_BYTES>>>(agg128, w1t, b1, dinv, h);

    // layer 2: tf32 gemm * dinv (bf16 out) -> fused aggregate + bias + relu + pool
    gemm_tc_kernel<HID_DIM, false, true, __nv_bfloat16>
        <<<ggrid, 256, GEMM_SMEM_BYTES>>>(h, w2t, b2, dinv, hs);
    zero_out_kernel<<<(N_GRAPHS * D + 255) / 256, 256>>>(out);
    aggpool2_kernel<<<dim3(N_GRAPHS, POOL_CH), 256>>>(hs, srow, startp, dinv, b2, batch, out);
}

// round 12
// speedup vs baseline: 4.1115x; 1.0538x over previous
#include <cuda_runtime.h>
#include <cuda_bf16.h>
#include <cstdint>

#define N_NODES  100000
#define N_EDGES  1600000
#define N_GRAPHS 64
#define IN_DIM   128
#define HID_DIM  256
#define OUT_DIM  256
#define D        256
#define SCAN_NB  98
#define POOL_CH  24
#define CHUNK0   25600                       // stream-0 node chunk (200 gemm blocks)
#define CHUNK1   (N_NODES - CHUNK0)          // 74400

// ---------------- scratch (no allocs allowed) ----------------
__device__ int   g_cnt   [N_NODES];
__device__ float g_dinv  [N_NODES];
__device__ int   g_start [N_NODES + 1];
__device__ int   g_cursor[N_NODES];
__device__ int   g_srow  [N_EDGES];
__device__ int   g_bsum  [SCAN_NB];
__device__ int   g_boff  [SCAN_NB];
__device__ __nv_bfloat16 g_xs[(size_t)N_NODES * IN_DIM];
__device__ float g_agg128[(size_t)N_NODES * IN_DIM];       // tf32-rounded
__device__ float g_h     [(size_t)N_NODES * D];            // tf32-rounded
__device__ __nv_bfloat16 g_hs[(size_t)N_NODES * D];
__device__ float g_w1t   [IN_DIM * D];                     // tf32-rounded W1
__device__ float g_w2t   [HID_DIM * D];                    // tf32-rounded W2

__device__ __forceinline__ unsigned f2tf32(float f) {
    unsigned r;
    asm("cvt.rna.tf32.f32 %0, %1;" : "=r"(r) : "f"(f));
    return r;
}

// ---------------- stream/event plumbing (created at static init, outside checkpoints) ----
static cudaStream_t g_s1 = 0;
static cudaEvent_t  g_evRoot = 0, g_evDinv = 0, g_evPre = 0, g_evPlace = 0, g_evJoin = 0;
static bool g_ok = false;

namespace {
struct SInit {
    SInit() {
        bool ok = (cudaStreamCreateWithFlags(&g_s1, cudaStreamNonBlocking) == cudaSuccess);
        ok = ok && (cudaEventCreateWithFlags(&g_evRoot,  cudaEventDisableTiming) == cudaSuccess);
        ok = ok && (cudaEventCreateWithFlags(&g_evDinv,  cudaEventDisableTiming) == cudaSuccess);
        ok = ok && (cudaEventCreateWithFlags(&g_evPre,   cudaEventDisableTiming) == cudaSuccess);
        ok = ok && (cudaEventCreateWithFlags(&g_evPlace, cudaEventDisableTiming) == cudaSuccess);
        ok = ok && (cudaEventCreateWithFlags(&g_evJoin,  cudaEventDisableTiming) == cudaSuccess);
        g_ok = ok;
    }
};
static SInit s_init;
}

// ---------------- degree / CSR build ----------------
__global__ void zero_cnt_kernel(int* cnt) {
    int i = blockIdx.x * blockDim.x + threadIdx.x;
    if (i < N_NODES) cnt[i] = 0;
}

__global__ void hist_kernel(const int* __restrict__ cols, int* cnt) {
    int e = blockIdx.x * blockDim.x + threadIdx.x;
    if (e < N_EDGES) atomicAdd(&cnt[cols[e]], 1);
}

__global__ void dinv_kernel(const int* __restrict__ cnt, float* __restrict__ dinv) {
    int i = blockIdx.x * blockDim.x + threadIdx.x;
    if (i < N_NODES) dinv[i] = rsqrtf((float)(cnt[i] + 1));
}

__global__ __launch_bounds__(256)
void partial_sum_kernel(const int* __restrict__ cnt, int* __restrict__ bsum) {
    __shared__ int sh[256];
    int b = blockIdx.x, t = threadIdx.x;
    int base = b * 1024;
    int s = 0;
    #pragma unroll
    for (int j = 0; j < 4; j++) {
        int i = base + t + j * 256;
        if (i < N_NODES) s += cnt[i];
    }
    sh[t] = s;
    __syncthreads();
    for (int off = 128; off > 0; off >>= 1) {
        if (t < off) sh[t] += sh[t + off];
        __syncthreads();
    }
    if (t == 0) bsum[b] = sh[0];
}

__global__ __launch_bounds__(128)
void scan_bsum_kernel(const int* __restrict__ bsum, int* __restrict__ boff) {
    __shared__ int sh[128];
    int t = threadIdx.x;
    sh[t] = (t < SCAN_NB) ? bsum[t] : 0;
    __syncthreads();
    for (int off = 1; off < 128; off <<= 1) {
        int v = (t >= off) ? sh[t - off] : 0;
        __syncthreads();
        sh[t] += v;
        __syncthreads();
    }
    if (t < SCAN_NB) boff[t] = (t == 0) ? 0 : sh[t - 1];
}

__global__ __launch_bounds__(256)
void scan_final_kernel(const int* __restrict__ cnt, const int* __restrict__ boff,
                       int* __restrict__ start, int* __restrict__ cursor) {
    __shared__ int sh[256];
    int b = blockIdx.x, t = threadIdx.x;
    int base = b * 1024 + t * 4;
    int c[4];
    int s = 0;
    #pragma unroll
    for (int j = 0; j < 4; j++) {
        int i = base + j;
        c[j] = (i < N_NODES) ? cnt[i] : 0;
        s += c[j];
    }
    sh[t] = s;
    __syncthreads();
    for (int off = 1; off < 256; off <<= 1) {
        int v = (t >= off) ? sh[t - off] : 0;
        __syncthreads();
        sh[t] += v;
        __syncthreads();
    }
    int pre = boff[b] + ((t == 0) ? 0 : sh[t - 1]);
    #pragma unroll
    for (int j = 0; j < 4; j++) {
        int i = base + j;
        if (i < N_NODES) { start[i] = pre; cursor[i] = pre; }
        pre += c[j];
    }
    if (b == 0 && t == 0) start[N_NODES] = N_EDGES;
}

__global__ void place_kernel(const int* __restrict__ rows, const int* __restrict__ cols,
                             int* cursor, int* __restrict__ srow)
{
    int e = blockIdx.x * blockDim.x + threadIdx.x;
    if (e >= N_EDGES) return;
    int c = cols[e];
    int p = atomicAdd(&cursor[c], 1);
    srow[p] = rows[e];
}

// ---------------- W pre-round to tf32 ----------------
__global__ void round_w_kernel(const float* __restrict__ W, float* __restrict__ Wt, int n) {
    int i = blockIdx.x * blockDim.x + threadIdx.x;
    if (i < n) Wt[i] = __uint_as_float(f2tf32(W[i]));
}

// ---------------- xs = bf16(x * dinv[node]) ----------------
__global__ __launch_bounds__(256)
void scale_x_kernel(const float* __restrict__ x, const float* __restrict__ dinv,
                    __nv_bfloat16* __restrict__ xs)
{
    int idx = blockIdx.x * blockDim.x + threadIdx.x;
    if (idx >= N_NODES * (IN_DIM / 2)) return;
    int node = idx >> 6;
    float dc = dinv[node];
    float2 v = ((const float2*)x)[idx];
    __nv_bfloat162 p = __floats2bfloat162_rn(v.x * dc, v.y * dc);
    ((__nv_bfloat162*)xs)[idx] = p;
}

// ---------------- layer-1 aggregation (chunked) ----------------
__device__ __forceinline__ void bf16x4_add(uint2 v, float* a) {
    float2 f0 = __bfloat1622float2(*(__nv_bfloat162*)&v.x);
    float2 f1 = __bfloat1622float2(*(__nv_bfloat162*)&v.y);
    a[0] += f0.x; a[1] += f0.y; a[2] += f1.x; a[3] += f1.y;
}

__global__ __launch_bounds__(256)
void agg1_kernel(const __nv_bfloat16* __restrict__ xs, const int* __restrict__ srow,
                 const int* __restrict__ start, const float* __restrict__ dinv,
                 float* __restrict__ out, int nbase, int ncount)
{
    int warp = (blockIdx.x * blockDim.x + threadIdx.x) >> 5;
    int lane = threadIdx.x & 31;
    if (warp >= ncount) return;
    int node = nbase + warp;
    int s = start[node], e = start[node + 1];

    float acc[4] = {0, 0, 0, 0};
    uint2 sv = ((const uint2*)(xs + (size_t)node * IN_DIM))[lane];
    bf16x4_add(sv, acc);

    int i = s;
    for (; i + 8 <= e; i += 8) {
        int r0 = srow[i],     r1 = srow[i + 1], r2 = srow[i + 2], r3 = srow[i + 3];
        int r4 = srow[i + 4], r5 = srow[i + 5], r6 = srow[i + 6], r7 = srow[i + 7];
        uint2 v0 = ((const uint2*)(xs + (size_t)r0 * IN_DIM))[lane];
        uint2 v1 = ((const uint2*)(xs + (size_t)r1 * IN_DIM))[lane];
        uint2 v2 = ((const uint2*)(xs + (size_t)r2 * IN_DIM))[lane];
        uint2 v3 = ((const uint2*)(xs + (size_t)r3 * IN_DIM))[lane];
        uint2 v4 = ((const uint2*)(xs + (size_t)r4 * IN_DIM))[lane];
        uint2 v5 = ((const uint2*)(xs + (size_t)r5 * IN_DIM))[lane];
        uint2 v6 = ((const uint2*)(xs + (size_t)r6 * IN_DIM))[lane];
        uint2 v7 = ((const uint2*)(xs + (size_t)r7 * IN_DIM))[lane];
        bf16x4_add(v0, acc); bf16x4_add(v1, acc);
        bf16x4_add(v2, acc); bf16x4_add(v3, acc);
        bf16x4_add(v4, acc); bf16x4_add(v5, acc);
        bf16x4_add(v6, acc); bf16x4_add(v7, acc);
    }
    for (; i + 2 <= e; i += 2) {
        int r0 = srow[i], r1 = srow[i + 1];
        uint2 v0 = ((const uint2*)(xs + (size_t)r0 * IN_DIM))[lane];
        uint2 v1 = ((const uint2*)(xs + (size_t)r1 * IN_DIM))[lane];
        bf16x4_add(v0, acc); bf16x4_add(v1, acc);
    }
    if (i < e) {
        int r = srow[i];
        uint2 v = ((const uint2*)(xs + (size_t)r * IN_DIM))[lane];
        bf16x4_add(v, acc);
    }

    float dc = dinv[node];
    float4 o;
    o.x = __uint_as_float(f2tf32(acc[0] * dc));
    o.y = __uint_as_float(f2tf32(acc[1] * dc));
    o.z = __uint_as_float(f2tf32(acc[2] * dc));
    o.w = __uint_as_float(f2tf32(acc[3] * dc));
    ((float4*)(out + (size_t)node * IN_DIM))[lane] = o;
}

// ---------------- fused layer-2 aggregation + global mean pool ----------------
__device__ __forceinline__ void bf16x8_add(uint4 v, float* a) {
    float2 f0 = __bfloat1622float2(*(__nv_bfloat162*)&v.x);
    float2 f1 = __bfloat1622float2(*(__nv_bfloat162*)&v.y);
    float2 f2 = __bfloat1622float2(*(__nv_bfloat162*)&v.z);
    float2 f3 = __bfloat1622float2(*(__nv_bfloat162*)&v.w);
    a[0] += f0.x; a[1] += f0.y; a[2] += f1.x; a[3] += f1.y;
    a[4] += f2.x; a[5] += f2.y; a[6] += f3.x; a[7] += f3.y;
}

__device__ __forceinline__ int lower_bound_i(const int* a, int n, int v) {
    int lo = 0, hi = n;
    while (lo < hi) {
        int mid = (lo + hi) >> 1;
        if (a[mid] < v) lo = mid + 1; else hi = mid;
    }
    return lo;
}

__global__ __launch_bounds__(256)
void aggpool2_kernel(const __nv_bfloat16* __restrict__ hs, const int* __restrict__ srow,
                     const int* __restrict__ start, const float* __restrict__ dinv,
                     const float* __restrict__ bias, const int* __restrict__ batch,
                     float* __restrict__ out)
{
    int g  = blockIdx.x;
    int ch = blockIdx.y;
    int w    = threadIdx.x >> 5;
    int lane = threadIdx.x & 31;

    __shared__ int slo, shi;
    __shared__ float red[8 * 256];
    if (threadIdx.x == 0) slo = lower_bound_i(batch, N_NODES, g);
    if (threadIdx.x == 1) shi = lower_bound_i(batch, N_NODES, g + 1);
    __syncthreads();
    int lo = slo, hi = shi;
    int cnt = hi - lo;

    float pool[8] = {0, 0, 0, 0, 0, 0, 0, 0};
    if (cnt > 0) {
        float4 b_lo = ((const float4*)bias)[lane * 2];
        float4 b_hi = ((const float4*)bias)[lane * 2 + 1];
        for (int node = lo + ch * 8 + w; node < hi; node += POOL_CH * 8) {
            int s = start[node], e = start[node + 1];
            float acc[8] = {0, 0, 0, 0, 0, 0, 0, 0};
            uint4 sv = ((const uint4*)(hs + (size_t)node * D))[lane];
            bf16x8_add(sv, acc);
            int i = s;
            for (; i + 8 <= e; i += 8) {
                int r0 = srow[i],     r1 = srow[i + 1], r2 = srow[i + 2], r3 = srow[i + 3];
                int r4 = srow[i + 4], r5 = srow[i + 5], r6 = srow[i + 6], r7 = srow[i + 7];
                uint4 v0 = ((const uint4*)(hs + (size_t)r0 * D))[lane];
                uint4 v1 = ((const uint4*)(hs + (size_t)r1 * D))[lane];
                uint4 v2 = ((const uint4*)(hs + (size_t)r2 * D))[lane];
                uint4 v3 = ((const uint4*)(hs + (size_t)r3 * D))[lane];
                uint4 v4 = ((const uint4*)(hs + (size_t)r4 * D))[lane];
                uint4 v5 = ((const uint4*)(hs + (size_t)r5 * D))[lane];
                uint4 v6 = ((const uint4*)(hs + (size_t)r6 * D))[lane];
                uint4 v7 = ((const uint4*)(hs + (size_t)r7 * D))[lane];
                bf16x8_add(v0, acc); bf16x8_add(v1, acc);
                bf16x8_add(v2, acc); bf16x8_add(v3, acc);
                bf16x8_add(v4, acc); bf16x8_add(v5, acc);
                bf16x8_add(v6, acc); bf16x8_add(v7, acc);
            }
            for (; i + 2 <= e; i += 2) {
                int r0 = srow[i], r1 = srow[i + 1];
                uint4 v0 = ((const uint4*)(hs + (size_t)r0 * D))[lane];
                uint4 v1 = ((const uint4*)(hs + (size_t)r1 * D))[lane];
                bf16x8_add(v0, acc); bf16x8_add(v1, acc);
            }
            if (i < e) {
                int r = srow[i];
                uint4 v = ((const uint4*)(hs + (size_t)r * D))[lane];
                bf16x8_add(v, acc);
            }
            float dc = dinv[node];
            pool[0] += fmaxf(fmaf(acc[0], dc, b_lo.x), 0.f);
            pool[1] += fmaxf(fmaf(acc[1], dc, b_lo.y), 0.f);
            pool[2] += fmaxf(fmaf(acc[2], dc, b_lo.z), 0.f);
            pool[3] += fmaxf(fmaf(acc[3], dc, b_lo.w), 0.f);
            pool[4] += fmaxf(fmaf(acc[4], dc, b_hi.x), 0.f);
            pool[5] += fmaxf(fmaf(acc[5], dc, b_hi.y), 0.f);
            pool[6] += fmaxf(fmaf(acc[6], dc, b_hi.z), 0.f);
            pool[7] += fmaxf(fmaf(acc[7], dc, b_hi.w), 0.f);
        }
        float inv = 1.f / (float)cnt;
        #pragma unroll
        for (int j = 0; j < 8; j++) pool[j] *= inv;
    }

    #pragma unroll
    for (int j = 0; j < 8; j++) red[w * 256 + lane * 8 + j] = pool[j];
    __syncthreads();
    int t = threadIdx.x;
    float s = 0.f;
    #pragma unroll
    for (int wj = 0; wj < 8; wj++) s += red[wj * 256 + t];
    atomicAdd(&out[g * D + t], s);
}

// ---------------- tf32 GEMM, cp.async 2-stage pipeline (chunked by m_base) ----------------
__device__ __forceinline__ void mma_tf32(float* c, const unsigned* a, const unsigned* b) {
    asm volatile(
        "mma.sync.aligned.m16n8k8.row.col.f32.tf32.tf32.f32 "
        "{%0,%1,%2,%3}, {%4,%5,%6,%7}, {%8,%9}, {%0,%1,%2,%3};"
        : "+f"(c[0]), "+f"(c[1]), "+f"(c[2]), "+f"(c[3])
        : "r"(a[0]), "r"(a[1]), "r"(a[2]), "r"(a[3]), "r"(b[0]), "r"(b[1]));
}

__device__ __forceinline__ void cp16(unsigned smem_dst, const void* gsrc, bool valid) {
    int sz = valid ? 16 : 0;
    asm volatile("cp.async.ca.shared.global [%0], [%1], 16, %2;"
                 :: "r"(smem_dst), "l"(gsrc), "r"(sz));
}

#define GEMM_BM 128
#define GEMM_BN 128
#define GEMM_BK 32
#define GEMM_APAD 36
#define GEMM_BPAD 132
#define GEMM_A_WORDS (GEMM_BM * GEMM_APAD)
#define GEMM_B_WORDS (GEMM_BK * GEMM_BPAD)
#define GEMM_SMEM_BYTES ((2 * GEMM_A_WORDS + 2 * GEMM_B_WORDS) * 4)

template <int K, bool RELU, bool SCALE, typename OutT>
__global__ __launch_bounds__(256)
void gemm_tc_kernel(const float* __restrict__ A, const float* __restrict__ W,
                    const float* __restrict__ bias, const float* __restrict__ dinv,
                    OutT* __restrict__ out, int m_base)
{
    extern __shared__ unsigned smem[];
    unsigned* As = smem;
    unsigned* Bs = smem + 2 * GEMM_A_WORDS;

    const int tid  = threadIdx.x;
    const int wid  = tid >> 5;
    const int lane = tid & 31;
    const int gid  = lane >> 2;
    const int tig  = lane & 3;
    const int wm   = (wid & 3) * 32;
    const int wn   = (wid >> 2) * 64;

    const int m0 = m_base + blockIdx.x * GEMM_BM;
    const int n0 = blockIdx.y * GEMM_BN;

    const int a_r  = tid >> 3;
    const int a_c4 = (tid & 7) * 4;
    const int b_kr = tid >> 5;
    const int b_c4 = (tid & 31) * 4;

    unsigned sbase = (unsigned)__cvta_generic_to_shared(smem);
    unsigned aBase = sbase;
    unsigned bBase = sbase + 2 * GEMM_A_WORDS * 4;

    auto load_stage = [&](int s, int k0) {
        #pragma unroll
        for (int it = 0; it < 4; it++) {
            int r = it * 32 + a_r;
            bool valid = (m0 + r < N_NODES);
            unsigned dst = aBase + (unsigned)((s * GEMM_A_WORDS + r * GEMM_APAD + a_c4) * 4);
            cp16(dst, A + (size_t)(m0 + r) * K + k0 + a_c4, valid);
            int kr = it * 8 + b_kr;
            unsigned dstB = bBase + (unsigned)((s * GEMM_B_WORDS + kr * GEMM_BPAD + b_c4) * 4);
            cp16(dstB, W + (size_t)(k0 + kr) * D + n0 + b_c4, true);
        }
        asm volatile("cp.async.commit_group;");
    };

    float c[2][8][4];
    #pragma unroll
    for (int mt = 0; mt < 2; mt++)
        #pragma unroll
        for (int nt = 0; nt < 8; nt++)
            #pragma unroll
            for (int r = 0; r < 4; r++) c[mt][nt][r] = 0.f;

    load_stage(0, 0);

    int cur = 0;
    for (int k0 = 0; k0 < K; k0 += GEMM_BK) {
        asm volatile("cp.async.wait_group 0;");
        __syncthreads();

        if (k0 + GEMM_BK < K)
            load_stage(cur ^ 1, k0 + GEMM_BK);

        const unsigned* Ac = As + cur * GEMM_A_WORDS;
        const unsigned* Bc = Bs + cur * GEMM_B_WORDS;

        #pragma unroll
        for (int ks = 0; ks < 4; ks++) {
            int kb = ks * 8;
            unsigned a[2][4];
            #pragma unroll
            for (int mt = 0; mt < 2; mt++) {
                int row = wm + mt * 16;
                a[mt][0] = Ac[(row + gid    ) * GEMM_APAD + kb + tig];
                a[mt][1] = Ac[(row + gid + 8) * GEMM_APAD + kb + tig];
                a[mt][2] = Ac[(row + gid    ) * GEMM_APAD + kb + tig + 4];
                a[mt][3] = Ac[(row + gid + 8) * GEMM_APAD + kb + tig + 4];
            }
            unsigned b[8][2];
            #pragma unroll
            for (int nt = 0; nt < 8; nt++) {
                int col = wn + nt * 8 + gid;
                b[nt][0] = Bc[(kb + tig    ) * GEMM_BPAD + col];
                b[nt][1] = Bc[(kb + tig + 4) * GEMM_BPAD + col];
            }
            #pragma unroll
            for (int mt = 0; mt < 2; mt++)
                #pragma unroll
                for (int nt = 0; nt < 8; nt++)
                    mma_tf32(c[mt][nt], a[mt], b[nt]);
        }
        __syncthreads();
        cur ^= 1;
    }

    #pragma unroll
    for (int mt = 0; mt < 2; mt++) {
        #pragma unroll
        for (int rh = 0; rh < 2; rh++) {
            int row = m0 + wm + mt * 16 + gid + rh * 8;
            if (row >= N_NODES) continue;
            float sc = SCALE ? dinv[row] : 1.f;
            #pragma unroll
            for (int nt = 0; nt < 8; nt++) {
                int col = n0 + wn + nt * 8 + 2 * tig;
                float v0 = c[mt][nt][rh * 2 + 0] * sc;
                float v1 = c[mt][nt][rh * 2 + 1] * sc;
                if (RELU) {
                    v0 = fmaxf(v0 + bias[col],     0.f);
                    v1 = fmaxf(v1 + bias[col + 1], 0.f);
                }
                if constexpr (sizeof(OutT) == 4) {
                    float2 v;
                    v.x = __uint_as_float(f2tf32(v0));
                    v.y = __uint_as_float(f2tf32(v1));
                    *(float2*)((float*)out + (size_t)row * D + col) = v;
                } else {
                    __nv_bfloat162 p = __floats2bfloat162_rn(v0, v1);
                    *(unsigned*)((__nv_bfloat16*)out + (size_t)row * D + col) =
                        *(unsigned*)&p;
                }
            }
        }
    }
}

// ---------------- out zero-init ----------------
__global__ void zero_out_kernel(float* out) {
    int i = blockIdx.x * blockDim.x + threadIdx.x;
    if (i < N_GRAPHS * D) out[i] = 0.f;
}

// ---------------------------------------------------------------------------
extern "C" void kernel_launch(void* const* d_in, const int* in_sizes, int n_in,
                              void* d_out, int out_size)
{
    const float* x     = (const float*)d_in[0];
    const int*   eidx  = (const int*)  d_in[1];
    const int*   batch = (const int*)  d_in[2];
    const float* W1    = (const float*)d_in[3];
    const float* b1    = (const float*)d_in[4];
    const float* W2    = (const float*)d_in[5];
    const float* b2    = (const float*)d_in[6];
    float* out = (float*)d_out;

    const int* erow = eidx;
    const int* ecol = eidx + N_EDGES;

    int *cnt, *startp, *cursor, *srow, *bsum, *boff;
    float *dinv, *agg128, *h, *w1t, *w2t;
    __nv_bfloat16 *hs, *xs;
    cudaGetSymbolAddress((void**)&cnt,    g_cnt);
    cudaGetSymbolAddress((void**)&dinv,   g_dinv);
    cudaGetSymbolAddress((void**)&startp, g_start);
    cudaGetSymbolAddress((void**)&cursor, g_cursor);
    cudaGetSymbolAddress((void**)&srow,   g_srow);
    cudaGetSymbolAddress((void**)&bsum,   g_bsum);
    cudaGetSymbolAddress((void**)&boff,   g_boff);
    cudaGetSymbolAddress((void**)&xs,     g_xs);
    cudaGetSymbolAddress((void**)&agg128, g_agg128);
    cudaGetSymbolAddress((void**)&h,      g_h);
    cudaGetSymbolAddress((void**)&hs,     g_hs);
    cudaGetSymbolAddress((void**)&w1t,    g_w1t);
    cudaGetSymbolAddress((void**)&w2t,    g_w2t);

    static bool attr_done = false;
    if (!attr_done) {
        cudaFuncSetAttribute(gemm_tc_kernel<IN_DIM, true, false, float>,
                             cudaFuncAttributeMaxDynamicSharedMemorySize, GEMM_SMEM_BYTES);
        cudaFuncSetAttribute(gemm_tc_kernel<HID_DIM, false, true, __nv_bfloat16>,
                             cudaFuncAttributeMaxDynamicSharedMemorySize, GEMM_SMEM_BYTES);
        attr_done = true;
    }

    cudaStream_t s1 = g_ok ? g_s1 : (cudaStream_t)0;
    // NOTE: launch order below is a dependency-valid TOTAL order, so the
    // single-stream fallback (g_ok == false) remains correct.

    if (g_ok) { cudaEventRecord(g_evRoot, 0); cudaStreamWaitEvent(s1, g_evRoot, 0); }

    // s1: no-dependency prep (hidden under CSR build)
    round_w_kernel<<<(IN_DIM * D + 255) / 256, 256, 0, s1>>>(W1, w1t, IN_DIM * D);
    round_w_kernel<<<(HID_DIM * D + 255) / 256, 256, 0, s1>>>(W2, w2t, HID_DIM * D);
    zero_out_kernel<<<(N_GRAPHS * D + 255) / 256, 256, 0, s1>>>(out);

    // s0: CSR head
    zero_cnt_kernel   <<<(N_NODES + 255) / 256, 256>>>(cnt);
    hist_kernel       <<<(N_EDGES + 255) / 256, 256>>>(ecol, cnt);
    dinv_kernel       <<<(N_NODES + 255) / 256, 256>>>(cnt, dinv);
    if (g_ok) { cudaEventRecord(g_evDinv, 0); cudaStreamWaitEvent(s1, g_evDinv, 0); }

    // s1: scale_x (needs dinv), overlaps scan/place
    scale_x_kernel<<<(N_NODES * (IN_DIM / 2) + 255) / 256, 256, 0, s1>>>(x, dinv, xs);
    if (g_ok) cudaEventRecord(g_evPre, s1);

    // s0: scan + place
    partial_sum_kernel<<<SCAN_NB, 256>>>(cnt, bsum);
    scan_bsum_kernel  <<<1, 128>>>(bsum, boff);
    scan_final_kernel <<<SCAN_NB, 256>>>(cnt, boff, startp, cursor);
    place_kernel      <<<(N_EDGES + 255) / 256, 256>>>(erow, ecol, cursor, srow);
    if (g_ok) { cudaEventRecord(g_evPlace, 0); cudaStreamWaitEvent(s1, g_evPlace, 0); }
    if (g_ok) cudaStreamWaitEvent(0, g_evPre, 0);

    // chunk 0 (small, stream 0): its gemms overlap chunk-1's aggregation
    agg1_kernel<<<(CHUNK0 * 32) / 256, 256>>>(xs, srow, startp, dinv, agg128, 0, CHUNK0);
    gemm_tc_kernel<IN_DIM, true, false, float>
        <<<dim3(CHUNK0 / 128, 2), 256, GEMM_SMEM_BYTES>>>(agg128, w1t, b1, dinv, h, 0);
    gemm_tc_kernel<HID_DIM, false, true, __nv_bfloat16>
        <<<dim3(CHUNK0 / 128, 2), 256, GEMM_SMEM_BYTES>>>(h, w2t, b2, dinv, hs, 0);

    // chunk 1 (large, stream 1)
    agg1_kernel<<<(CHUNK1 * 32 + 255) / 256, 256, 0, s1>>>(xs, srow, startp, dinv, agg128,
                                                           CHUNK0, CHUNK1);
    gemm_tc_kernel<IN_DIM, true, false, float>
        <<<dim3((CHUNK1 + 127) / 128, 2), 256, GEMM_SMEM_BYTES, s1>>>(agg128, w1t, b1, dinv, h, CHUNK0);
    gemm_tc_kernel<HID_DIM, false, true, __nv_bfloat16>
        <<<dim3((CHUNK1 + 127) / 128, 2), 256, GEMM_SMEM_BYTES, s1>>>(h, w2t, b2, dinv, hs, CHUNK0);
    if (g_ok) { cudaEventRecord(g_evJoin, s1); cudaStreamWaitEvent(0, g_evJoin, 0); }

    // fused aggregate + pool (needs all hs + zeroed out)
    aggpool2_kernel<<<dim3(N_GRAPHS, POOL_CH), 256>>>(hs, srow, startp, dinv, b2, batch, out);
}

// round 13
// speedup vs baseline: 4.7840x; 1.1636x over previous
#include <cuda_runtime.h>
#include <cuda_bf16.h>
#include <cuda_fp16.h>
#include <cstdint>

#define N_NODES  100000
#define N_EDGES  1600000
#define N_GRAPHS 64
#define IN_DIM   128
#define HID_DIM  256
#define OUT_DIM  256
#define D        256
#define SCAN_NB  98
#define POOL_CH  24
#define CHUNK0   25600
#define CHUNK1   (N_NODES - CHUNK0)

// ---------------- scratch (no allocs allowed) ----------------
__device__ int   g_cnt   [N_NODES];
__device__ float g_dinv  [N_NODES];
__device__ int   g_start [N_NODES + 1];
__device__ int   g_cursor[N_NODES];
__device__ int   g_srow  [N_EDGES];
__device__ int   g_bsum  [SCAN_NB];
__device__ int   g_boff  [SCAN_NB];
__device__ __nv_bfloat16 g_xs[(size_t)N_NODES * IN_DIM];
__device__ __half g_aggh [(size_t)N_NODES * IN_DIM];       // fp16 agg1 output
__device__ __half g_hh   [(size_t)N_NODES * D];            // fp16 layer-1 output
__device__ __nv_bfloat16 g_hs[(size_t)N_NODES * D];
__device__ __half g_w1t  [D * IN_DIM];                     // W1^T fp16 [256][128]
__device__ __half g_w2t  [D * HID_DIM];                    // W2^T fp16 [256][256]

// ---------------- stream/event plumbing ----------------
static cudaStream_t g_s1 = 0;
static cudaEvent_t  g_evRoot = 0, g_evDinv = 0, g_evPre = 0, g_evPlace = 0, g_evJoin = 0;
static bool g_ok = false;

namespace {
struct SInit {
    SInit() {
        bool ok = (cudaStreamCreateWithFlags(&g_s1, cudaStreamNonBlocking) == cudaSuccess);
        ok = ok && (cudaEventCreateWithFlags(&g_evRoot,  cudaEventDisableTiming) == cudaSuccess);
        ok = ok && (cudaEventCreateWithFlags(&g_evDinv,  cudaEventDisableTiming) == cudaSuccess);
        ok = ok && (cudaEventCreateWithFlags(&g_evPre,   cudaEventDisableTiming) == cudaSuccess);
        ok = ok && (cudaEventCreateWithFlags(&g_evPlace, cudaEventDisableTiming) == cudaSuccess);
        ok = ok && (cudaEventCreateWithFlags(&g_evJoin,  cudaEventDisableTiming) == cudaSuccess);
        g_ok = ok;
    }
};
static SInit s_init;
}

// ---------------- degree / CSR build ----------------
__global__ void zero_cnt_kernel(int* cnt) {
    int i = blockIdx.x * blockDim.x + threadIdx.x;
    if (i < N_NODES) cnt[i] = 0;
}

__global__ void hist_kernel(const int* __restrict__ cols, int* cnt) {
    int e = blockIdx.x * blockDim.x + threadIdx.x;
    if (e < N_EDGES) atomicAdd(&cnt[cols[e]], 1);
}

__global__ void dinv_kernel(const int* __restrict__ cnt, float* __restrict__ dinv) {
    int i = blockIdx.x * blockDim.x + threadIdx.x;
    if (i < N_NODES) dinv[i] = rsqrtf((float)(cnt[i] + 1));
}

__global__ __launch_bounds__(256)
void partial_sum_kernel(const int* __restrict__ cnt, int* __restrict__ bsum) {
    __shared__ int sh[256];
    int b = blockIdx.x, t = threadIdx.x;
    int base = b * 1024;
    int s = 0;
    #pragma unroll
    for (int j = 0; j < 4; j++) {
        int i = base + t + j * 256;
        if (i < N_NODES) s += cnt[i];
    }
    sh[t] = s;
    __syncthreads();
    for (int off = 128; off > 0; off >>= 1) {
        if (t < off) sh[t] += sh[t + off];
        __syncthreads();
    }
    if (t == 0) bsum[b] = sh[0];
}

__global__ __launch_bounds__(128)
void scan_bsum_kernel(const int* __restrict__ bsum, int* __restrict__ boff) {
    __shared__ int sh[128];
    int t = threadIdx.x;
    sh[t] = (t < SCAN_NB) ? bsum[t] : 0;
    __syncthreads();
    for (int off = 1; off < 128; off <<= 1) {
        int v = (t >= off) ? sh[t - off] : 0;
        __syncthreads();
        sh[t] += v;
        __syncthreads();
    }
    if (t < SCAN_NB) boff[t] = (t == 0) ? 0 : sh[t - 1];
}

__global__ __launch_bounds__(256)
void scan_final_kernel(const int* __restrict__ cnt, const int* __restrict__ boff,
                       int* __restrict__ start, int* __restrict__ cursor) {
    __shared__ int sh[256];
    int b = blockIdx.x, t = threadIdx.x;
    int base = b * 1024 + t * 4;
    int c[4];
    int s = 0;
    #pragma unroll
    for (int j = 0; j < 4; j++) {
        int i = base + j;
        c[j] = (i < N_NODES) ? cnt[i] : 0;
        s += c[j];
    }
    sh[t] = s;
    __syncthreads();
    for (int off = 1; off < 256; off <<= 1) {
        int v = (t >= off) ? sh[t - off] : 0;
        __syncthreads();
        sh[t] += v;
        __syncthreads();
    }
    int pre = boff[b] + ((t == 0) ? 0 : sh[t - 1]);
    #pragma unroll
    for (int j = 0; j < 4; j++) {
        int i = base + j;
        if (i < N_NODES) { start[i] = pre; cursor[i] = pre; }
        pre += c[j];
    }
    if (b == 0 && t == 0) start[N_NODES] = N_EDGES;
}

__global__ void place_kernel(const int* __restrict__ rows, const int* __restrict__ cols,
                             int* cursor, int* __restrict__ srow)
{
    int e = blockIdx.x * blockDim.x + threadIdx.x;
    if (e >= N_EDGES) return;
    int c = cols[e];
    int p = atomicAdd(&cursor[c], 1);
    srow[p] = rows[e];
}

// ---------------- W transpose to fp16: Wt[n][k] = fp16(W[k][n]) ----------------
__global__ void transpose_wh_kernel(const float* __restrict__ W, __half* __restrict__ Wt, int K) {
    __shared__ float t[32][33];
    int k0 = blockIdx.x * 32, n0 = blockIdx.y * 32;
    int tx = threadIdx.x, ty = threadIdx.y;   // 32 x 8
    #pragma unroll
    for (int j = 0; j < 32; j += 8)
        t[ty + j][tx] = W[(size_t)(k0 + ty + j) * D + n0 + tx];
    __syncthreads();
    #pragma unroll
    for (int j = 0; j < 32; j += 8)
        Wt[(size_t)(n0 + ty + j) * K + k0 + tx] = __float2half(t[tx][ty + j]);
}

// ---------------- xs = bf16(x * dinv[node]) ----------------
__global__ __launch_bounds__(256)
void scale_x_kernel(const float* __restrict__ x, const float* __restrict__ dinv,
                    __nv_bfloat16* __restrict__ xs)
{
    int idx = blockIdx.x * blockDim.x + threadIdx.x;
    if (idx >= N_NODES * (IN_DIM / 2)) return;
    int node = idx >> 6;
    float dc = dinv[node];
    float2 v = ((const float2*)x)[idx];
    __nv_bfloat162 p = __floats2bfloat162_rn(v.x * dc, v.y * dc);
    ((__nv_bfloat162*)xs)[idx] = p;
}

// ---------------- layer-1 aggregation -> fp16 output ----------------
__device__ __forceinline__ void bf16x4_add(uint2 v, float* a) {
    float2 f0 = __bfloat1622float2(*(__nv_bfloat162*)&v.x);
    float2 f1 = __bfloat1622float2(*(__nv_bfloat162*)&v.y);
    a[0] += f0.x; a[1] += f0.y; a[2] += f1.x; a[3] += f1.y;
}

__global__ __launch_bounds__(256)
void agg1_kernel(const __nv_bfloat16* __restrict__ xs, const int* __restrict__ srow,
                 const int* __restrict__ start, const float* __restrict__ dinv,
                 __half* __restrict__ out, int nbase, int ncount)
{
    int warp = (blockIdx.x * blockDim.x + threadIdx.x) >> 5;
    int lane = threadIdx.x & 31;
    if (warp >= ncount) return;
    int node = nbase + warp;
    int s = start[node], e = start[node + 1];

    float acc[4] = {0, 0, 0, 0};
    uint2 sv = ((const uint2*)(xs + (size_t)node * IN_DIM))[lane];
    bf16x4_add(sv, acc);

    int i = s;
    for (; i + 8 <= e; i += 8) {
        int r0 = srow[i],     r1 = srow[i + 1], r2 = srow[i + 2], r3 = srow[i + 3];
        int r4 = srow[i + 4], r5 = srow[i + 5], r6 = srow[i + 6], r7 = srow[i + 7];
        uint2 v0 = ((const uint2*)(xs + (size_t)r0 * IN_DIM))[lane];
        uint2 v1 = ((const uint2*)(xs + (size_t)r1 * IN_DIM))[lane];
        uint2 v2 = ((const uint2*)(xs + (size_t)r2 * IN_DIM))[lane];
        uint2 v3 = ((const uint2*)(xs + (size_t)r3 * IN_DIM))[lane];
        uint2 v4 = ((const uint2*)(xs + (size_t)r4 * IN_DIM))[lane];
        uint2 v5 = ((const uint2*)(xs + (size_t)r5 * IN_DIM))[lane];
        uint2 v6 = ((const uint2*)(xs + (size_t)r6 * IN_DIM))[lane];
        uint2 v7 = ((const uint2*)(xs + (size_t)r7 * IN_DIM))[lane];
        bf16x4_add(v0, acc); bf16x4_add(v1, acc);
        bf16x4_add(v2, acc); bf16x4_add(v3, acc);
        bf16x4_add(v4, acc); bf16x4_add(v5, acc);
        bf16x4_add(v6, acc); bf16x4_add(v7, acc);
    }
    for (; i + 2 <= e; i += 2) {
        int r0 = srow[i], r1 = srow[i + 1];
        uint2 v0 = ((const uint2*)(xs + (size_t)r0 * IN_DIM))[lane];
        uint2 v1 = ((const uint2*)(xs + (size_t)r1 * IN_DIM))[lane];
        bf16x4_add(v0, acc); bf16x4_add(v1, acc);
    }
    if (i < e) {
        int r = srow[i];
        uint2 v = ((const uint2*)(xs + (size_t)r * IN_DIM))[lane];
        bf16x4_add(v, acc);
    }

    float dc = dinv[node];
    __half2 p0 = __floats2half2_rn(acc[0] * dc, acc[1] * dc);
    __half2 p1 = __floats2half2_rn(acc[2] * dc, acc[3] * dc);
    uint2 o;
    o.x = *(unsigned*)&p0;
    o.y = *(unsigned*)&p1;
    ((uint2*)(out + (size_t)node * IN_DIM))[lane] = o;
}

// ---------------- fused layer-2 aggregation + global mean pool ----------------
__device__ __forceinline__ void bf16x8_add(uint4 v, float* a) {
    float2 f0 = __bfloat1622float2(*(__nv_bfloat162*)&v.x);
    float2 f1 = __bfloat1622float2(*(__nv_bfloat162*)&v.y);
    float2 f2 = __bfloat1622float2(*(__nv_bfloat162*)&v.z);
    float2 f3 = __bfloat1622float2(*(__nv_bfloat162*)&v.w);
    a[0] += f0.x; a[1] += f0.y; a[2] += f1.x; a[3] += f1.y;
    a[4] += f2.x; a[5] += f2.y; a[6] += f3.x; a[7] += f3.y;
}

__device__ __forceinline__ int lower_bound_i(const int* a, int n, int v) {
    int lo = 0, hi = n;
    while (lo < hi) {
        int mid = (lo + hi) >> 1;
        if (a[mid] < v) lo = mid + 1; else hi = mid;
    }
    return lo;
}

__global__ __launch_bounds__(256)
void aggpool2_kernel(const __nv_bfloat16* __restrict__ hs, const int* __restrict__ srow,
                     const int* __restrict__ start, const float* __restrict__ dinv,
                     const float* __restrict__ bias, const int* __restrict__ batch,
                     float* __restrict__ out)
{
    int g  = blockIdx.x;
    int ch = blockIdx.y;
    int w    = threadIdx.x >> 5;
    int lane = threadIdx.x & 31;

    __shared__ int slo, shi;
    __shared__ float red[8 * 256];
    if (threadIdx.x == 0) slo = lower_bound_i(batch, N_NODES, g);
    if (threadIdx.x == 1) shi = lower_bound_i(batch, N_NODES, g + 1);
    __syncthreads();
    int lo = slo, hi = shi;
    int cnt = hi - lo;

    float pool[8] = {0, 0, 0, 0, 0, 0, 0, 0};
    if (cnt > 0) {
        float4 b_lo = ((const float4*)bias)[lane * 2];
        float4 b_hi = ((const float4*)bias)[lane * 2 + 1];
        for (int node = lo + ch * 8 + w; node < hi; node += POOL_CH * 8) {
            int s = start[node], e = start[node + 1];
            float acc[8] = {0, 0, 0, 0, 0, 0, 0, 0};
            uint4 sv = ((const uint4*)(hs + (size_t)node * D))[lane];
            bf16x8_add(sv, acc);
            int i = s;
            for (; i + 8 <= e; i += 8) {
                int r0 = srow[i],     r1 = srow[i + 1], r2 = srow[i + 2], r3 = srow[i + 3];
                int r4 = srow[i + 4], r5 = srow[i + 5], r6 = srow[i + 6], r7 = srow[i + 7];
                uint4 v0 = ((const uint4*)(hs + (size_t)r0 * D))[lane];
                uint4 v1 = ((const uint4*)(hs + (size_t)r1 * D))[lane];
                uint4 v2 = ((const uint4*)(hs + (size_t)r2 * D))[lane];
                uint4 v3 = ((const uint4*)(hs + (size_t)r3 * D))[lane];
                uint4 v4 = ((const uint4*)(hs + (size_t)r4 * D))[lane];
                uint4 v5 = ((const uint4*)(hs + (size_t)r5 * D))[lane];
                uint4 v6 = ((const uint4*)(hs + (size_t)r6 * D))[lane];
                uint4 v7 = ((const uint4*)(hs + (size_t)r7 * D))[lane];
                bf16x8_add(v0, acc); bf16x8_add(v1, acc);
                bf16x8_add(v2, acc); bf16x8_add(v3, acc);
                bf16x8_add(v4, acc); bf16x8_add(v5, acc);
                bf16x8_add(v6, acc); bf16x8_add(v7, acc);
            }
            for (; i + 2 <= e; i += 2) {
                int r0 = srow[i], r1 = srow[i + 1];
                uint4 v0 = ((const uint4*)(hs + (size_t)r0 * D))[lane];
                uint4 v1 = ((const uint4*)(hs + (size_t)r1 * D))[lane];
                bf16x8_add(v0, acc); bf16x8_add(v1, acc);
            }
            if (i < e) {
                int r = srow[i];
                uint4 v = ((const uint4*)(hs + (size_t)r * D))[lane];
                bf16x8_add(v, acc);
            }
            float dc = dinv[node];
            pool[0] += fmaxf(fmaf(acc[0], dc, b_lo.x), 0.f);
            pool[1] += fmaxf(fmaf(acc[1], dc, b_lo.y), 0.f);
            pool[2] += fmaxf(fmaf(acc[2], dc, b_lo.z), 0.f);
            pool[3] += fmaxf(fmaf(acc[3], dc, b_lo.w), 0.f);
            pool[4] += fmaxf(fmaf(acc[4], dc, b_hi.x), 0.f);
            pool[5] += fmaxf(fmaf(acc[5], dc, b_hi.y), 0.f);
            pool[6] += fmaxf(fmaf(acc[6], dc, b_hi.z), 0.f);
            pool[7] += fmaxf(fmaf(acc[7], dc, b_hi.w), 0.f);
        }
        float inv = 1.f / (float)cnt;
        #pragma unroll
        for (int j = 0; j < 8; j++) pool[j] *= inv;
    }

    #pragma unroll
    for (int j = 0; j < 8; j++) red[w * 256 + lane * 8 + j] = pool[j];
    __syncthreads();
    int t = threadIdx.x;
    float s = 0.f;
    #pragma unroll
    for (int wj = 0; wj < 8; wj++) s += red[wj * 256 + t];
    atomicAdd(&out[g * D + t], s);
}

// ---------------- fp16 GEMM, mma.m16n8k16, cp.async 2-stage ----------------
// out[m][256] = A[m][K](fp16) @ W, where Wt[n][k] = fp16(W[k][n]) (k-contiguous)
__device__ __forceinline__ void mma_f16(float* c, const unsigned* a, const unsigned* b) {
    asm volatile(
        "mma.sync.aligned.m16n8k16.row.col.f32.f16.f16.f32 "
        "{%0,%1,%2,%3}, {%4,%5,%6,%7}, {%8,%9}, {%0,%1,%2,%3};"
        : "+f"(c[0]), "+f"(c[1]), "+f"(c[2]), "+f"(c[3])
        : "r"(a[0]), "r"(a[1]), "r"(a[2]), "r"(a[3]), "r"(b[0]), "r"(b[1]));
}

__device__ __forceinline__ void cp16(unsigned smem_dst, const void* gsrc, bool valid) {
    int sz = valid ? 16 : 0;
    asm volatile("cp.async.ca.shared.global [%0], [%1], 16, %2;"
                 :: "r"(smem_dst), "l"(gsrc), "r"(sz));
}

__device__ __forceinline__ void store_pair(__half* out, size_t idx, float v0, float v1) {
    __half2 p = __floats2half2_rn(v0, v1);
    *(unsigned*)(out + idx) = *(unsigned*)&p;
}
__device__ __forceinline__ void store_pair(__nv_bfloat16* out, size_t idx, float v0, float v1) {
    __nv_bfloat162 p = __floats2bfloat162_rn(v0, v1);
    *(unsigned*)(out + idx) = *(unsigned*)&p;
}

#define GEMM_BM 128
#define GEMM_BN 128
#define GEMM_BK 32
#define GEMM_ROWH 40                               // halves per smem row (32 + 8 pad)
#define GEMM_A_HALFS (GEMM_BM * GEMM_ROWH)         // 5120
#define GEMM_B_HALFS (GEMM_BN * GEMM_ROWH)         // 5120
#define GEMM_SMEM_BYTES ((2 * GEMM_A_HALFS + 2 * GEMM_B_HALFS) * 2)   // 40960

template <int K, bool RELU, bool SCALE, typename OutT>
__global__ __launch_bounds__(256)
void gemm_f16_kernel(const __half* __restrict__ A, const __half* __restrict__ Wt,
                     const float* __restrict__ bias, const float* __restrict__ dinv,
                     OutT* __restrict__ out, int m_base)
{
    extern __shared__ __half smh[];
    const int tid  = threadIdx.x;
    const int wid  = tid >> 5;
    const int lane = tid & 31;
    const int gid  = lane >> 2;
    const int tig  = lane & 3;
    const int wm   = (wid & 3) * 32;
    const int wn   = (wid >> 2) * 64;

    const int m0 = m_base + blockIdx.x * GEMM_BM;
    const int n0 = blockIdx.y * GEMM_BN;

    unsigned sbase = (unsigned)__cvta_generic_to_shared(smh);
    unsigned aBase = sbase;                                    // [2][128][40] halves
    unsigned bBase = sbase + 2 * GEMM_A_HALFS * 2;             // bytes

    const int ld_r   = tid >> 1;          // 0..127
    const int ld_seg = (tid & 1) * 32;    // byte offset within 64B row

    auto load_stage = [&](int s, int k0) {
        // A row: 32 halves = 64B; two cp16 per thread
        bool valid = (m0 + ld_r) < N_NODES;
        const char* asrc = (const char*)(A + (size_t)(m0 + ld_r) * K + k0) + ld_seg;
        unsigned adst = aBase + (unsigned)(s * GEMM_A_HALFS * 2 + ld_r * (GEMM_ROWH * 2) + ld_seg);
        cp16(adst,      asrc,      valid);
        cp16(adst + 16, asrc + 16, valid);
        // B row (n = n0 + ld_r): 32 halves from Wt[n][k0..]
        const char* bsrc = (const char*)(Wt + (size_t)(n0 + ld_r) * K + k0) + ld_seg;
        unsigned bdst = bBase + (unsigned)(s * GEMM_B_HALFS * 2 + ld_r * (GEMM_ROWH * 2) + ld_seg);
        cp16(bdst,      bsrc,      true);
        cp16(bdst + 16, bsrc + 16, true);
        asm volatile("cp.async.commit_group;");
    };

    float c[2][8][4];
    #pragma unroll
    for (int mt = 0; mt < 2; mt++)
        #pragma unroll
        for (int nt = 0; nt < 8; nt++)
            #pragma unroll
            for (int r = 0; r < 4; r++) c[mt][nt][r] = 0.f;

    load_stage(0, 0);

    int cur = 0;
    for (int k0 = 0; k0 < K; k0 += GEMM_BK) {
        asm volatile("cp.async.wait_group 0;");
        __syncthreads();

        if (k0 + GEMM_BK < K)
            load_stage(cur ^ 1, k0 + GEMM_BK);

        const __half* Ah = smh + cur * GEMM_A_HALFS;
        const __half* Bh = smh + 2 * GEMM_A_HALFS + cur * GEMM_B_HALFS;

        #pragma unroll
        for (int ks = 0; ks < 2; ks++) {
            int kk = ks * 16;
            unsigned a[2][4];
            #pragma unroll
            for (int mt = 0; mt < 2; mt++) {
                int row = wm + mt * 16;
                a[mt][0] = *(const unsigned*)&Ah[(row + gid    ) * GEMM_ROWH + kk + 2 * tig];
                a[mt][1] = *(const unsigned*)&Ah[(row + gid + 8) * GEMM_ROWH + kk + 2 * tig];
                a[mt][2] = *(const unsigned*)&Ah[(row + gid    ) * GEMM_ROWH + kk + 2 * tig + 8];
                a[mt][3] = *(const unsigned*)&Ah[(row + gid + 8) * GEMM_ROWH + kk + 2 * tig + 8];
            }
            unsigned b[8][2];
            #pragma unroll
            for (int nt = 0; nt < 8; nt++) {
                int col = wn + nt * 8 + gid;
                b[nt][0] = *(const unsigned*)&Bh[col * GEMM_ROWH + kk + 2 * tig];
                b[nt][1] = *(const unsigned*)&Bh[col * GEMM_ROWH + kk + 2 * tig + 8];
            }
            #pragma unroll
            for (int mt = 0; mt < 2; mt++)
                #pragma unroll
                for (int nt = 0; nt < 8; nt++)
                    mma_f16(c[mt][nt], a[mt], b[nt]);
        }
        __syncthreads();
        cur ^= 1;
    }

    #pragma unroll
    for (int mt = 0; mt < 2; mt++) {
        #pragma unroll
        for (int rh = 0; rh < 2; rh++) {
            int row = m0 + wm + mt * 16 + gid + rh * 8;
            if (row >= N_NODES) continue;
            float sc = SCALE ? dinv[row] : 1.f;
            #pragma unroll
            for (int nt = 0; nt < 8; nt++) {
                int col = n0 + wn + nt * 8 + 2 * tig;
                float v0 = c[mt][nt][rh * 2 + 0] * sc;
                float v1 = c[mt][nt][rh * 2 + 1] * sc;
                if (RELU) {
                    v0 = fmaxf(v0 + bias[col],     0.f);
                    v1 = fmaxf(v1 + bias[col + 1], 0.f);
                }
                store_pair(out, (size_t)row * D + col, v0, v1);
            }
        }
    }
}

// ---------------- out zero-init ----------------
__global__ void zero_out_kernel(float* out) {
    int i = blockIdx.x * blockDim.x + threadIdx.x;
    if (i < N_GRAPHS * D) out[i] = 0.f;
}

// ---------------------------------------------------------------------------
extern "C" void kernel_launch(void* const* d_in, const int* in_sizes, int n_in,
                              void* d_out, int out_size)
{
    const float* x     = (const float*)d_in[0];
    const int*   eidx  = (const int*)  d_in[1];
    const int*   batch = (const int*)  d_in[2];
    const float* W1    = (const float*)d_in[3];
    const float* b1    = (const float*)d_in[4];
    const float* W2    = (const float*)d_in[5];
    const float* b2    = (const float*)d_in[6];
    float* out = (float*)d_out;

    const int* erow = eidx;
    const int* ecol = eidx + N_EDGES;

    int *cnt, *startp, *cursor, *srow, *bsum, *boff;
    float *dinv;
    __half *aggh, *hh, *w1t, *w2t;
    __nv_bfloat16 *hs, *xs;
    cudaGetSymbolAddress((void**)&cnt,    g_cnt);
    cudaGetSymbolAddress((void**)&dinv,   g_dinv);
    cudaGetSymbolAddress((void**)&startp, g_start);
    cudaGetSymbolAddress((void**)&cursor, g_cursor);
    cudaGetSymbolAddress((void**)&srow,   g_srow);
    cudaGetSymbolAddress((void**)&bsum,   g_bsum);
    cudaGetSymbolAddress((void**)&boff,   g_boff);
    cudaGetSymbolAddress((void**)&xs,     g_xs);
    cudaGetSymbolAddress((void**)&aggh,   g_aggh);
    cudaGetSymbolAddress((void**)&hh,     g_hh);
    cudaGetSymbolAddress((void**)&hs,     g_hs);
    cudaGetSymbolAddress((void**)&w1t,    g_w1t);
    cudaGetSymbolAddress((void**)&w2t,    g_w2t);

    static bool attr_done = false;
    if (!attr_done) {
        cudaFuncSetAttribute(gemm_f16_kernel<IN_DIM, true, false, __half>,
                             cudaFuncAttributeMaxDynamicSharedMemorySize, GEMM_SMEM_BYTES);
        cudaFuncSetAttribute(gemm_f16_kernel<HID_DIM, false, true, __nv_bfloat16>,
                             cudaFuncAttributeMaxDynamicSharedMemorySize, GEMM_SMEM_BYTES);
        attr_done = true;
    }

    cudaStream_t s1 = g_ok ? g_s1 : (cudaStream_t)0;
    // Launch order is a dependency-valid TOTAL order -> single-stream fallback correct.

    if (g_ok) { cudaEventRecord(g_evRoot, 0); cudaStreamWaitEvent(s1, g_evRoot, 0); }

    // s1: prep (hidden under CSR build)
    transpose_wh_kernel<<<dim3(IN_DIM / 32, D / 32), dim3(32, 8), 0, s1>>>(W1, w1t, IN_DIM);
    transpose_wh_kernel<<<dim3(HID_DIM / 32, D / 32), dim3(32, 8), 0, s1>>>(W2, w2t, HID_DIM);
    zero_out_kernel<<<(N_GRAPHS * D + 255) / 256, 256, 0, s1>>>(out);

    // s0: CSR head
    zero_cnt_kernel   <<<(N_NODES + 255) / 256, 256>>>(cnt);
    hist_kernel       <<<(N_EDGES + 255) / 256, 256>>>(ecol, cnt);
    dinv_kernel       <<<(N_NODES + 255) / 256, 256>>>(cnt, dinv);
    if (g_ok) { cudaEventRecord(g_evDinv, 0); cudaStreamWaitEvent(s1, g_evDinv, 0); }

    // s1: scale_x overlaps scan/place
    scale_x_kernel<<<(N_NODES * (IN_DIM / 2) + 255) / 256, 256, 0, s1>>>(x, dinv, xs);
    if (g_ok) cudaEventRecord(g_evPre, s1);

    // s0: scan + place
    partial_sum_kernel<<<SCAN_NB, 256>>>(cnt, bsum);
    scan_bsum_kernel  <<<1, 128>>>(bsum, boff);
    scan_final_kernel <<<SCAN_NB, 256>>>(cnt, boff, startp, cursor);
    place_kernel      <<<(N_EDGES + 255) / 256, 256>>>(erow, ecol, cursor, srow);
    if (g_ok) { cudaEventRecord(g_evPlace, 0); cudaStreamWaitEvent(s1, g_evPlace, 0); }
    if (g_ok) cudaStreamWaitEvent(0, g_evPre, 0);

    // chunk 0 (stream 0)
    agg1_kernel<<<(CHUNK0 * 32) / 256, 256>>>(xs, srow, startp, dinv, aggh, 0, CHUNK0);
    gemm_f16_kernel<IN_DIM, true, false, __half>
        <<<dim3(CHUNK0 / 128, 2), 256, GEMM_SMEM_BYTES>>>(aggh, w1t, b1, dinv, hh, 0);
    gemm_f16_kernel<HID_DIM, false, true, __nv_bfloat16>
        <<<dim3(CHUNK0 / 128, 2), 256, GEMM_SMEM_BYTES>>>(hh, w2t, b2, dinv, hs, 0);

    // chunk 1 (stream 1)
    agg1_kernel<<<(CHUNK1 * 32 + 255) / 256, 256, 0, s1>>>(xs, srow, startp, dinv, aggh,
                                                           CHUNK0, CHUNK1);
    gemm_f16_kernel<IN_DIM, true, false, __half>
        <<<dim3((CHUNK1 + 127) / 128, 2), 256, GEMM_SMEM_BYTES, s1>>>(aggh, w1t, b1, dinv, hh, CHUNK0);
    gemm_f16_kernel<HID_DIM, false, true, __nv_bfloat16>
        <<<dim3((CHUNK1 + 127) / 128, 2), 256, GEMM_SMEM_BYTES, s1>>>(hh, w2t, b2, dinv, hs, CHUNK0);
    if (g_ok) { cudaEventRecord(g_evJoin, s1); cudaStreamWaitEvent(0, g_evJoin, 0); }

    // fused aggregate + pool
    aggpool2_kernel<<<dim3(N_GRAPHS, POOL_CH), 256>>>(hs, srow, startp, dinv, b2, batch, out);
}

// round 14
// speedup vs baseline: 5.3770x; 1.1240x over previous
#include <cuda_runtime.h>
#include <cuda_bf16.h>
#include <cuda_fp16.h>
#include <cstdint>

#define N_NODES  100000
#define N_EDGES  1600000
#define N_GRAPHS 64
#define IN_DIM   128
#define HID_DIM  256
#define OUT_DIM  256
#define D        256
#define SCAN_NB  98
#define POOL_CH  24
#define CHUNK0   25600
#define CHUNK1   (N_NODES - CHUNK0)

// ---------------- scratch (no allocs allowed) ----------------
__device__ int   g_cnt   [N_NODES];
__device__ float g_dinv  [N_NODES];
__device__ int   g_start [N_NODES + 1];
__device__ int   g_cursor[N_NODES];
__device__ int   g_srow  [N_EDGES];
__device__ int   g_bsum  [SCAN_NB];
__device__ int   g_boff  [SCAN_NB];
__device__ __nv_bfloat16 g_xs[(size_t)N_NODES * IN_DIM];
__device__ __half g_aggh [(size_t)N_NODES * IN_DIM];       // fp16 agg1 output
__device__ __half g_hh   [(size_t)N_NODES * D];            // fp16 layer-1 output
__device__ unsigned char g_hs8[(size_t)N_NODES * D];       // fp8 e4m3 layer-2 pre-agg
__device__ __half g_w1t  [D * IN_DIM];                     // W1^T fp16 [256][128]
__device__ __half g_w2t  [D * HID_DIM];                    // W2^T fp16 [256][256]

// ---------------- stream/event plumbing ----------------
static cudaStream_t g_s1 = 0;
static cudaEvent_t  g_evRoot = 0, g_evDinv = 0, g_evPre = 0, g_evPlace = 0, g_evJoin = 0;
static bool g_ok = false;

namespace {
struct SInit {
    SInit() {
        bool ok = (cudaStreamCreateWithFlags(&g_s1, cudaStreamNonBlocking) == cudaSuccess);
        ok = ok && (cudaEventCreateWithFlags(&g_evRoot,  cudaEventDisableTiming) == cudaSuccess);
        ok = ok && (cudaEventCreateWithFlags(&g_evDinv,  cudaEventDisableTiming) == cudaSuccess);
        ok = ok && (cudaEventCreateWithFlags(&g_evPre,   cudaEventDisableTiming) == cudaSuccess);
        ok = ok && (cudaEventCreateWithFlags(&g_evPlace, cudaEventDisableTiming) == cudaSuccess);
        ok = ok && (cudaEventCreateWithFlags(&g_evJoin,  cudaEventDisableTiming) == cudaSuccess);
        g_ok = ok;
    }
};
static SInit s_init;
}

// ---------------- degree / CSR build ----------------
__global__ void zero_cnt_kernel(int* cnt) {
    int i = blockIdx.x * blockDim.x + threadIdx.x;
    if (i < N_NODES) cnt[i] = 0;
}

__global__ void hist_kernel(const int* __restrict__ cols, int* cnt) {
    int e = blockIdx.x * blockDim.x + threadIdx.x;
    if (e < N_EDGES) atomicAdd(&cnt[cols[e]], 1);
}

__global__ void dinv_kernel(const int* __restrict__ cnt, float* __restrict__ dinv) {
    int i = blockIdx.x * blockDim.x + threadIdx.x;
    if (i < N_NODES) dinv[i] = rsqrtf((float)(cnt[i] + 1));
}

__global__ __launch_bounds__(256)
void partial_sum_kernel(const int* __restrict__ cnt, int* __restrict__ bsum) {
    __shared__ int sh[256];
    int b = blockIdx.x, t = threadIdx.x;
    int base = b * 1024;
    int s = 0;
    #pragma unroll
    for (int j = 0; j < 4; j++) {
        int i = base + t + j * 256;
        if (i < N_NODES) s += cnt[i];
    }
    sh[t] = s;
    __syncthreads();
    for (int off = 128; off > 0; off >>= 1) {
        if (t < off) sh[t] += sh[t + off];
        __syncthreads();
    }
    if (t == 0) bsum[b] = sh[0];
}

__global__ __launch_bounds__(128)
void scan_bsum_kernel(const int* __restrict__ bsum, int* __restrict__ boff) {
    __shared__ int sh[128];
    int t = threadIdx.x;
    sh[t] = (t < SCAN_NB) ? bsum[t] : 0;
    __syncthreads();
    for (int off = 1; off < 128; off <<= 1) {
        int v = (t >= off) ? sh[t - off] : 0;
        __syncthreads();
        sh[t] += v;
        __syncthreads();
    }
    if (t < SCAN_NB) boff[t] = (t == 0) ? 0 : sh[t - 1];
}

__global__ __launch_bounds__(256)
void scan_final_kernel(const int* __restrict__ cnt, const int* __restrict__ boff,
                       int* __restrict__ start, int* __restrict__ cursor) {
    __shared__ int sh[256];
    int b = blockIdx.x, t = threadIdx.x;
    int base = b * 1024 + t * 4;
    int c[4];
    int s = 0;
    #pragma unroll
    for (int j = 0; j < 4; j++) {
        int i = base + j;
        c[j] = (i < N_NODES) ? cnt[i] : 0;
        s += c[j];
    }
    sh[t] = s;
    __syncthreads();
    for (int off = 1; off < 256; off <<= 1) {
        int v = (t >= off) ? sh[t - off] : 0;
        __syncthreads();
        sh[t] += v;
        __syncthreads();
    }
    int pre = boff[b] + ((t == 0) ? 0 : sh[t - 1]);
    #pragma unroll
    for (int j = 0; j < 4; j++) {
        int i = base + j;
        if (i < N_NODES) { start[i] = pre; cursor[i] = pre; }
        pre += c[j];
    }
    if (b == 0 && t == 0) start[N_NODES] = N_EDGES;
}

__global__ void place_kernel(const int* __restrict__ rows, const int* __restrict__ cols,
                             int* cursor, int* __restrict__ srow)
{
    int e = blockIdx.x * blockDim.x + threadIdx.x;
    if (e >= N_EDGES) return;
    int c = cols[e];
    int p = atomicAdd(&cursor[c], 1);
    srow[p] = rows[e];
}

// ---------------- W transpose to fp16: Wt[n][k] = fp16(W[k][n]) ----------------
__global__ void transpose_wh_kernel(const float* __restrict__ W, __half* __restrict__ Wt, int K) {
    __shared__ float t[32][33];
    int k0 = blockIdx.x * 32, n0 = blockIdx.y * 32;
    int tx = threadIdx.x, ty = threadIdx.y;   // 32 x 8
    #pragma unroll
    for (int j = 0; j < 32; j += 8)
        t[ty + j][tx] = W[(size_t)(k0 + ty + j) * D + n0 + tx];
    __syncthreads();
    #pragma unroll
    for (int j = 0; j < 32; j += 8)
        Wt[(size_t)(n0 + ty + j) * K + k0 + tx] = __float2half(t[tx][ty + j]);
}

// ---------------- xs = bf16(x * dinv[node]) ----------------
__global__ __launch_bounds__(256)
void scale_x_kernel(const float* __restrict__ x, const float* __restrict__ dinv,
                    __nv_bfloat16* __restrict__ xs)
{
    int idx = blockIdx.x * blockDim.x + threadIdx.x;
    if (idx >= N_NODES * (IN_DIM / 2)) return;
    int node = idx >> 6;
    float dc = dinv[node];
    float2 v = ((const float2*)x)[idx];
    __nv_bfloat162 p = __floats2bfloat162_rn(v.x * dc, v.y * dc);
    ((__nv_bfloat162*)xs)[idx] = p;
}

// ---------------- layer-1 aggregation -> fp16 output ----------------
__device__ __forceinline__ void bf16x4_add(uint2 v, float* a) {
    float2 f0 = __bfloat1622float2(*(__nv_bfloat162*)&v.x);
    float2 f1 = __bfloat1622float2(*(__nv_bfloat162*)&v.y);
    a[0] += f0.x; a[1] += f0.y; a[2] += f1.x; a[3] += f1.y;
}

__global__ __launch_bounds__(256)
void agg1_kernel(const __nv_bfloat16* __restrict__ xs, const int* __restrict__ srow,
                 const int* __restrict__ start, const float* __restrict__ dinv,
                 __half* __restrict__ out, int nbase, int ncount)
{
    int warp = (blockIdx.x * blockDim.x + threadIdx.x) >> 5;
    int lane = threadIdx.x & 31;
    if (warp >= ncount) return;
    int node = nbase + warp;
    int s = start[node], e = start[node + 1];

    float acc[4] = {0, 0, 0, 0};
    uint2 sv = ((const uint2*)(xs + (size_t)node * IN_DIM))[lane];
    bf16x4_add(sv, acc);

    int i = s;
    for (; i + 8 <= e; i += 8) {
        int r0 = srow[i],     r1 = srow[i + 1], r2 = srow[i + 2], r3 = srow[i + 3];
        int r4 = srow[i + 4], r5 = srow[i + 5], r6 = srow[i + 6], r7 = srow[i + 7];
        uint2 v0 = ((const uint2*)(xs + (size_t)r0 * IN_DIM))[lane];
        uint2 v1 = ((const uint2*)(xs + (size_t)r1 * IN_DIM))[lane];
        uint2 v2 = ((const uint2*)(xs + (size_t)r2 * IN_DIM))[lane];
        uint2 v3 = ((const uint2*)(xs + (size_t)r3 * IN_DIM))[lane];
        uint2 v4 = ((const uint2*)(xs + (size_t)r4 * IN_DIM))[lane];
        uint2 v5 = ((const uint2*)(xs + (size_t)r5 * IN_DIM))[lane];
        uint2 v6 = ((const uint2*)(xs + (size_t)r6 * IN_DIM))[lane];
        uint2 v7 = ((const uint2*)(xs + (size_t)r7 * IN_DIM))[lane];
        bf16x4_add(v0, acc); bf16x4_add(v1, acc);
        bf16x4_add(v2, acc); bf16x4_add(v3, acc);
        bf16x4_add(v4, acc); bf16x4_add(v5, acc);
        bf16x4_add(v6, acc); bf16x4_add(v7, acc);
    }
    for (; i + 2 <= e; i += 2) {
        int r0 = srow[i], r1 = srow[i + 1];
        uint2 v0 = ((const uint2*)(xs + (size_t)r0 * IN_DIM))[lane];
        uint2 v1 = ((const uint2*)(xs + (size_t)r1 * IN_DIM))[lane];
        bf16x4_add(v0, acc); bf16x4_add(v1, acc);
    }
    if (i < e) {
        int r = srow[i];
        uint2 v = ((const uint2*)(xs + (size_t)r * IN_DIM))[lane];
        bf16x4_add(v, acc);
    }

    float dc = dinv[node];
    __half2 p0 = __floats2half2_rn(acc[0] * dc, acc[1] * dc);
    __half2 p1 = __floats2half2_rn(acc[2] * dc, acc[3] * dc);
    uint2 o;
    o.x = *(unsigned*)&p0;
    o.y = *(unsigned*)&p1;
    ((uint2*)(out + (size_t)node * IN_DIM))[lane] = o;
}

// ---------------- fused layer-2 aggregation (fp8 gather) + global mean pool ----------------
// hs8 rows: 256 e4m3 bytes; lane covers features [lane*8, lane*8+8).
__device__ __forceinline__ void fp8x8_addh(uint2 v, __half2* a) {
    unsigned r0, r1, r2, r3;
    asm("{\n\t.reg .b16 lo, hi;\n\t"
        "mov.b32 {lo, hi}, %2;\n\t"
        "cvt.rn.f16x2.e4m3x2 %0, lo;\n\t"
        "cvt.rn.f16x2.e4m3x2 %1, hi;\n\t}"
        : "=r"(r0), "=r"(r1) : "r"(v.x));
    asm("{\n\t.reg .b16 lo, hi;\n\t"
        "mov.b32 {lo, hi}, %2;\n\t"
        "cvt.rn.f16x2.e4m3x2 %0, lo;\n\t"
        "cvt.rn.f16x2.e4m3x2 %1, hi;\n\t}"
        : "=r"(r2), "=r"(r3) : "r"(v.y));
    a[0] = __hadd2(a[0], *(__half2*)&r0);
    a[1] = __hadd2(a[1], *(__half2*)&r1);
    a[2] = __hadd2(a[2], *(__half2*)&r2);
    a[3] = __hadd2(a[3], *(__half2*)&r3);
}

__device__ __forceinline__ int lower_bound_i(const int* a, int n, int v) {
    int lo = 0, hi = n;
    while (lo < hi) {
        int mid = (lo + hi) >> 1;
        if (a[mid] < v) lo = mid + 1; else hi = mid;
    }
    return lo;
}

__global__ __launch_bounds__(256)
void aggpool2_kernel(const unsigned char* __restrict__ hs, const int* __restrict__ srow,
                     const int* __restrict__ start, const float* __restrict__ dinv,
                     const float* __restrict__ bias, const int* __restrict__ batch,
                     float* __restrict__ out)
{
    int g  = blockIdx.x;
    int ch = blockIdx.y;
    int w    = threadIdx.x >> 5;
    int lane = threadIdx.x & 31;

    __shared__ int slo, shi;
    __shared__ float red[8 * 256];
    if (threadIdx.x == 0) slo = lower_bound_i(batch, N_NODES, g);
    if (threadIdx.x == 1) shi = lower_bound_i(batch, N_NODES, g + 1);
    __syncthreads();
    int lo = slo, hi = shi;
    int cnt = hi - lo;

    float pool[8] = {0, 0, 0, 0, 0, 0, 0, 0};
    if (cnt > 0) {
        float4 b_lo = ((const float4*)bias)[lane * 2];
        float4 b_hi = ((const float4*)bias)[lane * 2 + 1];
        for (int node = lo + ch * 8 + w; node < hi; node += POOL_CH * 8) {
            int s = start[node], e = start[node + 1];
            __half2 acch[4];
            acch[0] = __half2half2(__ushort_as_half(0));
            acch[1] = acch[0]; acch[2] = acch[0]; acch[3] = acch[0];
            uint2 sv = ((const uint2*)(hs + (size_t)node * D))[lane];
            fp8x8_addh(sv, acch);
            int i = s;
            for (; i + 8 <= e; i += 8) {
                int r0 = srow[i],     r1 = srow[i + 1], r2 = srow[i + 2], r3 = srow[i + 3];
                int r4 = srow[i + 4], r5 = srow[i + 5], r6 = srow[i + 6], r7 = srow[i + 7];
                uint2 v0 = ((const uint2*)(hs + (size_t)r0 * D))[lane];
                uint2 v1 = ((const uint2*)(hs + (size_t)r1 * D))[lane];
                uint2 v2 = ((const uint2*)(hs + (size_t)r2 * D))[lane];
                uint2 v3 = ((const uint2*)(hs + (size_t)r3 * D))[lane];
                uint2 v4 = ((const uint2*)(hs + (size_t)r4 * D))[lane];
                uint2 v5 = ((const uint2*)(hs + (size_t)r5 * D))[lane];
                uint2 v6 = ((const uint2*)(hs + (size_t)r6 * D))[lane];
                uint2 v7 = ((const uint2*)(hs + (size_t)r7 * D))[lane];
                fp8x8_addh(v0, acch); fp8x8_addh(v1, acch);
                fp8x8_addh(v2, acch); fp8x8_addh(v3, acch);
                fp8x8_addh(v4, acch); fp8x8_addh(v5, acch);
                fp8x8_addh(v6, acch); fp8x8_addh(v7, acch);
            }
            for (; i + 2 <= e; i += 2) {
                int r0 = srow[i], r1 = srow[i + 1];
                uint2 v0 = ((const uint2*)(hs + (size_t)r0 * D))[lane];
                uint2 v1 = ((const uint2*)(hs + (size_t)r1 * D))[lane];
                fp8x8_addh(v0, acch); fp8x8_addh(v1, acch);
            }
            if (i < e) {
                int r = srow[i];
                uint2 v = ((const uint2*)(hs + (size_t)r * D))[lane];
                fp8x8_addh(v, acch);
            }
            float2 f0 = __half22float2(acch[0]);
            float2 f1 = __half22float2(acch[1]);
            float2 f2 = __half22float2(acch[2]);
            float2 f3 = __half22float2(acch[3]);
            float dc = dinv[node];
            pool[0] += fmaxf(fmaf(f0.x, dc, b_lo.x), 0.f);
            pool[1] += fmaxf(fmaf(f0.y, dc, b_lo.y), 0.f);
            pool[2] += fmaxf(fmaf(f1.x, dc, b_lo.z), 0.f);
            pool[3] += fmaxf(fmaf(f1.y, dc, b_lo.w), 0.f);
            pool[4] += fmaxf(fmaf(f2.x, dc, b_hi.x), 0.f);
            pool[5] += fmaxf(fmaf(f2.y, dc, b_hi.y), 0.f);
            pool[6] += fmaxf(fmaf(f3.x, dc, b_hi.z), 0.f);
            pool[7] += fmaxf(fmaf(f3.y, dc, b_hi.w), 0.f);
        }
        float inv = 1.f / (float)cnt;
        #pragma unroll
        for (int j = 0; j < 8; j++) pool[j] *= inv;
    }

    #pragma unroll
    for (int j = 0; j < 8; j++) red[w * 256 + lane * 8 + j] = pool[j];
    __syncthreads();
    int t = threadIdx.x;
    float s = 0.f;
    #pragma unroll
    for (int wj = 0; wj < 8; wj++) s += red[wj * 256 + t];
    atomicAdd(&out[g * D + t], s);
}

// ---------------- fp16 GEMM, mma.m16n8k16, cp.async 2-stage ----------------
__device__ __forceinline__ void mma_f16(float* c, const unsigned* a, const unsigned* b) {
    asm volatile(
        "mma.sync.aligned.m16n8k16.row.col.f32.f16.f16.f32 "
        "{%0,%1,%2,%3}, {%4,%5,%6,%7}, {%8,%9}, {%0,%1,%2,%3};"
        : "+f"(c[0]), "+f"(c[1]), "+f"(c[2]), "+f"(c[3])
        : "r"(a[0]), "r"(a[1]), "r"(a[2]), "r"(a[3]), "r"(b[0]), "r"(b[1]));
}

__device__ __forceinline__ void cp16(unsigned smem_dst, const void* gsrc, bool valid) {
    int sz = valid ? 16 : 0;
    asm volatile("cp.async.ca.shared.global [%0], [%1], 16, %2;"
                 :: "r"(smem_dst), "l"(gsrc), "r"(sz));
}

__device__ __forceinline__ void store_pair(__half* out, size_t idx, float v0, float v1) {
    __half2 p = __floats2half2_rn(v0, v1);
    *(unsigned*)(out + idx) = *(unsigned*)&p;
}
__device__ __forceinline__ void store_pair(unsigned char* out, size_t idx, float v0, float v1) {
    unsigned short p;
    asm("cvt.rn.satfinite.e4m3x2.f32 %0, %1, %2;" : "=h"(p) : "f"(v1), "f"(v0));
    *(unsigned short*)(out + idx) = p;
}

#define GEMM_BM 128
#define GEMM_BN 128
#define GEMM_BK 32
#define GEMM_ROWH 40
#define GEMM_A_HALFS (GEMM_BM * GEMM_ROWH)
#define GEMM_B_HALFS (GEMM_BN * GEMM_ROWH)
#define GEMM_SMEM_BYTES ((2 * GEMM_A_HALFS + 2 * GEMM_B_HALFS) * 2)

template <int K, bool RELU, bool SCALE, typename OutT>
__global__ __launch_bounds__(256)
void gemm_f16_kernel(const __half* __restrict__ A, const __half* __restrict__ Wt,
                     const float* __restrict__ bias, const float* __restrict__ dinv,
                     OutT* __restrict__ out, int m_base)
{
    extern __shared__ __half smh[];
    const int tid  = threadIdx.x;
    const int wid  = tid >> 5;
    const int lane = tid & 31;
    const int gid  = lane >> 2;
    const int tig  = lane & 3;
    const int wm   = (wid & 3) * 32;
    const int wn   = (wid >> 2) * 64;

    const int m0 = m_base + blockIdx.x * GEMM_BM;
    const int n0 = blockIdx.y * GEMM_BN;

    unsigned sbase = (unsigned)__cvta_generic_to_shared(smh);
    unsigned aBase = sbase;
    unsigned bBase = sbase + 2 * GEMM_A_HALFS * 2;

    const int ld_r   = tid >> 1;
    const int ld_seg = (tid & 1) * 32;

    auto load_stage = [&](int s, int k0) {
        bool valid = (m0 + ld_r) < N_NODES;
        const char* asrc = (const char*)(A + (size_t)(m0 + ld_r) * K + k0) + ld_seg;
        unsigned adst = aBase + (unsigned)(s * GEMM_A_HALFS * 2 + ld_r * (GEMM_ROWH * 2) + ld_seg);
        cp16(adst,      asrc,      valid);
        cp16(adst + 16, asrc + 16, valid);
        const char* bsrc = (const char*)(Wt + (size_t)(n0 + ld_r) * K + k0) + ld_seg;
        unsigned bdst = bBase + (unsigned)(s * GEMM_B_HALFS * 2 + ld_r * (GEMM_ROWH * 2) + ld_seg);
        cp16(bdst,      bsrc,      true);
        cp16(bdst + 16, bsrc + 16, true);
        asm volatile("cp.async.commit_group;");
    };

    float c[2][8][4];
    #pragma unroll
    for (int mt = 0; mt < 2; mt++)
        #pragma unroll
        for (int nt = 0; nt < 8; nt++)
            #pragma unroll
            for (int r = 0; r < 4; r++) c[mt][nt][r] = 0.f;

    load_stage(0, 0);

    int cur = 0;
    for (int k0 = 0; k0 < K; k0 += GEMM_BK) {
        asm volatile("cp.async.wait_group 0;");
        __syncthreads();

        if (k0 + GEMM_BK < K)
            load_stage(cur ^ 1, k0 + GEMM_BK);

        const __half* Ah = smh + cur * GEMM_A_HALFS;
        const __half* Bh = smh + 2 * GEMM_A_HALFS + cur * GEMM_B_HALFS;

        #pragma unroll
        for (int ks = 0; ks < 2; ks++) {
            int kk = ks * 16;
            unsigned a[2][4];
            #pragma unroll
            for (int mt = 0; mt < 2; mt++) {
                int row = wm + mt * 16;
                a[mt][0] = *(const unsigned*)&Ah[(row + gid    ) * GEMM_ROWH + kk + 2 * tig];
                a[mt][1] = *(const unsigned*)&Ah[(row + gid + 8) * GEMM_ROWH + kk + 2 * tig];
                a[mt][2] = *(const unsigned*)&Ah[(row + gid    ) * GEMM_ROWH + kk + 2 * tig + 8];
                a[mt][3] = *(const unsigned*)&Ah[(row + gid + 8) * GEMM_ROWH + kk + 2 * tig + 8];
            }
            unsigned b[8][2];
            #pragma unroll
            for (int nt = 0; nt < 8; nt++) {
                int col = wn + nt * 8 + gid;
                b[nt][0] = *(const unsigned*)&Bh[col * GEMM_ROWH + kk + 2 * tig];
                b[nt][1] = *(const unsigned*)&Bh[col * GEMM_ROWH + kk + 2 * tig + 8];
            }
            #pragma unroll
            for (int mt = 0; mt < 2; mt++)
                #pragma unroll
                for (int nt = 0; nt < 8; nt++)
                    mma_f16(c[mt][nt], a[mt], b[nt]);
        }
        __syncthreads();
        cur ^= 1;
    }

    #pragma unroll
    for (int mt = 0; mt < 2; mt++) {
        #pragma unroll
        for (int rh = 0; rh < 2; rh++) {
            int row = m0 + wm + mt * 16 + gid + rh * 8;
            if (row >= N_NODES) continue;
            float sc = SCALE ? dinv[row] : 1.f;
            #pragma unroll
            for (int nt = 0; nt < 8; nt++) {
                int col = n0 + wn + nt * 8 + 2 * tig;
                float v0 = c[mt][nt][rh * 2 + 0] * sc;
                float v1 = c[mt][nt][rh * 2 + 1] * sc;
                if (RELU) {
                    v0 = fmaxf(v0 + bias[col],     0.f);
                    v1 = fmaxf(v1 + bias[col + 1], 0.f);
                }
                store_pair(out, (size_t)row * D + col, v0, v1);
            }
        }
    }
}

// ---------------- out zero-init ----------------
__global__ void zero_out_kernel(float* out) {
    int i = blockIdx.x * blockDim.x + threadIdx.x;
    if (i < N_GRAPHS * D) out[i] = 0.f;
}

// ---------------------------------------------------------------------------
extern "C" void kernel_launch(void* const* d_in, const int* in_sizes, int n_in,
                              void* d_out, int out_size)
{
    const float* x     = (const float*)d_in[0];
    const int*   eidx  = (const int*)  d_in[1];
    const int*   batch = (const int*)  d_in[2];
    const float* W1    = (const float*)d_in[3];
    const float* b1    = (const float*)d_in[4];
    const float* W2    = (const float*)d_in[5];
    const float* b2    = (const float*)d_in[6];
    float* out = (float*)d_out;

    const int* erow = eidx;
    const int* ecol = eidx + N_EDGES;

    int *cnt, *startp, *cursor, *srow, *bsum, *boff;
    float *dinv;
    __half *aggh, *hh, *w1t, *w2t;
    unsigned char *hs8;
    __nv_bfloat16 *xs;
    cudaGetSymbolAddress((void**)&cnt,    g_cnt);
    cudaGetSymbolAddress((void**)&dinv,   g_dinv);
    cudaGetSymbolAddress((void**)&startp, g_start);
    cudaGetSymbolAddress((void**)&cursor, g_cursor);
    cudaGetSymbolAddress((void**)&srow,   g_srow);
    cudaGetSymbolAddress((void**)&bsum,   g_bsum);
    cudaGetSymbolAddress((void**)&boff,   g_boff);
    cudaGetSymbolAddress((void**)&xs,     g_xs);
    cudaGetSymbolAddress((void**)&aggh,   g_aggh);
    cudaGetSymbolAddress((void**)&hh,     g_hh);
    cudaGetSymbolAddress((void**)&hs8,    g_hs8);
    cudaGetSymbolAddress((void**)&w1t,    g_w1t);
    cudaGetSymbolAddress((void**)&w2t,    g_w2t);

    static bool attr_done = false;
    if (!attr_done) {
        cudaFuncSetAttribute(gemm_f16_kernel<IN_DIM, true, false, __half>,
                             cudaFuncAttributeMaxDynamicSharedMemorySize, GEMM_SMEM_BYTES);
        cudaFuncSetAttribute(gemm_f16_kernel<HID_DIM, false, true, unsigned char>,
                             cudaFuncAttributeMaxDynamicSharedMemorySize, GEMM_SMEM_BYTES);
        attr_done = true;
    }

    cudaStream_t s1 = g_ok ? g_s1 : (cudaStream_t)0;
    // Launch order is a dependency-valid TOTAL order -> single-stream fallback correct.

    if (g_ok) { cudaEventRecord(g_evRoot, 0); cudaStreamWaitEvent(s1, g_evRoot, 0); }

    // s1: prep (hidden under CSR build)
    transpose_wh_kernel<<<dim3(IN_DIM / 32, D / 32), dim3(32, 8), 0, s1>>>(W1, w1t, IN_DIM);
    transpose_wh_kernel<<<dim3(HID_DIM / 32, D / 32), dim3(32, 8), 0, s1>>>(W2, w2t, HID_DIM);
    zero_out_kernel<<<(N_GRAPHS * D + 255) / 256, 256, 0, s1>>>(out);

    // s0: CSR head
    zero_cnt_kernel   <<<(N_NODES + 255) / 256, 256>>>(cnt);
    hist_kernel       <<<(N_EDGES + 255) / 256, 256>>>(ecol, cnt);
    dinv_kernel       <<<(N_NODES + 255) / 256, 256>>>(cnt, dinv);
    if (g_ok) { cudaEventRecord(g_evDinv, 0); cudaStreamWaitEvent(s1, g_evDinv, 0); }

    // s1: scale_x overlaps scan/place
    scale_x_kernel<<<(N_NODES * (IN_DIM / 2) + 255) / 256, 256, 0, s1>>>(x, dinv, xs);
    if (g_ok) cudaEventRecord(g_evPre, s1);

    // s0: scan + place
    partial_sum_kernel<<<SCAN_NB, 256>>>(cnt, bsum);
    scan_bsum_kernel  <<<1, 128>>>(bsum, boff);
    scan_final_kernel <<<SCAN_NB, 256>>>(cnt, boff, startp, cursor);
    place_kernel      <<<(N_EDGES + 255) / 256, 256>>>(erow, ecol, cursor, srow);
    if (g_ok) { cudaEventRecord(g_evPlace, 0); cudaStreamWaitEvent(s1, g_evPlace, 0); }
    if (g_ok) cudaStreamWaitEvent(0, g_evPre, 0);

    // chunk 0 (stream 0)
    agg1_kernel<<<(CHUNK0 * 32) / 256, 256>>>(xs, srow, startp, dinv, aggh, 0, CHUNK0);
    gemm_f16_kernel<IN_DIM, true, false, __half>
        <<<dim3(CHUNK0 / 128, 2), 256, GEMM_SMEM_BYTES>>>(aggh, w1t, b1, dinv, hh, 0);
    gemm_f16_kernel<HID_DIM, false, true, unsigned char>
        <<<dim3(CHUNK0 / 128, 2), 256, GEMM_SMEM_BYTES>>>(hh, w2t, b2, dinv, hs8, 0);

    // chunk 1 (stream 1)
    agg1_kernel<<<(CHUNK1 * 32 + 255) / 256, 256, 0, s1>>>(xs, srow, startp, dinv, aggh,
                                                           CHUNK0, CHUNK1);
    gemm_f16_kernel<IN_DIM, true, false, __half>
        <<<dim3((CHUNK1 + 127) / 128, 2), 256, GEMM_SMEM_BYTES, s1>>>(aggh, w1t, b1, dinv, hh, CHUNK0);
    gemm_f16_kernel<HID_DIM, false, true, unsigned char>
        <<<dim3((CHUNK1 + 127) / 128, 2), 256, GEMM_SMEM_BYTES, s1>>>(hh, w2t, b2, dinv, hs8, CHUNK0);
    if (g_ok) { cudaEventRecord(g_evJoin, s1); cudaStreamWaitEvent(0, g_evJoin, 0); }

    // fused aggregate + pool (fp8 gather)
    aggpool2_kernel<<<dim3(N_GRAPHS, POOL_CH), 256>>>(hs8, srow, startp, dinv, b2, batch, out);
}